// round 7
// baseline (speedup 1.0000x reference)
#include <cuda_runtime.h>
#include <cstdint>
#include <math.h>

#define BB 4
#define SS 4096
#define DD 256
#define HH 400
#define BSROWS (BB*SS)

// ---- scratch ----
__device__ float g_Q[BSROWS*DD];
__device__ float g_K[BSROWS*DD];
__device__ float g_V[BSROWS*DD];
__device__ float g_T[BSROWS*DD];
__device__ float g_X[BSROWS*DD];
__device__ float g_Y[BSROWS*DD];
__device__ float g_H[BSROWS*HH];

// ============================================================
// helpers
// ============================================================
__device__ __forceinline__ float tf32r(float x) {
    float r; asm("cvt.rna.tf32.f32 %0, %1;" : "=f"(r) : "f"(x)); return r;
}
__device__ __forceinline__ void mma8(float c[4], const uint32_t a[4], const uint32_t b[2]) {
    asm volatile(
        "mma.sync.aligned.m16n8k8.row.col.f32.tf32.tf32.f32 "
        "{%0,%1,%2,%3}, {%4,%5,%6,%7}, {%8,%9}, {%0,%1,%2,%3};"
        : "+f"(c[0]), "+f"(c[1]), "+f"(c[2]), "+f"(c[3])
        : "r"(a[0]), "r"(a[1]), "r"(a[2]), "r"(a[3]), "r"(b[0]), "r"(b[1]));
}
__device__ __forceinline__ uint32_t f2u(float x) { return __float_as_uint(x); }

// ============================================================
// Flash attention, tf32 HMMA, scalar-LDS fragment gather.
// CTA: 64 queries, 512 threads (16 warps = 4 row-groups x 4 col-quarters).
// K/V chunks of 64 keys. Same SMEM as round-3 (218.9 KB), 2x warps.
// ============================================================
#define FBQ 64
#define FBK 64
#define QSTR 260
#define KSTR 260
#define VSTR 264
#define SSTR 68
// f32 offsets in dynamic smem
#define OQ  0
#define OK  16640                 // 64*260
#define OV  33280                 // + 64*260
#define OS  50176                 // + 64*264
#define OM  54528                 // + 64*68
#define OL  54592
#define OA  54656
#define FL_FLOATS 54720           // *4 = 218880 bytes

__global__ void __launch_bounds__(512, 1)
flash_mma(const float* __restrict__ Qg, const float* __restrict__ Kg,
          const float* __restrict__ Vg, float* __restrict__ Og, int causal) {
    extern __shared__ float fs[];
    int tid = threadIdx.x;
    int wid = tid >> 5, lane = tid & 31;
    int rg = wid >> 2;        // row-group: rows 16*rg .. +15
    int h  = wid & 3;         // quarter: score cols 16h..+15 / O cols 64h..+63
    int lrow = lane >> 2;
    int lcol = lane & 3;
    int b = blockIdx.y, q0 = blockIdx.x * FBQ;

    // ---- stage Q (prescaled by 1/sqrt(4096)=1/64, rna-tf32) ----
    {
        const float4* Qr = (const float4*)(Qg + ((size_t)b * SS + q0) * DD);
        #pragma unroll
        for (int p = 0; p < 8; p++) {
            int idx = tid + p * 512;
            int r = idx >> 6, c4 = idx & 63;
            float4 v = Qr[r * 64 + c4];
            v.x = tf32r(v.x * 0.015625f); v.y = tf32r(v.y * 0.015625f);
            v.z = tf32r(v.z * 0.015625f); v.w = tf32r(v.w * 0.015625f);
            *(float4*)&fs[OQ + r * QSTR + c4 * 4] = v;
        }
    }
    if (tid < FBQ) { fs[OM + tid] = -INFINITY; fs[OL + tid] = 0.0f; }

    float ofrag[8][4];
    #pragma unroll
    for (int nb = 0; nb < 8; nb++)
        #pragma unroll
        for (int j = 0; j < 4; j++) ofrag[nb][j] = 0.0f;

    int nc = causal ? (blockIdx.x + 1) : (SS / FBK);

    for (int c = 0; c < nc; c++) {
        int k0 = c * FBK;
        bool maskc = causal && (k0 == q0);

        // ---- stage K and V (row-major, rna-tf32) ----
        {
            const float4* Kr = (const float4*)(Kg + ((size_t)b * SS + k0) * DD);
            const float4* Vr = (const float4*)(Vg + ((size_t)b * SS + k0) * DD);
            #pragma unroll
            for (int p = 0; p < 8; p++) {
                int idx = tid + p * 512;
                int r = idx >> 6, c4 = idx & 63;
                float4 v = Kr[r * 64 + c4];
                v.x = tf32r(v.x); v.y = tf32r(v.y); v.z = tf32r(v.z); v.w = tf32r(v.w);
                *(float4*)&fs[OK + r * KSTR + c4 * 4] = v;
                float4 w = Vr[r * 64 + c4];
                w.x = tf32r(w.x); w.y = tf32r(w.y); w.z = tf32r(w.z); w.w = tf32r(w.w);
                *(float4*)&fs[OV + r * VSTR + c4 * 4] = w;
            }
        }
        __syncthreads();   // (A)

        // ---- scores: warp (rg,h): S[16rg..+15][16h..+15] ----
        {
            float sfr[2][4];
            #pragma unroll
            for (int nb = 0; nb < 2; nb++)
                #pragma unroll
                for (int j = 0; j < 4; j++) sfr[nb][j] = 0.0f;

            #pragma unroll 8
            for (int kb = 0; kb < 32; kb++) {
                int kk = kb * 8 + lcol;
                uint32_t a[4];
                a[0] = f2u(fs[OQ + (16 * rg + lrow) * QSTR + kk]);
                a[1] = f2u(fs[OQ + (16 * rg + lrow + 8) * QSTR + kk]);
                a[2] = f2u(fs[OQ + (16 * rg + lrow) * QSTR + kk + 4]);
                a[3] = f2u(fs[OQ + (16 * rg + lrow + 8) * QSTR + kk + 4]);
                #pragma unroll
                for (int nb = 0; nb < 2; nb++) {
                    int nrow = 16 * h + nb * 8 + lrow;
                    uint32_t b2[2];
                    b2[0] = f2u(fs[OK + nrow * KSTR + kk]);
                    b2[1] = f2u(fs[OK + nrow * KSTR + kk + 4]);
                    mma8(sfr[nb], a, b2);
                }
            }
            int grow0 = q0 + 16 * rg + lrow;
            #pragma unroll
            for (int nb = 0; nb < 2; nb++) {
                int cb0 = 16 * h + nb * 8 + 2 * lcol;
                float2 v0 = make_float2(sfr[nb][0], sfr[nb][1]);
                float2 v1 = make_float2(sfr[nb][2], sfr[nb][3]);
                if (maskc) {
                    int g = k0 + cb0;
                    if (g > grow0)         v0.x = -1e30f;
                    if (g + 1 > grow0)     v0.y = -1e30f;
                    if (g > grow0 + 8)     v1.x = -1e30f;
                    if (g + 1 > grow0 + 8) v1.y = -1e30f;
                }
                *(float2*)&fs[OS + (16 * rg + lrow) * SSTR + cb0] = v0;
                *(float2*)&fs[OS + (16 * rg + lrow + 8) * SSTR + cb0] = v1;
            }
        }
        __syncthreads();   // (B)

        // ---- online softmax: 8 threads per row, 8 cols each ----
        {
            int row = tid >> 3, seg = tid & 7;
            float* Sr = &fs[OS + row * SSTR + seg * 8];
            float4 x0 = ((float4*)Sr)[0];
            float4 x1 = ((float4*)Sr)[1];
            float mx = fmaxf(fmaxf(fmaxf(x0.x, x0.y), fmaxf(x0.z, x0.w)),
                             fmaxf(fmaxf(x1.x, x1.y), fmaxf(x1.z, x1.w)));
            mx = fmaxf(mx, __shfl_xor_sync(0xffffffff, mx, 1));
            mx = fmaxf(mx, __shfl_xor_sync(0xffffffff, mx, 2));
            mx = fmaxf(mx, __shfl_xor_sync(0xffffffff, mx, 4));
            float mold = fs[OM + row];
            float mnew = fmaxf(mold, mx);
            float alpha = __expf(mold - mnew);
            x0.x = __expf(x0.x - mnew); x0.y = __expf(x0.y - mnew);
            x0.z = __expf(x0.z - mnew); x0.w = __expf(x0.w - mnew);
            x1.x = __expf(x1.x - mnew); x1.y = __expf(x1.y - mnew);
            x1.z = __expf(x1.z - mnew); x1.w = __expf(x1.w - mnew);
            float sum = x0.x + x0.y + x0.z + x0.w + x1.x + x1.y + x1.z + x1.w;
            x0.x = tf32r(x0.x); x0.y = tf32r(x0.y); x0.z = tf32r(x0.z); x0.w = tf32r(x0.w);
            x1.x = tf32r(x1.x); x1.y = tf32r(x1.y); x1.z = tf32r(x1.z); x1.w = tf32r(x1.w);
            ((float4*)Sr)[0] = x0;
            ((float4*)Sr)[1] = x1;
            sum += __shfl_xor_sync(0xffffffff, sum, 1);
            sum += __shfl_xor_sync(0xffffffff, sum, 2);
            sum += __shfl_xor_sync(0xffffffff, sum, 4);
            if (seg == 0) {
                fs[OL + row] = fs[OL + row] * alpha + sum;
                fs[OM + row] = mnew;
                fs[OA + row] = alpha;
            }
        }
        __syncthreads();   // (C)

        // ---- PV: warp (rg,h): O[16rg..+15][64h..+63] += P * V ----
        {
            float al0 = fs[OA + 16 * rg + lrow];
            float al8 = fs[OA + 16 * rg + lrow + 8];
            #pragma unroll
            for (int nb = 0; nb < 8; nb++) {
                ofrag[nb][0] *= al0; ofrag[nb][1] *= al0;
                ofrag[nb][2] *= al8; ofrag[nb][3] *= al8;
            }
            #pragma unroll
            for (int kb = 0; kb < 8; kb++) {
                int kk = kb * 8 + lcol;
                uint32_t a[4];
                a[0] = f2u(fs[OS + (16 * rg + lrow) * SSTR + kk]);
                a[1] = f2u(fs[OS + (16 * rg + lrow + 8) * SSTR + kk]);
                a[2] = f2u(fs[OS + (16 * rg + lrow) * SSTR + kk + 4]);
                a[3] = f2u(fs[OS + (16 * rg + lrow + 8) * SSTR + kk + 4]);
                #pragma unroll
                for (int nb = 0; nb < 8; nb++) {
                    int ncol = 64 * h + nb * 8 + lrow;
                    uint32_t b2[2];
                    b2[0] = f2u(fs[OV + kk * VSTR + ncol]);
                    b2[1] = f2u(fs[OV + (kk + 4) * VSTR + ncol]);
                    mma8(ofrag[nb], a, b2);
                }
            }
        }
        __syncthreads();   // (D)
    }

    // ---- epilogue ----
    {
        int row = 16 * rg + lrow;
        float inv0 = 1.0f / fs[OL + row];
        float inv8 = 1.0f / fs[OL + row + 8];
        float* Or0 = Og + ((size_t)b * SS + q0 + row) * DD;
        float* Or8 = Or0 + 8 * DD;
        #pragma unroll
        for (int nb = 0; nb < 8; nb++) {
            int col = 64 * h + nb * 8 + 2 * lcol;
            *(float2*)&Or0[col] = make_float2(ofrag[nb][0] * inv0, ofrag[nb][1] * inv0);
            *(float2*)&Or8[col] = make_float2(ofrag[nb][2] * inv8, ofrag[nb][3] * inv8);
        }
    }
}

// ============================================================
// tf32 HMMA GEMM (round-3 proven): C[M,N]=A[M,K]*W[K,N] (+bias,+leaky)
// BM=64, BN=64, BK=16, 256 threads (8 warps = 4m x 2n).
// ============================================================
#define ASTR 20
#define WSTR 72

template<int BIAS, int LEAKY>
__global__ void __launch_bounds__(256)
gemm_tc(const float* __restrict__ A, const float* __restrict__ W,
        const float* __restrict__ bias, float* __restrict__ C,
        int M, int N, int K) {
    __shared__ float As[64 * ASTR];
    __shared__ float Ws[16 * WSTR];
    int tid = threadIdx.x;
    int wid = tid >> 5, lane = tid & 31;
    int wm = wid & 3, wn = wid >> 2;
    int lrow = lane >> 2, lcol = lane & 3;
    int rb = blockIdx.y * 64, cb = blockIdx.x * 64;

    float cfr[4][4];
    #pragma unroll
    for (int nb = 0; nb < 4; nb++)
        #pragma unroll
        for (int j = 0; j < 4; j++) cfr[nb][j] = 0.0f;

    for (int k0 = 0; k0 < K; k0 += 16) {
        // stage A tile 64x16
        {
            int row = tid >> 2, kq = tid & 3;
            float4 v = *(const float4*)&A[(size_t)(rb + row) * K + k0 + kq * 4];
            v.x = tf32r(v.x); v.y = tf32r(v.y); v.z = tf32r(v.z); v.w = tf32r(v.w);
            *(float4*)&As[row * ASTR + kq * 4] = v;
        }
        // stage W tile 16x64
        {
            int kk = tid >> 4, n4 = tid & 15;
            int col = cb + n4 * 4;
            float4 v;
            if (col + 3 < N) {
                v = *(const float4*)&W[(size_t)(k0 + kk) * N + col];
            } else {
                v.x = (col + 0 < N) ? W[(size_t)(k0 + kk) * N + col + 0] : 0.0f;
                v.y = (col + 1 < N) ? W[(size_t)(k0 + kk) * N + col + 1] : 0.0f;
                v.z = (col + 2 < N) ? W[(size_t)(k0 + kk) * N + col + 2] : 0.0f;
                v.w = (col + 3 < N) ? W[(size_t)(k0 + kk) * N + col + 3] : 0.0f;
            }
            v.x = tf32r(v.x); v.y = tf32r(v.y); v.z = tf32r(v.z); v.w = tf32r(v.w);
            *(float4*)&Ws[kk * WSTR + n4 * 4] = v;
        }
        __syncthreads();
        #pragma unroll
        for (int kb = 0; kb < 2; kb++) {
            int kk = kb * 8 + lcol;
            uint32_t a[4];
            a[0] = f2u(As[(16 * wm + lrow) * ASTR + kk]);
            a[1] = f2u(As[(16 * wm + lrow + 8) * ASTR + kk]);
            a[2] = f2u(As[(16 * wm + lrow) * ASTR + kk + 4]);
            a[3] = f2u(As[(16 * wm + lrow + 8) * ASTR + kk + 4]);
            #pragma unroll
            for (int nb = 0; nb < 4; nb++) {
                int ncol = 32 * wn + nb * 8 + lrow;
                uint32_t b2[2];
                b2[0] = f2u(Ws[kk * WSTR + ncol]);
                b2[1] = f2u(Ws[(kk + 4) * WSTR + ncol]);
                mma8(cfr[nb], a, b2);
            }
        }
        __syncthreads();
    }

    // epilogue
    int r0 = rb + 16 * wm + lrow;
    #pragma unroll
    for (int nb = 0; nb < 4; nb++) {
        int col = cb + 32 * wn + nb * 8 + 2 * lcol;
        if (col < N) {
            float v00 = cfr[nb][0], v01 = cfr[nb][1];
            float v10 = cfr[nb][2], v11 = cfr[nb][3];
            if (BIAS) {
                float b0 = bias[col], b1 = bias[col + 1];
                v00 += b0; v01 += b1; v10 += b0; v11 += b1;
            }
            if (LEAKY) {
                v00 = (v00 > 0.0f) ? v00 : 0.2f * v00;
                v01 = (v01 > 0.0f) ? v01 : 0.2f * v01;
                v10 = (v10 > 0.0f) ? v10 : 0.2f * v10;
                v11 = (v11 > 0.0f) ? v11 : 0.2f * v11;
            }
            *(float2*)&C[(size_t)r0 * N + col] = make_float2(v00, v01);
            *(float2*)&C[(size_t)(r0 + 8) * N + col] = make_float2(v10, v11);
        }
    }
}

// ============================================================
// out = LayerNorm(a + b), eps = 1e-3.  One warp per row (8 rows/block).
// ============================================================
__global__ void __launch_bounds__(256)
add_ln_kernel(const float* __restrict__ a, const float* __restrict__ bvec,
              const float* __restrict__ gamma, const float* __restrict__ beta,
              float* __restrict__ out) {
    int wid = threadIdx.x >> 5, lane = threadIdx.x & 31;
    int row = blockIdx.x * 8 + wid;
    const float4* ar = (const float4*)(a + (size_t)row * DD);
    const float4* br = (const float4*)(bvec + (size_t)row * DD);
    float4 v0 = ar[lane];        float4 w0 = br[lane];
    float4 v1 = ar[lane + 32];   float4 w1 = br[lane + 32];
    v0.x += w0.x; v0.y += w0.y; v0.z += w0.z; v0.w += w0.w;
    v1.x += w1.x; v1.y += w1.y; v1.z += w1.z; v1.w += w1.w;

    float sum = v0.x + v0.y + v0.z + v0.w + v1.x + v1.y + v1.z + v1.w;
    #pragma unroll
    for (int off = 16; off > 0; off >>= 1) sum += __shfl_xor_sync(0xffffffff, sum, off);
    float mu = sum * (1.0f / DD);

    float sq = (v0.x - mu) * (v0.x - mu) + (v0.y - mu) * (v0.y - mu)
             + (v0.z - mu) * (v0.z - mu) + (v0.w - mu) * (v0.w - mu)
             + (v1.x - mu) * (v1.x - mu) + (v1.y - mu) * (v1.y - mu)
             + (v1.z - mu) * (v1.z - mu) + (v1.w - mu) * (v1.w - mu);
    #pragma unroll
    for (int off = 16; off > 0; off >>= 1) sq += __shfl_xor_sync(0xffffffff, sq, off);
    float rs = rsqrtf(sq * (1.0f / DD) + 1e-3f);

    const float4* g4 = (const float4*)gamma;
    const float4* b4 = (const float4*)beta;
    float4 g0 = g4[lane], g1 = g4[lane + 32];
    float4 e0 = b4[lane], e1 = b4[lane + 32];
    float4 o0, o1;
    o0.x = (v0.x - mu) * rs * g0.x + e0.x;
    o0.y = (v0.y - mu) * rs * g0.y + e0.y;
    o0.z = (v0.z - mu) * rs * g0.z + e0.z;
    o0.w = (v0.w - mu) * rs * g0.w + e0.w;
    o1.x = (v1.x - mu) * rs * g1.x + e1.x;
    o1.y = (v1.y - mu) * rs * g1.y + e1.y;
    o1.z = (v1.z - mu) * rs * g1.z + e1.z;
    o1.w = (v1.w - mu) * rs * g1.w + e1.w;
    float4* orow = (float4*)(out + (size_t)row * DD);
    orow[lane] = o0;
    orow[lane + 32] = o1;
}

// ============================================================
extern "C" void kernel_launch(void* const* d_in, const int* in_sizes, int n_in,
                              void* d_out, int out_size) {
    const float* inputs = (const float*)d_in[0];
    const float* ctx    = (const float*)d_in[1];
    const float* sa_Wk  = (const float*)d_in[2];
    const float* sa_Wv  = (const float*)d_in[3];
    const float* sa_Wq  = (const float*)d_in[4];
    const float* ca_Wk  = (const float*)d_in[5];
    const float* ca_Wv  = (const float*)d_in[6];
    const float* ca_Wq  = (const float*)d_in[7];
    const float* W1     = (const float*)d_in[8];
    const float* b1     = (const float*)d_in[9];
    const float* W2     = (const float*)d_in[10];
    const float* b2     = (const float*)d_in[11];
    const float* gamma  = (const float*)d_in[12];
    const float* beta   = (const float*)d_in[13];
    float* out = (float*)d_out;

    float *Qp, *Kp, *Vp, *Tp, *Xp, *Yp, *Hp;
    cudaGetSymbolAddress((void**)&Qp, g_Q);
    cudaGetSymbolAddress((void**)&Kp, g_K);
    cudaGetSymbolAddress((void**)&Vp, g_V);
    cudaGetSymbolAddress((void**)&Tp, g_T);
    cudaGetSymbolAddress((void**)&Xp, g_X);
    cudaGetSymbolAddress((void**)&Yp, g_Y);
    cudaGetSymbolAddress((void**)&Hp, g_H);

    const int flash_smem = FL_FLOATS * 4;
    cudaFuncSetAttribute(flash_mma, cudaFuncAttributeMaxDynamicSharedMemorySize, flash_smem);

    dim3 gD(DD / 64, BSROWS / 64);
    dim3 gH((HH + 63) / 64, BSROWS / 64);
    dim3 fg(SS / FBQ, BB);
    int lnB = BSROWS / 8;

    // 1) self-attention (causal)
    gemm_tc<0, 0><<<gD, 256>>>(inputs, sa_Wk, nullptr, Kp, BSROWS, DD, DD);
    gemm_tc<0, 0><<<gD, 256>>>(inputs, sa_Wv, nullptr, Vp, BSROWS, DD, DD);
    gemm_tc<0, 0><<<gD, 256>>>(inputs, sa_Wq, nullptr, Qp, BSROWS, DD, DD);
    flash_mma<<<fg, 512, flash_smem>>>(Qp, Kp, Vp, Tp, 1);
    add_ln_kernel<<<lnB, 256>>>(Tp, inputs, gamma, beta, Xp);

    // 2) cross-attention
    gemm_tc<0, 0><<<gD, 256>>>(ctx, ca_Wk, nullptr, Kp, BSROWS, DD, DD);
    gemm_tc<0, 0><<<gD, 256>>>(ctx, ca_Wv, nullptr, Vp, BSROWS, DD, DD);
    gemm_tc<0, 0><<<gD, 256>>>(Xp, ca_Wq, nullptr, Qp, BSROWS, DD, DD);
    flash_mma<<<fg, 512, flash_smem>>>(Qp, Kp, Vp, Tp, 0);
    add_ln_kernel<<<lnB, 256>>>(Tp, Xp, gamma, beta, Yp);

    // 3) FFN
    gemm_tc<1, 1><<<gH, 256>>>(Yp, W1, b1, Hp, BSROWS, HH, DD);
    gemm_tc<1, 0><<<gD, 256>>>(Hp, W2, b2, Tp, BSROWS, DD, HH);
    add_ln_kernel<<<lnB, 256>>>(Tp, Yp, gamma, beta, out);
}

// round 8
// speedup vs baseline: 1.0002x; 1.0002x over previous
#include <cuda_runtime.h>
#include <cstdint>
#include <math.h>

#define BB 4
#define SS 4096
#define DD 256
#define HH 400
#define BSROWS (BB*SS)

// ---- scratch ----
__device__ float g_Q[BSROWS*DD];
__device__ float g_K[BSROWS*DD];
__device__ float g_V[BSROWS*DD];
__device__ float g_T[BSROWS*DD];
__device__ float g_X[BSROWS*DD];
__device__ float g_Y[BSROWS*DD];
__device__ float g_H[BSROWS*HH];

// ============================================================
// helpers
// ============================================================
__device__ __forceinline__ float tf32r(float x) {
    float r; asm("cvt.rna.tf32.f32 %0, %1;" : "=f"(r) : "f"(x)); return r;
}
__device__ __forceinline__ void mma8(float c[4], const uint32_t a[4], const uint32_t b[2]) {
    asm volatile(
        "mma.sync.aligned.m16n8k8.row.col.f32.tf32.tf32.f32 "
        "{%0,%1,%2,%3}, {%4,%5,%6,%7}, {%8,%9}, {%0,%1,%2,%3};"
        : "+f"(c[0]), "+f"(c[1]), "+f"(c[2]), "+f"(c[3])
        : "r"(a[0]), "r"(a[1]), "r"(a[2]), "r"(a[3]), "r"(b[0]), "r"(b[1]));
}
__device__ __forceinline__ uint32_t f2u(float x) { return __float_as_uint(x); }

// ============================================================
// Flash attention, tf32 HMMA, BIG warp tiles (crossbar-minimal).
// CTA: 64 queries, 128 threads (4 warps = 2 row-groups x 2 halves).
// Scores: warp tile 32x32.  PV: warp tile 32x128.
// K/V chunks of 64 keys. SMEM 218.9 KB, 1 CTA/SM.
// ============================================================
#define FBQ 64
#define FBK 64
#define QSTR 260
#define KSTR 260
#define VSTR 264
#define SSTR 68
// f32 offsets in dynamic smem
#define OQ  0
#define OK  16640                 // 64*260
#define OV  33280                 // + 64*260
#define OS  50176                 // + 64*264
#define OM  54528                 // + 64*68
#define OL  54592
#define OA  54656
#define FL_FLOATS 54720           // *4 = 218880 bytes

__global__ void __launch_bounds__(128, 1)
flash_mma(const float* __restrict__ Qg, const float* __restrict__ Kg,
          const float* __restrict__ Vg, float* __restrict__ Og, int causal) {
    extern __shared__ float fs[];
    int tid = threadIdx.x;
    int wid = tid >> 5, lane = tid & 31;
    int rg = wid >> 1;        // row-group: rows 32*rg .. +31
    int h  = wid & 1;         // half: score cols 32h..+31 / O cols 128h..+127
    int lrow = lane >> 2;
    int lcol = lane & 3;
    int b = blockIdx.y, q0 = blockIdx.x * FBQ;

    // ---- stage Q (prescaled by 1/sqrt(4096)=1/64, rna-tf32) ----
    {
        const float4* Qr = (const float4*)(Qg + ((size_t)b * SS + q0) * DD);
        #pragma unroll
        for (int p = 0; p < 32; p++) {
            int idx = tid + p * 128;
            int r = idx >> 6, c4 = idx & 63;
            float4 v = Qr[r * 64 + c4];
            v.x = tf32r(v.x * 0.015625f); v.y = tf32r(v.y * 0.015625f);
            v.z = tf32r(v.z * 0.015625f); v.w = tf32r(v.w * 0.015625f);
            *(float4*)&fs[OQ + r * QSTR + c4 * 4] = v;
        }
    }
    if (tid < FBQ) { fs[OM + tid] = -INFINITY; fs[OL + tid] = 0.0f; }

    // O accumulator: 2 m-tiles x 16 n-tiles of c[4]  (128 regs)
    float ofrag[2][16][4];
    #pragma unroll
    for (int mt = 0; mt < 2; mt++)
        #pragma unroll
        for (int nb = 0; nb < 16; nb++)
            #pragma unroll
            for (int j = 0; j < 4; j++) ofrag[mt][nb][j] = 0.0f;

    int nc = causal ? (blockIdx.x + 1) : (SS / FBK);

    for (int c = 0; c < nc; c++) {
        int k0 = c * FBK;
        bool maskc = causal && (k0 == q0);

        // ---- stage K and V (row-major, rna-tf32) ----
        {
            const float4* Kr = (const float4*)(Kg + ((size_t)b * SS + k0) * DD);
            const float4* Vr = (const float4*)(Vg + ((size_t)b * SS + k0) * DD);
            #pragma unroll
            for (int p = 0; p < 32; p++) {
                int idx = tid + p * 128;
                int r = idx >> 6, c4 = idx & 63;
                float4 v = Kr[r * 64 + c4];
                v.x = tf32r(v.x); v.y = tf32r(v.y); v.z = tf32r(v.z); v.w = tf32r(v.w);
                *(float4*)&fs[OK + r * KSTR + c4 * 4] = v;
                float4 w = Vr[r * 64 + c4];
                w.x = tf32r(w.x); w.y = tf32r(w.y); w.z = tf32r(w.z); w.w = tf32r(w.w);
                *(float4*)&fs[OV + r * VSTR + c4 * 4] = w;
            }
        }
        __syncthreads();   // (A)

        // ---- scores: warp (rg,h): S[32rg..+31][32h..+31] ----
        {
            float sfr[2][4][4];
            #pragma unroll
            for (int mt = 0; mt < 2; mt++)
                #pragma unroll
                for (int nb = 0; nb < 4; nb++)
                    #pragma unroll
                    for (int j = 0; j < 4; j++) sfr[mt][nb][j] = 0.0f;

            #pragma unroll 8
            for (int kb = 0; kb < 32; kb++) {
                int kk = kb * 8 + lcol;
                uint32_t a[2][4];
                #pragma unroll
                for (int mt = 0; mt < 2; mt++) {
                    int qr = 32 * rg + 16 * mt + lrow;
                    a[mt][0] = f2u(fs[OQ + qr * QSTR + kk]);
                    a[mt][1] = f2u(fs[OQ + (qr + 8) * QSTR + kk]);
                    a[mt][2] = f2u(fs[OQ + qr * QSTR + kk + 4]);
                    a[mt][3] = f2u(fs[OQ + (qr + 8) * QSTR + kk + 4]);
                }
                #pragma unroll
                for (int nb = 0; nb < 4; nb++) {
                    int nrow = 32 * h + nb * 8 + lrow;
                    uint32_t b2[2];
                    b2[0] = f2u(fs[OK + nrow * KSTR + kk]);
                    b2[1] = f2u(fs[OK + nrow * KSTR + kk + 4]);
                    mma8(sfr[0][nb], a[0], b2);
                    mma8(sfr[1][nb], a[1], b2);
                }
            }
            #pragma unroll
            for (int mt = 0; mt < 2; mt++) {
                int r0 = 32 * rg + 16 * mt + lrow;
                int grow0 = q0 + r0;
                #pragma unroll
                for (int nb = 0; nb < 4; nb++) {
                    int cb0 = 32 * h + nb * 8 + 2 * lcol;
                    float2 v0 = make_float2(sfr[mt][nb][0], sfr[mt][nb][1]);
                    float2 v1 = make_float2(sfr[mt][nb][2], sfr[mt][nb][3]);
                    if (maskc) {
                        int g = k0 + cb0;
                        if (g > grow0)         v0.x = -1e30f;
                        if (g + 1 > grow0)     v0.y = -1e30f;
                        if (g > grow0 + 8)     v1.x = -1e30f;
                        if (g + 1 > grow0 + 8) v1.y = -1e30f;
                    }
                    *(float2*)&fs[OS + r0 * SSTR + cb0] = v0;
                    *(float2*)&fs[OS + (r0 + 8) * SSTR + cb0] = v1;
                }
            }
        }
        __syncthreads();   // (B)

        // ---- online softmax: 2 threads per row, 32 cols each ----
        {
            int row = tid >> 1, seg = tid & 1;
            float* Sr = &fs[OS + row * SSTR + seg * 32];
            float4 x[8];
            #pragma unroll
            for (int i = 0; i < 8; i++) x[i] = ((float4*)Sr)[i];
            float mx = -INFINITY;
            #pragma unroll
            for (int i = 0; i < 8; i++)
                mx = fmaxf(mx, fmaxf(fmaxf(x[i].x, x[i].y), fmaxf(x[i].z, x[i].w)));
            mx = fmaxf(mx, __shfl_xor_sync(0xffffffff, mx, 1));
            float mold = fs[OM + row];
            float mnew = fmaxf(mold, mx);
            float alpha = __expf(mold - mnew);
            float sum = 0.0f;
            #pragma unroll
            for (int i = 0; i < 8; i++) {
                x[i].x = __expf(x[i].x - mnew); x[i].y = __expf(x[i].y - mnew);
                x[i].z = __expf(x[i].z - mnew); x[i].w = __expf(x[i].w - mnew);
                sum += x[i].x + x[i].y + x[i].z + x[i].w;
                x[i].x = tf32r(x[i].x); x[i].y = tf32r(x[i].y);
                x[i].z = tf32r(x[i].z); x[i].w = tf32r(x[i].w);
                ((float4*)Sr)[i] = x[i];
            }
            sum += __shfl_xor_sync(0xffffffff, sum, 1);
            if (seg == 0) {
                fs[OL + row] = fs[OL + row] * alpha + sum;
                fs[OM + row] = mnew;
                fs[OA + row] = alpha;
            }
        }
        __syncthreads();   // (C)

        // ---- PV: warp (rg,h): O[32rg..+31][128h..+127] += P * V ----
        {
            float al[2][2];
            #pragma unroll
            for (int mt = 0; mt < 2; mt++) {
                al[mt][0] = fs[OA + 32 * rg + 16 * mt + lrow];
                al[mt][1] = fs[OA + 32 * rg + 16 * mt + lrow + 8];
            }
            #pragma unroll
            for (int mt = 0; mt < 2; mt++)
                #pragma unroll
                for (int nb = 0; nb < 16; nb++) {
                    ofrag[mt][nb][0] *= al[mt][0]; ofrag[mt][nb][1] *= al[mt][0];
                    ofrag[mt][nb][2] *= al[mt][1]; ofrag[mt][nb][3] *= al[mt][1];
                }
            #pragma unroll
            for (int kb = 0; kb < 8; kb++) {
                int kk = kb * 8 + lcol;
                uint32_t pa[2][4];
                #pragma unroll
                for (int mt = 0; mt < 2; mt++) {
                    int pr = 32 * rg + 16 * mt + lrow;
                    pa[mt][0] = f2u(fs[OS + pr * SSTR + kk]);
                    pa[mt][1] = f2u(fs[OS + (pr + 8) * SSTR + kk]);
                    pa[mt][2] = f2u(fs[OS + pr * SSTR + kk + 4]);
                    pa[mt][3] = f2u(fs[OS + (pr + 8) * SSTR + kk + 4]);
                }
                #pragma unroll
                for (int nb = 0; nb < 16; nb++) {
                    int ncol = 128 * h + nb * 8 + lrow;
                    uint32_t b2[2];
                    b2[0] = f2u(fs[OV + kk * VSTR + ncol]);
                    b2[1] = f2u(fs[OV + (kk + 4) * VSTR + ncol]);
                    mma8(ofrag[0][nb], pa[0], b2);
                    mma8(ofrag[1][nb], pa[1], b2);
                }
            }
        }
        __syncthreads();   // (D)
    }

    // ---- epilogue ----
    #pragma unroll
    for (int mt = 0; mt < 2; mt++) {
        int row = 32 * rg + 16 * mt + lrow;
        float inv0 = 1.0f / fs[OL + row];
        float inv8 = 1.0f / fs[OL + row + 8];
        float* Or0 = Og + ((size_t)b * SS + q0 + row) * DD;
        float* Or8 = Or0 + 8 * DD;
        #pragma unroll
        for (int nb = 0; nb < 16; nb++) {
            int col = 128 * h + nb * 8 + 2 * lcol;
            *(float2*)&Or0[col] = make_float2(ofrag[mt][nb][0] * inv0, ofrag[mt][nb][1] * inv0);
            *(float2*)&Or8[col] = make_float2(ofrag[mt][nb][2] * inv8, ofrag[mt][nb][3] * inv8);
        }
    }
}

// ============================================================
// tf32 HMMA GEMM v2: BM=128, BN=128, BK=16, double-buffered.
// 256 threads (8 warps = 4m x 2n), warp tile 32x64.
// M%128==0, K%16==0 required; N guarded (N%4==0 assumed).
// ============================================================
#define ASTR 20
#define WSTR 136

template<int BIAS, int LEAKY>
__global__ void __launch_bounds__(256, 2)
gemm_tc(const float* __restrict__ A, const float* __restrict__ W,
        const float* __restrict__ bias, float* __restrict__ C,
        int M, int N, int K) {
    __shared__ float As[2][128 * ASTR];
    __shared__ float Ws[2][16 * WSTR];
    int tid = threadIdx.x;
    int wid = tid >> 5, lane = tid & 31;
    int wm = wid & 3, wn = wid >> 2;
    int lrow = lane >> 2, lcol = lane & 3;
    int rb = blockIdx.y * 128, cb = blockIdx.x * 128;

    // staging maps
    int ar = tid & 127;           // A row
    int ak = (tid >> 7) * 8;      // A col base (two f4: ak, ak+4)
    int wr = wid;                 // W rows wr, wr+8
    int wc = lane * 4;            // W col offset (one f4 per row)
    int wcol = cb + wc;
    bool wok = (wcol < N);        // N%4==0 so whole f4 in/out

    float cfr[2][8][4];
    #pragma unroll
    for (int mt = 0; mt < 2; mt++)
        #pragma unroll
        for (int nb = 0; nb < 8; nb++)
            #pragma unroll
            for (int j = 0; j < 4; j++) cfr[mt][nb][j] = 0.0f;

    // ---- prologue: stage k0=0 into buf 0 ----
    {
        float4 a0 = *(const float4*)&A[(size_t)(rb + ar) * K + ak];
        float4 a1 = *(const float4*)&A[(size_t)(rb + ar) * K + ak + 4];
        a0.x = tf32r(a0.x); a0.y = tf32r(a0.y); a0.z = tf32r(a0.z); a0.w = tf32r(a0.w);
        a1.x = tf32r(a1.x); a1.y = tf32r(a1.y); a1.z = tf32r(a1.z); a1.w = tf32r(a1.w);
        *(float4*)&As[0][ar * ASTR + ak] = a0;
        *(float4*)&As[0][ar * ASTR + ak + 4] = a1;
        float4 w0 = make_float4(0.f, 0.f, 0.f, 0.f), w1 = w0;
        if (wok) {
            w0 = *(const float4*)&W[(size_t)wr * N + wcol];
            w1 = *(const float4*)&W[(size_t)(wr + 8) * N + wcol];
        }
        w0.x = tf32r(w0.x); w0.y = tf32r(w0.y); w0.z = tf32r(w0.z); w0.w = tf32r(w0.w);
        w1.x = tf32r(w1.x); w1.y = tf32r(w1.y); w1.z = tf32r(w1.z); w1.w = tf32r(w1.w);
        *(float4*)&Ws[0][wr * WSTR + wc] = w0;
        *(float4*)&Ws[0][(wr + 8) * WSTR + wc] = w1;
    }
    __syncthreads();

    int buf = 0;
    for (int k0 = 0; k0 < K; k0 += 16) {
        bool more = (k0 + 16) < K;
        float4 a0, a1, w0, w1;
        if (more) {
            a0 = *(const float4*)&A[(size_t)(rb + ar) * K + k0 + 16 + ak];
            a1 = *(const float4*)&A[(size_t)(rb + ar) * K + k0 + 16 + ak + 4];
            if (wok) {
                w0 = *(const float4*)&W[(size_t)(k0 + 16 + wr) * N + wcol];
                w1 = *(const float4*)&W[(size_t)(k0 + 16 + wr + 8) * N + wcol];
            } else {
                w0 = make_float4(0.f, 0.f, 0.f, 0.f); w1 = w0;
            }
        }

        // ---- compute on current buffer ----
        #pragma unroll
        for (int kb = 0; kb < 2; kb++) {
            int kk = kb * 8 + lcol;
            uint32_t a[2][4];
            #pragma unroll
            for (int mt = 0; mt < 2; mt++) {
                int row = 32 * wm + 16 * mt + lrow;
                a[mt][0] = f2u(As[buf][row * ASTR + kk]);
                a[mt][1] = f2u(As[buf][(row + 8) * ASTR + kk]);
                a[mt][2] = f2u(As[buf][row * ASTR + kk + 4]);
                a[mt][3] = f2u(As[buf][(row + 8) * ASTR + kk + 4]);
            }
            #pragma unroll
            for (int nb = 0; nb < 8; nb++) {
                int ncol = 64 * wn + nb * 8 + lrow;
                uint32_t b2[2];
                b2[0] = f2u(Ws[buf][kk * WSTR + ncol]);
                b2[1] = f2u(Ws[buf][(kk + 4) * WSTR + ncol]);
                mma8(cfr[0][nb], a[0], b2);
                mma8(cfr[1][nb], a[1], b2);
            }
        }

        if (more) {
            a0.x = tf32r(a0.x); a0.y = tf32r(a0.y); a0.z = tf32r(a0.z); a0.w = tf32r(a0.w);
            a1.x = tf32r(a1.x); a1.y = tf32r(a1.y); a1.z = tf32r(a1.z); a1.w = tf32r(a1.w);
            *(float4*)&As[buf ^ 1][ar * ASTR + ak] = a0;
            *(float4*)&As[buf ^ 1][ar * ASTR + ak + 4] = a1;
            w0.x = tf32r(w0.x); w0.y = tf32r(w0.y); w0.z = tf32r(w0.z); w0.w = tf32r(w0.w);
            w1.x = tf32r(w1.x); w1.y = tf32r(w1.y); w1.z = tf32r(w1.z); w1.w = tf32r(w1.w);
            *(float4*)&Ws[buf ^ 1][wr * WSTR + wc] = w0;
            *(float4*)&Ws[buf ^ 1][(wr + 8) * WSTR + wc] = w1;
        }
        __syncthreads();
        buf ^= 1;
    }

    // ---- epilogue ----
    #pragma unroll
    for (int mt = 0; mt < 2; mt++) {
        int r0 = rb + 32 * wm + 16 * mt + lrow;
        #pragma unroll
        for (int nb = 0; nb < 8; nb++) {
            int col = cb + 64 * wn + nb * 8 + 2 * lcol;
            if (col < N) {
                float v00 = cfr[mt][nb][0], v01 = cfr[mt][nb][1];
                float v10 = cfr[mt][nb][2], v11 = cfr[mt][nb][3];
                if (BIAS) {
                    float b0 = bias[col], b1 = bias[col + 1];
                    v00 += b0; v01 += b1; v10 += b0; v11 += b1;
                }
                if (LEAKY) {
                    v00 = (v00 > 0.0f) ? v00 : 0.2f * v00;
                    v01 = (v01 > 0.0f) ? v01 : 0.2f * v01;
                    v10 = (v10 > 0.0f) ? v10 : 0.2f * v10;
                    v11 = (v11 > 0.0f) ? v11 : 0.2f * v11;
                }
                *(float2*)&C[(size_t)r0 * N + col] = make_float2(v00, v01);
                *(float2*)&C[(size_t)(r0 + 8) * N + col] = make_float2(v10, v11);
            }
        }
    }
}

// ============================================================
// out = LayerNorm(a + b), eps = 1e-3.  One warp per row (8 rows/block).
// ============================================================
__global__ void __launch_bounds__(256)
add_ln_kernel(const float* __restrict__ a, const float* __restrict__ bvec,
              const float* __restrict__ gamma, const float* __restrict__ beta,
              float* __restrict__ out) {
    int wid = threadIdx.x >> 5, lane = threadIdx.x & 31;
    int row = blockIdx.x * 8 + wid;
    const float4* ar = (const float4*)(a + (size_t)row * DD);
    const float4* br = (const float4*)(bvec + (size_t)row * DD);
    float4 v0 = ar[lane];        float4 w0 = br[lane];
    float4 v1 = ar[lane + 32];   float4 w1 = br[lane + 32];
    v0.x += w0.x; v0.y += w0.y; v0.z += w0.z; v0.w += w0.w;
    v1.x += w1.x; v1.y += w1.y; v1.z += w1.z; v1.w += w1.w;

    float sum = v0.x + v0.y + v0.z + v0.w + v1.x + v1.y + v1.z + v1.w;
    #pragma unroll
    for (int off = 16; off > 0; off >>= 1) sum += __shfl_xor_sync(0xffffffff, sum, off);
    float mu = sum * (1.0f / DD);

    float sq = (v0.x - mu) * (v0.x - mu) + (v0.y - mu) * (v0.y - mu)
             + (v0.z - mu) * (v0.z - mu) + (v0.w - mu) * (v0.w - mu)
             + (v1.x - mu) * (v1.x - mu) + (v1.y - mu) * (v1.y - mu)
             + (v1.z - mu) * (v1.z - mu) + (v1.w - mu) * (v1.w - mu);
    #pragma unroll
    for (int off = 16; off > 0; off >>= 1) sq += __shfl_xor_sync(0xffffffff, sq, off);
    float rs = rsqrtf(sq * (1.0f / DD) + 1e-3f);

    const float4* g4 = (const float4*)gamma;
    const float4* b4 = (const float4*)beta;
    float4 g0 = g4[lane], g1 = g4[lane + 32];
    float4 e0 = b4[lane], e1 = b4[lane + 32];
    float4 o0, o1;
    o0.x = (v0.x - mu) * rs * g0.x + e0.x;
    o0.y = (v0.y - mu) * rs * g0.y + e0.y;
    o0.z = (v0.z - mu) * rs * g0.z + e0.z;
    o0.w = (v0.w - mu) * rs * g0.w + e0.w;
    o1.x = (v1.x - mu) * rs * g1.x + e1.x;
    o1.y = (v1.y - mu) * rs * g1.y + e1.y;
    o1.z = (v1.z - mu) * rs * g1.z + e1.z;
    o1.w = (v1.w - mu) * rs * g1.w + e1.w;
    float4* orow = (float4*)(out + (size_t)row * DD);
    orow[lane] = o0;
    orow[lane + 32] = o1;
}

// ============================================================
extern "C" void kernel_launch(void* const* d_in, const int* in_sizes, int n_in,
                              void* d_out, int out_size) {
    const float* inputs = (const float*)d_in[0];
    const float* ctx    = (const float*)d_in[1];
    const float* sa_Wk  = (const float*)d_in[2];
    const float* sa_Wv  = (const float*)d_in[3];
    const float* sa_Wq  = (const float*)d_in[4];
    const float* ca_Wk  = (const float*)d_in[5];
    const float* ca_Wv  = (const float*)d_in[6];
    const float* ca_Wq  = (const float*)d_in[7];
    const float* W1     = (const float*)d_in[8];
    const float* b1     = (const float*)d_in[9];
    const float* W2     = (const float*)d_in[10];
    const float* b2     = (const float*)d_in[11];
    const float* gamma  = (const float*)d_in[12];
    const float* beta   = (const float*)d_in[13];
    float* out = (float*)d_out;

    float *Qp, *Kp, *Vp, *Tp, *Xp, *Yp, *Hp;
    cudaGetSymbolAddress((void**)&Qp, g_Q);
    cudaGetSymbolAddress((void**)&Kp, g_K);
    cudaGetSymbolAddress((void**)&Vp, g_V);
    cudaGetSymbolAddress((void**)&Tp, g_T);
    cudaGetSymbolAddress((void**)&Xp, g_X);
    cudaGetSymbolAddress((void**)&Yp, g_Y);
    cudaGetSymbolAddress((void**)&Hp, g_H);

    const int flash_smem = FL_FLOATS * 4;
    cudaFuncSetAttribute(flash_mma, cudaFuncAttributeMaxDynamicSharedMemorySize, flash_smem);

    dim3 gD(DD / 128, BSROWS / 128);            // projections / FFN2: N=256
    dim3 gH((HH + 127) / 128, BSROWS / 128);    // FFN1: N=400
    dim3 fg(SS / FBQ, BB);
    int lnB = BSROWS / 8;

    // 1) self-attention (causal)
    gemm_tc<0, 0><<<gD, 256>>>(inputs, sa_Wk, nullptr, Kp, BSROWS, DD, DD);
    gemm_tc<0, 0><<<gD, 256>>>(inputs, sa_Wv, nullptr, Vp, BSROWS, DD, DD);
    gemm_tc<0, 0><<<gD, 256>>>(inputs, sa_Wq, nullptr, Qp, BSROWS, DD, DD);
    flash_mma<<<fg, 128, flash_smem>>>(Qp, Kp, Vp, Tp, 1);
    add_ln_kernel<<<lnB, 256>>>(Tp, inputs, gamma, beta, Xp);

    // 2) cross-attention
    gemm_tc<0, 0><<<gD, 256>>>(ctx, ca_Wk, nullptr, Kp, BSROWS, DD, DD);
    gemm_tc<0, 0><<<gD, 256>>>(ctx, ca_Wv, nullptr, Vp, BSROWS, DD, DD);
    gemm_tc<0, 0><<<gD, 256>>>(Xp, ca_Wq, nullptr, Qp, BSROWS, DD, DD);
    flash_mma<<<fg, 128, flash_smem>>>(Qp, Kp, Vp, Tp, 0);
    add_ln_kernel<<<lnB, 256>>>(Tp, Xp, gamma, beta, Yp);

    // 3) FFN
    gemm_tc<1, 1><<<gH, 256>>>(Yp, W1, b1, Hp, BSROWS, HH, DD);
    gemm_tc<1, 0><<<gD, 256>>>(Hp, W2, b2, Tp, BSROWS, DD, HH);
    add_ln_kernel<<<lnB, 256>>>(Tp, Yp, gamma, beta, out);
}

// round 9
// speedup vs baseline: 1.0076x; 1.0074x over previous
#include <cuda_runtime.h>
#include <cstdint>
#include <math.h>

#define BB 4
#define SS 4096
#define DD 256
#define HH 400
#define BSROWS (BB*SS)

// ---- scratch ----
__device__ float g_Q[BSROWS*DD];
__device__ float g_K[BSROWS*DD];
__device__ float g_V[BSROWS*DD];
__device__ float g_T[BSROWS*DD];
__device__ float g_X[BSROWS*DD];
__device__ float g_Y[BSROWS*DD];
__device__ float g_H[BSROWS*HH];

// ============================================================
// helpers
// ============================================================
__device__ __forceinline__ float tf32r(float x) {
    float r; asm("cvt.rna.tf32.f32 %0, %1;" : "=f"(r) : "f"(x)); return r;
}
__device__ __forceinline__ void mma8(float c[4], const uint32_t a[4], const uint32_t b[2]) {
    asm volatile(
        "mma.sync.aligned.m16n8k8.row.col.f32.tf32.tf32.f32 "
        "{%0,%1,%2,%3}, {%4,%5,%6,%7}, {%8,%9}, {%0,%1,%2,%3};"
        : "+f"(c[0]), "+f"(c[1]), "+f"(c[2]), "+f"(c[3])
        : "r"(a[0]), "r"(a[1]), "r"(a[2]), "r"(a[3]), "r"(b[0]), "r"(b[1]));
}
__device__ __forceinline__ uint32_t f2u(float x) { return __float_as_uint(x); }

// ============================================================
// Flash attention, tf32 HMMA, BIG warp tiles (crossbar-minimal).
// CTA: 64 queries, 128 threads (4 warps = 2 row-groups x 2 halves).
// Scores: warp tile 32x32.  PV: warp tile 32x128.
// K/V chunks of 64 keys. SMEM 218.9 KB, 1 CTA/SM.
// ============================================================
#define FBQ 64
#define FBK 64
#define QSTR 260
#define KSTR 260
#define VSTR 264
#define SSTR 68
// f32 offsets in dynamic smem
#define OQ  0
#define OK  16640                 // 64*260
#define OV  33280                 // + 64*260
#define OS  50176                 // + 64*264
#define OM  54528                 // + 64*68
#define OL  54592
#define OA  54656
#define FL_FLOATS 54720           // *4 = 218880 bytes

__global__ void __launch_bounds__(128, 1)
flash_mma(const float* __restrict__ Qg, const float* __restrict__ Kg,
          const float* __restrict__ Vg, float* __restrict__ Og, int causal) {
    extern __shared__ float fs[];
    int tid = threadIdx.x;
    int wid = tid >> 5, lane = tid & 31;
    int rg = wid >> 1;        // row-group: rows 32*rg .. +31
    int h  = wid & 1;         // half: score cols 32h..+31 / O cols 128h..+127
    int lrow = lane >> 2;
    int lcol = lane & 3;
    int b = blockIdx.y, q0 = blockIdx.x * FBQ;

    // ---- stage Q (prescaled by 1/sqrt(4096)=1/64, rna-tf32) ----
    {
        const float4* Qr = (const float4*)(Qg + ((size_t)b * SS + q0) * DD);
        #pragma unroll
        for (int p = 0; p < 32; p++) {
            int idx = tid + p * 128;
            int r = idx >> 6, c4 = idx & 63;
            float4 v = Qr[r * 64 + c4];
            v.x = tf32r(v.x * 0.015625f); v.y = tf32r(v.y * 0.015625f);
            v.z = tf32r(v.z * 0.015625f); v.w = tf32r(v.w * 0.015625f);
            *(float4*)&fs[OQ + r * QSTR + c4 * 4] = v;
        }
    }
    if (tid < FBQ) { fs[OM + tid] = -INFINITY; fs[OL + tid] = 0.0f; }

    // O accumulator: 2 m-tiles x 16 n-tiles of c[4]  (128 regs)
    float ofrag[2][16][4];
    #pragma unroll
    for (int mt = 0; mt < 2; mt++)
        #pragma unroll
        for (int nb = 0; nb < 16; nb++)
            #pragma unroll
            for (int j = 0; j < 4; j++) ofrag[mt][nb][j] = 0.0f;

    int nc = causal ? (blockIdx.x + 1) : (SS / FBK);

    for (int c = 0; c < nc; c++) {
        int k0 = c * FBK;
        bool maskc = causal && (k0 == q0);

        // ---- stage K and V (row-major, rna-tf32) ----
        {
            const float4* Kr = (const float4*)(Kg + ((size_t)b * SS + k0) * DD);
            const float4* Vr = (const float4*)(Vg + ((size_t)b * SS + k0) * DD);
            #pragma unroll
            for (int p = 0; p < 32; p++) {
                int idx = tid + p * 128;
                int r = idx >> 6, c4 = idx & 63;
                float4 v = Kr[r * 64 + c4];
                v.x = tf32r(v.x); v.y = tf32r(v.y); v.z = tf32r(v.z); v.w = tf32r(v.w);
                *(float4*)&fs[OK + r * KSTR + c4 * 4] = v;
                float4 w = Vr[r * 64 + c4];
                w.x = tf32r(w.x); w.y = tf32r(w.y); w.z = tf32r(w.z); w.w = tf32r(w.w);
                *(float4*)&fs[OV + r * VSTR + c4 * 4] = w;
            }
        }
        __syncthreads();   // (A)

        // ---- scores: warp (rg,h): S[32rg..+31][32h..+31] ----
        {
            float sfr[2][4][4];
            #pragma unroll
            for (int mt = 0; mt < 2; mt++)
                #pragma unroll
                for (int nb = 0; nb < 4; nb++)
                    #pragma unroll
                    for (int j = 0; j < 4; j++) sfr[mt][nb][j] = 0.0f;

            #pragma unroll 8
            for (int kb = 0; kb < 32; kb++) {
                int kk = kb * 8 + lcol;
                uint32_t a[2][4];
                #pragma unroll
                for (int mt = 0; mt < 2; mt++) {
                    int qr = 32 * rg + 16 * mt + lrow;
                    a[mt][0] = f2u(fs[OQ + qr * QSTR + kk]);
                    a[mt][1] = f2u(fs[OQ + (qr + 8) * QSTR + kk]);
                    a[mt][2] = f2u(fs[OQ + qr * QSTR + kk + 4]);
                    a[mt][3] = f2u(fs[OQ + (qr + 8) * QSTR + kk + 4]);
                }
                #pragma unroll
                for (int nb = 0; nb < 4; nb++) {
                    int nrow = 32 * h + nb * 8 + lrow;
                    uint32_t b2[2];
                    b2[0] = f2u(fs[OK + nrow * KSTR + kk]);
                    b2[1] = f2u(fs[OK + nrow * KSTR + kk + 4]);
                    mma8(sfr[0][nb], a[0], b2);
                    mma8(sfr[1][nb], a[1], b2);
                }
            }
            #pragma unroll
            for (int mt = 0; mt < 2; mt++) {
                int r0 = 32 * rg + 16 * mt + lrow;
                int grow0 = q0 + r0;
                #pragma unroll
                for (int nb = 0; nb < 4; nb++) {
                    int cb0 = 32 * h + nb * 8 + 2 * lcol;
                    float2 v0 = make_float2(sfr[mt][nb][0], sfr[mt][nb][1]);
                    float2 v1 = make_float2(sfr[mt][nb][2], sfr[mt][nb][3]);
                    if (maskc) {
                        int g = k0 + cb0;
                        if (g > grow0)         v0.x = -1e30f;
                        if (g + 1 > grow0)     v0.y = -1e30f;
                        if (g > grow0 + 8)     v1.x = -1e30f;
                        if (g + 1 > grow0 + 8) v1.y = -1e30f;
                    }
                    *(float2*)&fs[OS + r0 * SSTR + cb0] = v0;
                    *(float2*)&fs[OS + (r0 + 8) * SSTR + cb0] = v1;
                }
            }
        }
        __syncthreads();   // (B)

        // ---- online softmax: 2 threads per row, 32 cols each ----
        {
            int row = tid >> 1, seg = tid & 1;
            float* Sr = &fs[OS + row * SSTR + seg * 32];
            float4 x[8];
            #pragma unroll
            for (int i = 0; i < 8; i++) x[i] = ((float4*)Sr)[i];
            float mx = -INFINITY;
            #pragma unroll
            for (int i = 0; i < 8; i++)
                mx = fmaxf(mx, fmaxf(fmaxf(x[i].x, x[i].y), fmaxf(x[i].z, x[i].w)));
            mx = fmaxf(mx, __shfl_xor_sync(0xffffffff, mx, 1));
            float mold = fs[OM + row];
            float mnew = fmaxf(mold, mx);
            float alpha = __expf(mold - mnew);
            float sum = 0.0f;
            #pragma unroll
            for (int i = 0; i < 8; i++) {
                x[i].x = __expf(x[i].x - mnew); x[i].y = __expf(x[i].y - mnew);
                x[i].z = __expf(x[i].z - mnew); x[i].w = __expf(x[i].w - mnew);
                sum += x[i].x + x[i].y + x[i].z + x[i].w;
                x[i].x = tf32r(x[i].x); x[i].y = tf32r(x[i].y);
                x[i].z = tf32r(x[i].z); x[i].w = tf32r(x[i].w);
                ((float4*)Sr)[i] = x[i];
            }
            sum += __shfl_xor_sync(0xffffffff, sum, 1);
            if (seg == 0) {
                fs[OL + row] = fs[OL + row] * alpha + sum;
                fs[OM + row] = mnew;
                fs[OA + row] = alpha;
            }
        }
        __syncthreads();   // (C)

        // ---- PV: warp (rg,h): O[32rg..+31][128h..+127] += P * V ----
        {
            float al[2][2];
            #pragma unroll
            for (int mt = 0; mt < 2; mt++) {
                al[mt][0] = fs[OA + 32 * rg + 16 * mt + lrow];
                al[mt][1] = fs[OA + 32 * rg + 16 * mt + lrow + 8];
            }
            #pragma unroll
            for (int mt = 0; mt < 2; mt++)
                #pragma unroll
                for (int nb = 0; nb < 16; nb++) {
                    ofrag[mt][nb][0] *= al[mt][0]; ofrag[mt][nb][1] *= al[mt][0];
                    ofrag[mt][nb][2] *= al[mt][1]; ofrag[mt][nb][3] *= al[mt][1];
                }
            #pragma unroll
            for (int kb = 0; kb < 8; kb++) {
                int kk = kb * 8 + lcol;
                uint32_t pa[2][4];
                #pragma unroll
                for (int mt = 0; mt < 2; mt++) {
                    int pr = 32 * rg + 16 * mt + lrow;
                    pa[mt][0] = f2u(fs[OS + pr * SSTR + kk]);
                    pa[mt][1] = f2u(fs[OS + (pr + 8) * SSTR + kk]);
                    pa[mt][2] = f2u(fs[OS + pr * SSTR + kk + 4]);
                    pa[mt][3] = f2u(fs[OS + (pr + 8) * SSTR + kk + 4]);
                }
                #pragma unroll
                for (int nb = 0; nb < 16; nb++) {
                    int ncol = 128 * h + nb * 8 + lrow;
                    uint32_t b2[2];
                    b2[0] = f2u(fs[OV + kk * VSTR + ncol]);
                    b2[1] = f2u(fs[OV + (kk + 4) * VSTR + ncol]);
                    mma8(ofrag[0][nb], pa[0], b2);
                    mma8(ofrag[1][nb], pa[1], b2);
                }
            }
        }
        __syncthreads();   // (D)
    }

    // ---- epilogue ----
    #pragma unroll
    for (int mt = 0; mt < 2; mt++) {
        int row = 32 * rg + 16 * mt + lrow;
        float inv0 = 1.0f / fs[OL + row];
        float inv8 = 1.0f / fs[OL + row + 8];
        float* Or0 = Og + ((size_t)b * SS + q0 + row) * DD;
        float* Or8 = Or0 + 8 * DD;
        #pragma unroll
        for (int nb = 0; nb < 16; nb++) {
            int col = 128 * h + nb * 8 + 2 * lcol;
            *(float2*)&Or0[col] = make_float2(ofrag[mt][nb][0] * inv0, ofrag[mt][nb][1] * inv0);
            *(float2*)&Or8[col] = make_float2(ofrag[mt][nb][2] * inv8, ofrag[mt][nb][3] * inv8);
        }
    }
}

// ============================================================
// tf32 HMMA GEMM v2: BM=128, BN=128, BK=16, double-buffered.
// 256 threads (8 warps = 4m x 2n), warp tile 32x64.
// M%128==0, K%16==0 required; N guarded (N%4==0 assumed).
// ============================================================
#define ASTR 20
#define WSTR 136

template<int BIAS, int LEAKY>
__global__ void __launch_bounds__(256, 2)
gemm_tc(const float* __restrict__ A, const float* __restrict__ W,
        const float* __restrict__ bias, float* __restrict__ C,
        int M, int N, int K) {
    __shared__ float As[2][128 * ASTR];
    __shared__ float Ws[2][16 * WSTR];
    int tid = threadIdx.x;
    int wid = tid >> 5, lane = tid & 31;
    int wm = wid & 3, wn = wid >> 2;
    int lrow = lane >> 2, lcol = lane & 3;
    int rb = blockIdx.y * 128, cb = blockIdx.x * 128;

    // staging maps
    int ar = tid & 127;           // A row
    int ak = (tid >> 7) * 8;      // A col base (two f4: ak, ak+4)
    int wr = wid;                 // W rows wr, wr+8
    int wc = lane * 4;            // W col offset (one f4 per row)
    int wcol = cb + wc;
    bool wok = (wcol < N);        // N%4==0 so whole f4 in/out

    float cfr[2][8][4];
    #pragma unroll
    for (int mt = 0; mt < 2; mt++)
        #pragma unroll
        for (int nb = 0; nb < 8; nb++)
            #pragma unroll
            for (int j = 0; j < 4; j++) cfr[mt][nb][j] = 0.0f;

    // ---- prologue: stage k0=0 into buf 0 ----
    {
        float4 a0 = *(const float4*)&A[(size_t)(rb + ar) * K + ak];
        float4 a1 = *(const float4*)&A[(size_t)(rb + ar) * K + ak + 4];
        a0.x = tf32r(a0.x); a0.y = tf32r(a0.y); a0.z = tf32r(a0.z); a0.w = tf32r(a0.w);
        a1.x = tf32r(a1.x); a1.y = tf32r(a1.y); a1.z = tf32r(a1.z); a1.w = tf32r(a1.w);
        *(float4*)&As[0][ar * ASTR + ak] = a0;
        *(float4*)&As[0][ar * ASTR + ak + 4] = a1;
        float4 w0 = make_float4(0.f, 0.f, 0.f, 0.f), w1 = w0;
        if (wok) {
            w0 = *(const float4*)&W[(size_t)wr * N + wcol];
            w1 = *(const float4*)&W[(size_t)(wr + 8) * N + wcol];
        }
        w0.x = tf32r(w0.x); w0.y = tf32r(w0.y); w0.z = tf32r(w0.z); w0.w = tf32r(w0.w);
        w1.x = tf32r(w1.x); w1.y = tf32r(w1.y); w1.z = tf32r(w1.z); w1.w = tf32r(w1.w);
        *(float4*)&Ws[0][wr * WSTR + wc] = w0;
        *(float4*)&Ws[0][(wr + 8) * WSTR + wc] = w1;
    }
    __syncthreads();

    int buf = 0;
    for (int k0 = 0; k0 < K; k0 += 16) {
        bool more = (k0 + 16) < K;
        float4 a0, a1, w0, w1;
        if (more) {
            a0 = *(const float4*)&A[(size_t)(rb + ar) * K + k0 + 16 + ak];
            a1 = *(const float4*)&A[(size_t)(rb + ar) * K + k0 + 16 + ak + 4];
            if (wok) {
                w0 = *(const float4*)&W[(size_t)(k0 + 16 + wr) * N + wcol];
                w1 = *(const float4*)&W[(size_t)(k0 + 16 + wr + 8) * N + wcol];
            } else {
                w0 = make_float4(0.f, 0.f, 0.f, 0.f); w1 = w0;
            }
        }

        // ---- compute on current buffer ----
        #pragma unroll
        for (int kb = 0; kb < 2; kb++) {
            int kk = kb * 8 + lcol;
            uint32_t a[2][4];
            #pragma unroll
            for (int mt = 0; mt < 2; mt++) {
                int row = 32 * wm + 16 * mt + lrow;
                a[mt][0] = f2u(As[buf][row * ASTR + kk]);
                a[mt][1] = f2u(As[buf][(row + 8) * ASTR + kk]);
                a[mt][2] = f2u(As[buf][row * ASTR + kk + 4]);
                a[mt][3] = f2u(As[buf][(row + 8) * ASTR + kk + 4]);
            }
            #pragma unroll
            for (int nb = 0; nb < 8; nb++) {
                int ncol = 64 * wn + nb * 8 + lrow;
                uint32_t b2[2];
                b2[0] = f2u(Ws[buf][kk * WSTR + ncol]);
                b2[1] = f2u(Ws[buf][(kk + 4) * WSTR + ncol]);
                mma8(cfr[0][nb], a[0], b2);
                mma8(cfr[1][nb], a[1], b2);
            }
        }

        if (more) {
            a0.x = tf32r(a0.x); a0.y = tf32r(a0.y); a0.z = tf32r(a0.z); a0.w = tf32r(a0.w);
            a1.x = tf32r(a1.x); a1.y = tf32r(a1.y); a1.z = tf32r(a1.z); a1.w = tf32r(a1.w);
            *(float4*)&As[buf ^ 1][ar * ASTR + ak] = a0;
            *(float4*)&As[buf ^ 1][ar * ASTR + ak + 4] = a1;
            w0.x = tf32r(w0.x); w0.y = tf32r(w0.y); w0.z = tf32r(w0.z); w0.w = tf32r(w0.w);
            w1.x = tf32r(w1.x); w1.y = tf32r(w1.y); w1.z = tf32r(w1.z); w1.w = tf32r(w1.w);
            *(float4*)&Ws[buf ^ 1][wr * WSTR + wc] = w0;
            *(float4*)&Ws[buf ^ 1][(wr + 8) * WSTR + wc] = w1;
        }
        __syncthreads();
        buf ^= 1;
    }

    // ---- epilogue ----
    #pragma unroll
    for (int mt = 0; mt < 2; mt++) {
        int r0 = rb + 32 * wm + 16 * mt + lrow;
        #pragma unroll
        for (int nb = 0; nb < 8; nb++) {
            int col = cb + 64 * wn + nb * 8 + 2 * lcol;
            if (col < N) {
                float v00 = cfr[mt][nb][0], v01 = cfr[mt][nb][1];
                float v10 = cfr[mt][nb][2], v11 = cfr[mt][nb][3];
                if (BIAS) {
                    float b0 = bias[col], b1 = bias[col + 1];
                    v00 += b0; v01 += b1; v10 += b0; v11 += b1;
                }
                if (LEAKY) {
                    v00 = (v00 > 0.0f) ? v00 : 0.2f * v00;
                    v01 = (v01 > 0.0f) ? v01 : 0.2f * v01;
                    v10 = (v10 > 0.0f) ? v10 : 0.2f * v10;
                    v11 = (v11 > 0.0f) ? v11 : 0.2f * v11;
                }
                *(float2*)&C[(size_t)r0 * N + col] = make_float2(v00, v01);
                *(float2*)&C[(size_t)(r0 + 8) * N + col] = make_float2(v10, v11);
            }
        }
    }
}

// ============================================================
// out = LayerNorm(a + b), eps = 1e-3.  One warp per row (8 rows/block).
// ============================================================
__global__ void __launch_bounds__(256)
add_ln_kernel(const float* __restrict__ a, const float* __restrict__ bvec,
              const float* __restrict__ gamma, const float* __restrict__ beta,
              float* __restrict__ out) {
    int wid = threadIdx.x >> 5, lane = threadIdx.x & 31;
    int row = blockIdx.x * 8 + wid;
    const float4* ar = (const float4*)(a + (size_t)row * DD);
    const float4* br = (const float4*)(bvec + (size_t)row * DD);
    float4 v0 = ar[lane];        float4 w0 = br[lane];
    float4 v1 = ar[lane + 32];   float4 w1 = br[lane + 32];
    v0.x += w0.x; v0.y += w0.y; v0.z += w0.z; v0.w += w0.w;
    v1.x += w1.x; v1.y += w1.y; v1.z += w1.z; v1.w += w1.w;

    float sum = v0.x + v0.y + v0.z + v0.w + v1.x + v1.y + v1.z + v1.w;
    #pragma unroll
    for (int off = 16; off > 0; off >>= 1) sum += __shfl_xor_sync(0xffffffff, sum, off);
    float mu = sum * (1.0f / DD);

    float sq = (v0.x - mu) * (v0.x - mu) + (v0.y - mu) * (v0.y - mu)
             + (v0.z - mu) * (v0.z - mu) + (v0.w - mu) * (v0.w - mu)
             + (v1.x - mu) * (v1.x - mu) + (v1.y - mu) * (v1.y - mu)
             + (v1.z - mu) * (v1.z - mu) + (v1.w - mu) * (v1.w - mu);
    #pragma unroll
    for (int off = 16; off > 0; off >>= 1) sq += __shfl_xor_sync(0xffffffff, sq, off);
    float rs = rsqrtf(sq * (1.0f / DD) + 1e-3f);

    const float4* g4 = (const float4*)gamma;
    const float4* b4 = (const float4*)beta;
    float4 g0 = g4[lane], g1 = g4[lane + 32];
    float4 e0 = b4[lane], e1 = b4[lane + 32];
    float4 o0, o1;
    o0.x = (v0.x - mu) * rs * g0.x + e0.x;
    o0.y = (v0.y - mu) * rs * g0.y + e0.y;
    o0.z = (v0.z - mu) * rs * g0.z + e0.z;
    o0.w = (v0.w - mu) * rs * g0.w + e0.w;
    o1.x = (v1.x - mu) * rs * g1.x + e1.x;
    o1.y = (v1.y - mu) * rs * g1.y + e1.y;
    o1.z = (v1.z - mu) * rs * g1.z + e1.z;
    o1.w = (v1.w - mu) * rs * g1.w + e1.w;
    float4* orow = (float4*)(out + (size_t)row * DD);
    orow[lane] = o0;
    orow[lane + 32] = o1;
}

// ============================================================
extern "C" void kernel_launch(void* const* d_in, const int* in_sizes, int n_in,
                              void* d_out, int out_size) {
    const float* inputs = (const float*)d_in[0];
    const float* ctx    = (const float*)d_in[1];
    const float* sa_Wk  = (const float*)d_in[2];
    const float* sa_Wv  = (const float*)d_in[3];
    const float* sa_Wq  = (const float*)d_in[4];
    const float* ca_Wk  = (const float*)d_in[5];
    const float* ca_Wv  = (const float*)d_in[6];
    const float* ca_Wq  = (const float*)d_in[7];
    const float* W1     = (const float*)d_in[8];
    const float* b1     = (const float*)d_in[9];
    const float* W2     = (const float*)d_in[10];
    const float* b2     = (const float*)d_in[11];
    const float* gamma  = (const float*)d_in[12];
    const float* beta   = (const float*)d_in[13];
    float* out = (float*)d_out;

    float *Qp, *Kp, *Vp, *Tp, *Xp, *Yp, *Hp;
    cudaGetSymbolAddress((void**)&Qp, g_Q);
    cudaGetSymbolAddress((void**)&Kp, g_K);
    cudaGetSymbolAddress((void**)&Vp, g_V);
    cudaGetSymbolAddress((void**)&Tp, g_T);
    cudaGetSymbolAddress((void**)&Xp, g_X);
    cudaGetSymbolAddress((void**)&Yp, g_Y);
    cudaGetSymbolAddress((void**)&Hp, g_H);

    const int flash_smem = FL_FLOATS * 4;
    cudaFuncSetAttribute(flash_mma, cudaFuncAttributeMaxDynamicSharedMemorySize, flash_smem);

    dim3 gD(DD / 128, BSROWS / 128);            // projections / FFN2: N=256
    dim3 gH((HH + 127) / 128, BSROWS / 128);    // FFN1: N=400
    dim3 fg(SS / FBQ, BB);
    int lnB = BSROWS / 8;

    // 1) self-attention (causal)
    gemm_tc<0, 0><<<gD, 256>>>(inputs, sa_Wk, nullptr, Kp, BSROWS, DD, DD);
    gemm_tc<0, 0><<<gD, 256>>>(inputs, sa_Wv, nullptr, Vp, BSROWS, DD, DD);
    gemm_tc<0, 0><<<gD, 256>>>(inputs, sa_Wq, nullptr, Qp, BSROWS, DD, DD);
    flash_mma<<<fg, 128, flash_smem>>>(Qp, Kp, Vp, Tp, 1);
    add_ln_kernel<<<lnB, 256>>>(Tp, inputs, gamma, beta, Xp);

    // 2) cross-attention
    gemm_tc<0, 0><<<gD, 256>>>(ctx, ca_Wk, nullptr, Kp, BSROWS, DD, DD);
    gemm_tc<0, 0><<<gD, 256>>>(ctx, ca_Wv, nullptr, Vp, BSROWS, DD, DD);
    gemm_tc<0, 0><<<gD, 256>>>(Xp, ca_Wq, nullptr, Qp, BSROWS, DD, DD);
    flash_mma<<<fg, 128, flash_smem>>>(Qp, Kp, Vp, Tp, 0);
    add_ln_kernel<<<lnB, 256>>>(Tp, Xp, gamma, beta, Yp);

    // 3) FFN
    gemm_tc<1, 1><<<gH, 256>>>(Yp, W1, b1, Hp, BSROWS, HH, DD);
    gemm_tc<1, 0><<<gD, 256>>>(Hp, W2, b2, Tp, BSROWS, DD, HH);
    add_ln_kernel<<<lnB, 256>>>(Tp, Yp, gamma, beta, out);
}

// round 10
// speedup vs baseline: 1.1563x; 1.1476x over previous
#include <cuda_runtime.h>
#include <cstdint>
#include <math.h>

#define BB 4
#define SS 4096
#define DD 256
#define HH 400
#define BSROWS (BB*SS)

// ---- scratch ----
__device__ float g_Q[BSROWS*DD];
__device__ float g_K[BSROWS*DD];
__device__ float g_V[BSROWS*DD];
__device__ float g_T[BSROWS*DD];
__device__ float g_X[BSROWS*DD];
__device__ float g_Y[BSROWS*DD];
__device__ float g_H[BSROWS*HH];

// ============================================================
// helpers
// ============================================================
__device__ __forceinline__ float tf32r(float x) {
    float r; asm("cvt.rna.tf32.f32 %0, %1;" : "=f"(r) : "f"(x)); return r;
}
__device__ __forceinline__ uint32_t smem_u32(const void* p) {
    uint32_t a;
    asm("{ .reg .u64 t; cvta.to.shared.u64 t, %1; cvt.u32.u64 %0, t; }" : "=r"(a) : "l"(p));
    return a;
}
__device__ __forceinline__ void mma8(float c[4], const uint32_t a[4], const uint32_t b[2]) {
    asm volatile(
        "mma.sync.aligned.m16n8k8.row.col.f32.tf32.tf32.f32 "
        "{%0,%1,%2,%3}, {%4,%5,%6,%7}, {%8,%9}, {%0,%1,%2,%3};"
        : "+f"(c[0]), "+f"(c[1]), "+f"(c[2]), "+f"(c[3])
        : "r"(a[0]), "r"(a[1]), "r"(a[2]), "r"(a[3]), "r"(b[0]), "r"(b[1]));
}
__device__ __forceinline__ uint32_t f2u(float x) { return __float_as_uint(x); }

__device__ __forceinline__ void cp16z(uint32_t dst, const void* src, bool ok) {
    int sz = ok ? 16 : 0;
    asm volatile("cp.async.cg.shared.global [%0], [%1], 16, %2;" :: "r"(dst), "l"(src), "r"(sz));
}
#define CP_COMMIT() asm volatile("cp.async.commit_group;" ::: "memory")
#define CP_WAIT1()  asm volatile("cp.async.wait_group 1;" ::: "memory")

// ============================================================
// Flash attention, tf32 HMMA (round-3 proven: 585us cross-attn).
// CTA: 64 queries, 256 threads (8 warps = 4 row-groups x 2 halves).
// K/V chunks of 64 keys.
// ============================================================
#define FBQ 64
#define FBK 64
#define QSTR 260
#define KSTR 260
#define VSTR 264
#define SSTR 68
#define OQ 0
#define OKo 16640
#define OV 33280
#define OS 50176
#define OM 54528
#define OL 54592
#define OA 54656
#define FL_FLOATS 54720           // *4 = 218880 bytes

__global__ void __launch_bounds__(256, 1)
flash_mma(const float* __restrict__ Qg, const float* __restrict__ Kg,
          const float* __restrict__ Vg, float* __restrict__ Og, int causal) {
    extern __shared__ float fs[];
    int tid = threadIdx.x;
    int wid = tid >> 5, lane = tid & 31;
    int rg = wid & 3;          // row-group: rows 16*rg .. +15
    int h  = wid >> 2;         // half: cols 32h (scores) / 128h (PV)
    int lrow = lane >> 2;
    int lcol = lane & 3;
    int b = blockIdx.y, q0 = blockIdx.x * FBQ;

    // ---- stage Q (prescaled by 1/sqrt(4096)=1/64, tf32) ----
    {
        const float4* Qr = (const float4*)(Qg + ((size_t)b * SS + q0) * DD);
        #pragma unroll
        for (int p = 0; p < 16; p++) {
            int idx = tid + p * 256;
            int r = idx >> 6, c4 = idx & 63;
            float4 v = Qr[r * 64 + c4];
            v.x = tf32r(v.x * 0.015625f); v.y = tf32r(v.y * 0.015625f);
            v.z = tf32r(v.z * 0.015625f); v.w = tf32r(v.w * 0.015625f);
            *(float4*)&fs[OQ + r * QSTR + c4 * 4] = v;
        }
    }
    if (tid < FBQ) { fs[OM + tid] = -INFINITY; fs[OL + tid] = 0.0f; }

    float ofrag[16][4];
    #pragma unroll
    for (int nb = 0; nb < 16; nb++)
        #pragma unroll
        for (int j = 0; j < 4; j++) ofrag[nb][j] = 0.0f;

    int nc = causal ? (blockIdx.x + 1) : (SS / FBK);

    for (int c = 0; c < nc; c++) {
        int k0 = c * FBK;
        bool maskc = causal && (k0 == q0);

        // ---- stage K (tf32) and V (tf32) ----
        const float4* Kr = (const float4*)(Kg + ((size_t)b * SS + k0) * DD);
        const float4* Vr = (const float4*)(Vg + ((size_t)b * SS + k0) * DD);
        #pragma unroll
        for (int p = 0; p < 16; p++) {
            int idx = tid + p * 256;
            int r = idx >> 6, c4 = idx & 63;
            float4 v = Kr[r * 64 + c4];
            v.x = tf32r(v.x); v.y = tf32r(v.y); v.z = tf32r(v.z); v.w = tf32r(v.w);
            *(float4*)&fs[OKo + r * KSTR + c4 * 4] = v;
            float4 w = Vr[r * 64 + c4];
            w.x = tf32r(w.x); w.y = tf32r(w.y); w.z = tf32r(w.z); w.w = tf32r(w.w);
            *(float4*)&fs[OV + r * VSTR + c4 * 4] = w;
        }
        __syncthreads();   // (A)

        // ---- scores: warp (rg,h) computes S[16rg..+15][32h..+31] ----
        {
            float sfrag[4][4];
            #pragma unroll
            for (int nb = 0; nb < 4; nb++)
                #pragma unroll
                for (int j = 0; j < 4; j++) sfrag[nb][j] = 0.0f;

            int qrow = 16 * rg + lrow;
            #pragma unroll 4
            for (int kb = 0; kb < 32; kb++) {
                int kk = kb * 8 + lcol;
                uint32_t a[4];
                a[0] = f2u(fs[OQ + qrow * QSTR + kk]);
                a[1] = f2u(fs[OQ + (qrow + 8) * QSTR + kk]);
                a[2] = f2u(fs[OQ + qrow * QSTR + kk + 4]);
                a[3] = f2u(fs[OQ + (qrow + 8) * QSTR + kk + 4]);
                #pragma unroll
                for (int nb = 0; nb < 4; nb++) {
                    int nrow = 32 * h + nb * 8 + lrow;
                    uint32_t bf[2];
                    bf[0] = f2u(fs[OKo + nrow * KSTR + kk]);
                    bf[1] = f2u(fs[OKo + nrow * KSTR + kk + 4]);
                    mma8(sfrag[nb], a, bf);
                }
            }
            int grow0 = q0 + 16 * rg + lrow;
            #pragma unroll
            for (int nb = 0; nb < 4; nb++) {
                int cb0 = 32 * h + nb * 8 + 2 * lcol;
                float2 v0 = make_float2(sfrag[nb][0], sfrag[nb][1]);
                float2 v1 = make_float2(sfrag[nb][2], sfrag[nb][3]);
                if (maskc) {
                    int g = k0 + cb0;
                    if (g > grow0)         v0.x = -1e30f;
                    if (g + 1 > grow0)     v0.y = -1e30f;
                    if (g > grow0 + 8)     v1.x = -1e30f;
                    if (g + 1 > grow0 + 8) v1.y = -1e30f;
                }
                *(float2*)&fs[OS + (16 * rg + lrow) * SSTR + cb0] = v0;
                *(float2*)&fs[OS + (16 * rg + lrow + 8) * SSTR + cb0] = v1;
            }
        }
        __syncthreads();   // (B)

        // ---- online softmax: 4 threads per row, 16 cols each ----
        {
            int row = tid >> 2, seg = tid & 3;
            float* Sr = &fs[OS + row * SSTR + seg * 16];
            float4 x0 = ((float4*)Sr)[0];
            float4 x1 = ((float4*)Sr)[1];
            float4 x2 = ((float4*)Sr)[2];
            float4 x3 = ((float4*)Sr)[3];
            float mx = fmaxf(fmaxf(fmaxf(x0.x, x0.y), fmaxf(x0.z, x0.w)),
                       fmaxf(fmaxf(fmaxf(x1.x, x1.y), fmaxf(x1.z, x1.w)),
                       fmaxf(fmaxf(fmaxf(x2.x, x2.y), fmaxf(x2.z, x2.w)),
                             fmaxf(fmaxf(x3.x, x3.y), fmaxf(x3.z, x3.w)))));
            mx = fmaxf(mx, __shfl_xor_sync(0xffffffff, mx, 1));
            mx = fmaxf(mx, __shfl_xor_sync(0xffffffff, mx, 2));
            float mold = fs[OM + row];
            float mnew = fmaxf(mold, mx);
            float alpha = __expf(mold - mnew);
            float sum = 0.0f;
            #pragma unroll
            for (int q = 0; q < 4; q++) {
                float4* xp = (q == 0) ? &x0 : (q == 1) ? &x1 : (q == 2) ? &x2 : &x3;
                xp->x = __expf(xp->x - mnew); sum += xp->x; xp->x = tf32r(xp->x);
                xp->y = __expf(xp->y - mnew); sum += xp->y; xp->y = tf32r(xp->y);
                xp->z = __expf(xp->z - mnew); sum += xp->z; xp->z = tf32r(xp->z);
                xp->w = __expf(xp->w - mnew); sum += xp->w; xp->w = tf32r(xp->w);
            }
            ((float4*)Sr)[0] = x0; ((float4*)Sr)[1] = x1;
            ((float4*)Sr)[2] = x2; ((float4*)Sr)[3] = x3;
            sum += __shfl_xor_sync(0xffffffff, sum, 1);
            sum += __shfl_xor_sync(0xffffffff, sum, 2);
            if (seg == 0) {
                fs[OL + row] = fs[OL + row] * alpha + sum;
                fs[OM + row] = mnew;
                fs[OA + row] = alpha;
            }
        }
        __syncthreads();   // (C)

        // ---- PV: warp (rg,h): O[16rg..+15][128h..+127] += P * V ----
        {
            float al0 = fs[OA + 16 * rg + lrow];
            float al8 = fs[OA + 16 * rg + lrow + 8];
            #pragma unroll
            for (int nb = 0; nb < 16; nb++) {
                ofrag[nb][0] *= al0; ofrag[nb][1] *= al0;
                ofrag[nb][2] *= al8; ofrag[nb][3] *= al8;
            }
            int prow = 16 * rg + lrow;
            #pragma unroll
            for (int kb = 0; kb < 8; kb++) {
                int kk = kb * 8 + lcol;
                uint32_t a[4];
                a[0] = f2u(fs[OS + prow * SSTR + kk]);
                a[1] = f2u(fs[OS + (prow + 8) * SSTR + kk]);
                a[2] = f2u(fs[OS + prow * SSTR + kk + 4]);
                a[3] = f2u(fs[OS + (prow + 8) * SSTR + kk + 4]);
                #pragma unroll
                for (int nb = 0; nb < 16; nb++) {
                    int ncol = 128 * h + nb * 8 + lrow;
                    uint32_t bf[2];
                    bf[0] = f2u(fs[OV + kk * VSTR + ncol]);
                    bf[1] = f2u(fs[OV + (kk + 4) * VSTR + ncol]);
                    mma8(ofrag[nb], a, bf);
                }
            }
        }
        __syncthreads();   // (D)
    }

    // ---- epilogue ----
    {
        int row = 16 * rg + lrow;
        float inv0 = 1.0f / fs[OL + row];
        float inv8 = 1.0f / fs[OL + row + 8];
        float* Or0 = Og + ((size_t)b * SS + q0 + row) * DD;
        float* Or8 = Or0 + 8 * DD;
        #pragma unroll
        for (int nb = 0; nb < 16; nb++) {
            int col = 128 * h + nb * 8 + 2 * lcol;
            *(float2*)&Or0[col] = make_float2(ofrag[nb][0] * inv0, ofrag[nb][1] * inv0);
            *(float2*)&Or8[col] = make_float2(ofrag[nb][2] * inv8, ofrag[nb][3] * inv8);
        }
    }
}

// ============================================================
// tf32 HMMA GEMM v3: BM=128, BN=128, BK=32, cp.async double-buffered,
// COALESCED staging (warp = 4 rows x 128B for A; 1 row x 512B for W).
// 256 threads (8 warps = 4m x 2n), warp tile 32x64. Dynamic smem 70KB.
// ============================================================
// dyn smem floats: As[2] at 0 / 4608 (128*36 each); Ws[2] at 9216 / 13568 (32*136 each)
#define GEMM_SMEM_FLOATS 17920

template<int BIAS, int LEAKY>
__global__ void __launch_bounds__(256, 2)
gemm_tc(const float* __restrict__ A, const float* __restrict__ W,
        const float* __restrict__ bias, float* __restrict__ C,
        int M, int N, int K) {
    extern __shared__ float gs[];
    uint32_t sb = smem_u32(gs);
    int tid = threadIdx.x;
    int wid = tid >> 5, lane = tid & 31;
    int wm = wid & 3, wn = wid >> 2;
    int lrow = lane >> 2, lcol = lane & 3;
    int rb = blockIdx.y * 128, cb = blockIdx.x * 128;

    float cfr[2][8][4];
    #pragma unroll
    for (int mt = 0; mt < 2; mt++)
        #pragma unroll
        for (int nb = 0; nb < 8; nb++)
            #pragma unroll
            for (int j = 0; j < 4; j++) cfr[mt][nb][j] = 0.0f;

    int NI = (K + 31) / 32;

    // coalesced cp.async staging of one (A 128x32, W 32x128) k-tile
    #define STAGE(buf, k0s) do {                                                  \
        int _k0 = (k0s);                                                          \
        _Pragma("unroll")                                                         \
        for (int p = 0; p < 4; p++) {                                             \
            int idx = tid + p * 256;                                              \
            int r = idx >> 3, c4 = idx & 7;                                       \
            int col = _k0 + c4 * 4;                                               \
            bool ok = col < K;                                                    \
            const float* src = A + (size_t)(rb + r) * K + (ok ? col : 0);         \
            cp16z(sb + (uint32_t)((buf) * 4608 + r * 36 + c4 * 4) * 4, src, ok);  \
        }                                                                         \
        _Pragma("unroll")                                                         \
        for (int p = 0; p < 4; p++) {                                             \
            int idx = tid + p * 256;                                              \
            int r = idx >> 5, c4 = idx & 31;                                      \
            int row = _k0 + r, col = cb + c4 * 4;                                 \
            bool ok = (row < K) && (col < N);                                     \
            const float* src = W + (ok ? ((size_t)row * N + col) : 0);            \
            cp16z(sb + (uint32_t)(9216 + (buf) * 4352 + r * 136 + c4 * 4) * 4, src, ok); \
        }                                                                         \
    } while (0)

    STAGE(0, 0);
    CP_COMMIT();
    if (NI > 1) STAGE(1, 32);
    CP_COMMIT();

    for (int it = 0; it < NI; it++) {
        CP_WAIT1();
        __syncthreads();
        int Ab = (it & 1) * 4608;
        int Wb = 9216 + (it & 1) * 4352;
        #pragma unroll
        for (int kb = 0; kb < 4; kb++) {
            int kk = kb * 8 + lcol;
            uint32_t a[2][4];
            #pragma unroll
            for (int mt = 0; mt < 2; mt++) {
                int row = 32 * wm + 16 * mt + lrow;
                a[mt][0] = f2u(tf32r(gs[Ab + row * 36 + kk]));
                a[mt][1] = f2u(tf32r(gs[Ab + (row + 8) * 36 + kk]));
                a[mt][2] = f2u(tf32r(gs[Ab + row * 36 + kk + 4]));
                a[mt][3] = f2u(tf32r(gs[Ab + (row + 8) * 36 + kk + 4]));
            }
            #pragma unroll
            for (int nb = 0; nb < 8; nb++) {
                int ncol = 64 * wn + 8 * nb + lrow;
                uint32_t b2[2];
                b2[0] = f2u(tf32r(gs[Wb + kk * 136 + ncol]));
                b2[1] = f2u(tf32r(gs[Wb + (kk + 4) * 136 + ncol]));
                mma8(cfr[0][nb], a[0], b2);
                mma8(cfr[1][nb], a[1], b2);
            }
        }
        __syncthreads();
        if (it + 2 < NI) STAGE(it & 1, (it + 2) * 32);
        CP_COMMIT();
    }
    #undef STAGE

    // ---- epilogue ----
    #pragma unroll
    for (int mt = 0; mt < 2; mt++) {
        int r0 = rb + 32 * wm + 16 * mt + lrow;
        #pragma unroll
        for (int nb = 0; nb < 8; nb++) {
            int col = cb + 64 * wn + 8 * nb + 2 * lcol;
            if (col < N) {
                float v00 = cfr[mt][nb][0], v01 = cfr[mt][nb][1];
                float v10 = cfr[mt][nb][2], v11 = cfr[mt][nb][3];
                if (BIAS) {
                    float b0 = bias[col], b1 = bias[col + 1];
                    v00 += b0; v01 += b1; v10 += b0; v11 += b1;
                }
                if (LEAKY) {
                    v00 = (v00 > 0.0f) ? v00 : 0.2f * v00;
                    v01 = (v01 > 0.0f) ? v01 : 0.2f * v01;
                    v10 = (v10 > 0.0f) ? v10 : 0.2f * v10;
                    v11 = (v11 > 0.0f) ? v11 : 0.2f * v11;
                }
                *(float2*)&C[(size_t)r0 * N + col] = make_float2(v00, v01);
                *(float2*)&C[(size_t)(r0 + 8) * N + col] = make_float2(v10, v11);
            }
        }
    }
}

// ============================================================
// out = LayerNorm(a + b), eps = 1e-3.  One warp per row (8 rows/block).
// ============================================================
__global__ void __launch_bounds__(256)
add_ln_kernel(const float* __restrict__ a, const float* __restrict__ bvec,
              const float* __restrict__ gamma, const float* __restrict__ beta,
              float* __restrict__ out) {
    int wid = threadIdx.x >> 5, lane = threadIdx.x & 31;
    int row = blockIdx.x * 8 + wid;
    const float4* ar = (const float4*)(a + (size_t)row * DD);
    const float4* br = (const float4*)(bvec + (size_t)row * DD);
    float4 v0 = ar[lane];        float4 w0 = br[lane];
    float4 v1 = ar[lane + 32];   float4 w1 = br[lane + 32];
    v0.x += w0.x; v0.y += w0.y; v0.z += w0.z; v0.w += w0.w;
    v1.x += w1.x; v1.y += w1.y; v1.z += w1.z; v1.w += w1.w;

    float sum = v0.x + v0.y + v0.z + v0.w + v1.x + v1.y + v1.z + v1.w;
    #pragma unroll
    for (int off = 16; off > 0; off >>= 1) sum += __shfl_xor_sync(0xffffffff, sum, off);
    float mu = sum * (1.0f / DD);

    float sq = (v0.x - mu) * (v0.x - mu) + (v0.y - mu) * (v0.y - mu)
             + (v0.z - mu) * (v0.z - mu) + (v0.w - mu) * (v0.w - mu)
             + (v1.x - mu) * (v1.x - mu) + (v1.y - mu) * (v1.y - mu)
             + (v1.z - mu) * (v1.z - mu) + (v1.w - mu) * (v1.w - mu);
    #pragma unroll
    for (int off = 16; off > 0; off >>= 1) sq += __shfl_xor_sync(0xffffffff, sq, off);
    float rs = rsqrtf(sq * (1.0f / DD) + 1e-3f);

    const float4* g4 = (const float4*)gamma;
    const float4* b4 = (const float4*)beta;
    float4 g0 = g4[lane], g1 = g4[lane + 32];
    float4 e0 = b4[lane], e1 = b4[lane + 32];
    float4 o0, o1;
    o0.x = (v0.x - mu) * rs * g0.x + e0.x;
    o0.y = (v0.y - mu) * rs * g0.y + e0.y;
    o0.z = (v0.z - mu) * rs * g0.z + e0.z;
    o0.w = (v0.w - mu) * rs * g0.w + e0.w;
    o1.x = (v1.x - mu) * rs * g1.x + e1.x;
    o1.y = (v1.y - mu) * rs * g1.y + e1.y;
    o1.z = (v1.z - mu) * rs * g1.z + e1.z;
    o1.w = (v1.w - mu) * rs * g1.w + e1.w;
    float4* orow = (float4*)(out + (size_t)row * DD);
    orow[lane] = o0;
    orow[lane + 32] = o1;
}

// ============================================================
extern "C" void kernel_launch(void* const* d_in, const int* in_sizes, int n_in,
                              void* d_out, int out_size) {
    const float* inputs = (const float*)d_in[0];
    const float* ctx    = (const float*)d_in[1];
    const float* sa_Wk  = (const float*)d_in[2];
    const float* sa_Wv  = (const float*)d_in[3];
    const float* sa_Wq  = (const float*)d_in[4];
    const float* ca_Wk  = (const float*)d_in[5];
    const float* ca_Wv  = (const float*)d_in[6];
    const float* ca_Wq  = (const float*)d_in[7];
    const float* W1     = (const float*)d_in[8];
    const float* b1     = (const float*)d_in[9];
    const float* W2     = (const float*)d_in[10];
    const float* b2     = (const float*)d_in[11];
    const float* gamma  = (const float*)d_in[12];
    const float* beta   = (const float*)d_in[13];
    float* out = (float*)d_out;

    float *Qp, *Kp, *Vp, *Tp, *Xp, *Yp, *Hp;
    cudaGetSymbolAddress((void**)&Qp, g_Q);
    cudaGetSymbolAddress((void**)&Kp, g_K);
    cudaGetSymbolAddress((void**)&Vp, g_V);
    cudaGetSymbolAddress((void**)&Tp, g_T);
    cudaGetSymbolAddress((void**)&Xp, g_X);
    cudaGetSymbolAddress((void**)&Yp, g_Y);
    cudaGetSymbolAddress((void**)&Hp, g_H);

    const int flash_smem = FL_FLOATS * 4;
    const int gemm_smem = GEMM_SMEM_FLOATS * 4;
    cudaFuncSetAttribute(flash_mma, cudaFuncAttributeMaxDynamicSharedMemorySize, flash_smem);
    cudaFuncSetAttribute(gemm_tc<0, 0>, cudaFuncAttributeMaxDynamicSharedMemorySize, gemm_smem);
    cudaFuncSetAttribute(gemm_tc<1, 1>, cudaFuncAttributeMaxDynamicSharedMemorySize, gemm_smem);
    cudaFuncSetAttribute(gemm_tc<1, 0>, cudaFuncAttributeMaxDynamicSharedMemorySize, gemm_smem);

    dim3 gD(DD / 128, BSROWS / 128);            // N=256: (2,128)
    dim3 gH((HH + 127) / 128, BSROWS / 128);    // N=400: (4,128)
    dim3 fg(SS / FBQ, BB);
    int lnB = BSROWS / 8;

    // 1) self-attention (causal)
    gemm_tc<0, 0><<<gD, 256, gemm_smem>>>(inputs, sa_Wk, nullptr, Kp, BSROWS, DD, DD);
    gemm_tc<0, 0><<<gD, 256, gemm_smem>>>(inputs, sa_Wv, nullptr, Vp, BSROWS, DD, DD);
    gemm_tc<0, 0><<<gD, 256, gemm_smem>>>(inputs, sa_Wq, nullptr, Qp, BSROWS, DD, DD);
    flash_mma<<<fg, 256, flash_smem>>>(Qp, Kp, Vp, Tp, 1);
    add_ln_kernel<<<lnB, 256>>>(Tp, inputs, gamma, beta, Xp);

    // 2) cross-attention
    gemm_tc<0, 0><<<gD, 256, gemm_smem>>>(ctx, ca_Wk, nullptr, Kp, BSROWS, DD, DD);
    gemm_tc<0, 0><<<gD, 256, gemm_smem>>>(ctx, ca_Wv, nullptr, Vp, BSROWS, DD, DD);
    gemm_tc<0, 0><<<gD, 256, gemm_smem>>>(Xp, ca_Wq, nullptr, Qp, BSROWS, DD, DD);
    flash_mma<<<fg, 256, flash_smem>>>(Qp, Kp, Vp, Tp, 0);
    add_ln_kernel<<<lnB, 256>>>(Tp, Xp, gamma, beta, Yp);

    // 3) FFN
    gemm_tc<1, 1><<<gH, 256, gemm_smem>>>(Yp, W1, b1, Hp, BSROWS, HH, DD);
    gemm_tc<1, 0><<<gD, 256, gemm_smem>>>(Hp, W2, b2, Tp, BSROWS, DD, HH);
    add_ln_kernel<<<lnB, 256>>>(Tp, Yp, gamma, beta, out);
}

// round 11
// speedup vs baseline: 1.3877x; 1.2001x over previous
#include <cuda_runtime.h>
#include <cstdint>
#include <math.h>

#define BB 4
#define SS 4096
#define DD 256
#define HH 400
#define BSROWS (BB*SS)

// ---- scratch ----
__device__ float g_Q[BSROWS*DD];
__device__ float g_K[BSROWS*DD];
__device__ float g_V[BSROWS*DD];
__device__ float g_T[BSROWS*DD];
__device__ float g_X[BSROWS*DD];
__device__ float g_Y[BSROWS*DD];
__device__ float g_H[BSROWS*HH];

// ============================================================
// helpers
// ============================================================
__device__ __forceinline__ float tf32r(float x) {
    float r; asm("cvt.rna.tf32.f32 %0, %1;" : "=f"(r) : "f"(x)); return r;
}
__device__ __forceinline__ uint32_t smem_u32(const void* p) {
    uint32_t a;
    asm("{ .reg .u64 t; cvta.to.shared.u64 t, %1; cvt.u32.u64 %0, t; }" : "=r"(a) : "l"(p));
    return a;
}
__device__ __forceinline__ void mma8(float c[4], const uint32_t a[4], const uint32_t b[2]) {
    asm volatile(
        "mma.sync.aligned.m16n8k8.row.col.f32.tf32.tf32.f32 "
        "{%0,%1,%2,%3}, {%4,%5,%6,%7}, {%8,%9}, {%0,%1,%2,%3};"
        : "+f"(c[0]), "+f"(c[1]), "+f"(c[2]), "+f"(c[3])
        : "r"(a[0]), "r"(a[1]), "r"(a[2]), "r"(a[3]), "r"(b[0]), "r"(b[1]));
}
__device__ __forceinline__ uint32_t f2u(float x) { return __float_as_uint(x); }

__device__ __forceinline__ void cp16(uint32_t dst, const void* src) {
    asm volatile("cp.async.cg.shared.global [%0], [%1], 16;" :: "r"(dst), "l"(src));
}
__device__ __forceinline__ void cp16z(uint32_t dst, const void* src, bool ok) {
    int sz = ok ? 16 : 0;
    asm volatile("cp.async.cg.shared.global [%0], [%1], 16, %2;" :: "r"(dst), "l"(src), "r"(sz));
}
#define CP_COMMIT() asm volatile("cp.async.commit_group;" ::: "memory")
#define CP_WAIT0()  asm volatile("cp.async.wait_group 0;" ::: "memory")
#define CP_WAIT1()  asm volatile("cp.async.wait_group 1;" ::: "memory")
#define CP_WAIT2()  asm volatile("cp.async.wait_group 2;" ::: "memory")

// ============================================================
// Flash attention, tf32 HMMA. R3 skeleton + cp.async pipelined
// K/V staging (inputs pre-tf32-rounded by projection GEMMs) +
// reversed (LPT) causal CTA order.
// CTA: 64 queries, 256 threads (8 warps = 4 row-groups x 2 halves).
// ============================================================
#define FBQ 64
#define FBK 64
#define QSTR 260
#define KSTR 260
#define VSTR 264
#define SSTR 68
#define OQ 0
#define OKo 16640
#define OV 33280
#define OS 50176
#define OM 54528
#define OL 54592
#define OA 54656
#define FL_FLOATS 54720           // *4 = 218880 bytes

__global__ void __launch_bounds__(256, 1)
flash_mma(const float* __restrict__ Qg, const float* __restrict__ Kg,
          const float* __restrict__ Vg, float* __restrict__ Og, int causal) {
    extern __shared__ float fs[];
    uint32_t sb = smem_u32(fs);
    int tid = threadIdx.x;
    int wid = tid >> 5, lane = tid & 31;
    int rg = wid & 3;          // row-group: rows 16*rg .. +15
    int h  = wid >> 2;         // half: cols 32h (scores) / 128h (PV)
    int lrow = lane >> 2;
    int lcol = lane & 3;
    int b = blockIdx.y;
    int qb = causal ? ((int)gridDim.x - 1 - (int)blockIdx.x) : (int)blockIdx.x;
    int q0 = qb * FBQ;
    int nc = causal ? (qb + 1) : (SS / FBK);

    const float* QB = Qg + ((size_t)b * SS + q0) * DD;
    const float* KB = Kg + (size_t)b * SS * DD;
    const float* VB = Vg + (size_t)b * SS * DD;

    // ---- prologue: cp.async Q + K0 (group 1), V0 (group 2) ----
    {
        #pragma unroll
        for (int p = 0; p < 16; p++) {
            int idx = tid + p * 256;
            int r = idx >> 6, c4 = idx & 63;
            cp16(sb + (uint32_t)(OQ + r * QSTR + c4 * 4) * 4, QB + (size_t)r * DD + c4 * 4);
        }
        #pragma unroll
        for (int p = 0; p < 16; p++) {
            int idx = tid + p * 256;
            int r = idx >> 6, c4 = idx & 63;
            cp16(sb + (uint32_t)(OKo + r * KSTR + c4 * 4) * 4, KB + (size_t)r * DD + c4 * 4);
        }
        CP_COMMIT();
        #pragma unroll
        for (int p = 0; p < 16; p++) {
            int idx = tid + p * 256;
            int r = idx >> 6, c4 = idx & 63;
            cp16(sb + (uint32_t)(OV + r * VSTR + c4 * 4) * 4, VB + (size_t)r * DD + c4 * 4);
        }
        CP_COMMIT();
    }
    if (tid < FBQ) { fs[OM + tid] = -INFINITY; fs[OL + tid] = 0.0f; }

    float ofrag[16][4];
    #pragma unroll
    for (int nb = 0; nb < 16; nb++)
        #pragma unroll
        for (int j = 0; j < 4; j++) ofrag[nb][j] = 0.0f;

    for (int c = 0; c < nc; c++) {
        int k0 = c * FBK;
        bool maskc = causal && (k0 == q0);
        bool more = (c + 1) < nc;

        CP_WAIT1();        // K(c) (and Q on c==0) landed; V(c) may pend
        __syncthreads();   // (A)

        // ---- scores: warp (rg,h) computes S[16rg..+15][32h..+31] ----
        {
            float sfrag[4][4];
            #pragma unroll
            for (int nb = 0; nb < 4; nb++)
                #pragma unroll
                for (int j = 0; j < 4; j++) sfrag[nb][j] = 0.0f;

            int qrow = 16 * rg + lrow;
            #pragma unroll 4
            for (int kb = 0; kb < 32; kb++) {
                int kk = kb * 8 + lcol;
                uint32_t a[4];
                a[0] = f2u(fs[OQ + qrow * QSTR + kk]);
                a[1] = f2u(fs[OQ + (qrow + 8) * QSTR + kk]);
                a[2] = f2u(fs[OQ + qrow * QSTR + kk + 4]);
                a[3] = f2u(fs[OQ + (qrow + 8) * QSTR + kk + 4]);
                #pragma unroll
                for (int nb = 0; nb < 4; nb++) {
                    int nrow = 32 * h + nb * 8 + lrow;
                    uint32_t bf[2];
                    bf[0] = f2u(fs[OKo + nrow * KSTR + kk]);
                    bf[1] = f2u(fs[OKo + nrow * KSTR + kk + 4]);
                    mma8(sfrag[nb], a, bf);
                }
            }
            int grow0 = q0 + 16 * rg + lrow;
            #pragma unroll
            for (int nb = 0; nb < 4; nb++) {
                int cb0 = 32 * h + nb * 8 + 2 * lcol;
                float2 v0 = make_float2(sfrag[nb][0], sfrag[nb][1]);
                float2 v1 = make_float2(sfrag[nb][2], sfrag[nb][3]);
                if (maskc) {
                    int g = k0 + cb0;
                    if (g > grow0)         v0.x = -1e30f;
                    if (g + 1 > grow0)     v0.y = -1e30f;
                    if (g > grow0 + 8)     v1.x = -1e30f;
                    if (g + 1 > grow0 + 8) v1.y = -1e30f;
                }
                *(float2*)&fs[OS + (16 * rg + lrow) * SSTR + cb0] = v0;
                *(float2*)&fs[OS + (16 * rg + lrow + 8) * SSTR + cb0] = v1;
            }
        }
        __syncthreads();   // (B) scores visible; K buffer free

        // ---- early-issue K(c+1): latency hidden under softmax + PV ----
        if (more) {
            const float* Kn = KB + (size_t)(k0 + FBK) * DD;
            #pragma unroll
            for (int p = 0; p < 16; p++) {
                int idx = tid + p * 256;
                int r = idx >> 6, c4 = idx & 63;
                cp16(sb + (uint32_t)(OKo + r * KSTR + c4 * 4) * 4, Kn + (size_t)r * DD + c4 * 4);
            }
            CP_COMMIT();
        }

        // ---- online softmax: 4 threads per row, 16 cols each ----
        {
            int row = tid >> 2, seg = tid & 3;
            float* Sr = &fs[OS + row * SSTR + seg * 16];
            float4 x0 = ((float4*)Sr)[0];
            float4 x1 = ((float4*)Sr)[1];
            float4 x2 = ((float4*)Sr)[2];
            float4 x3 = ((float4*)Sr)[3];
            float mx = fmaxf(fmaxf(fmaxf(x0.x, x0.y), fmaxf(x0.z, x0.w)),
                       fmaxf(fmaxf(fmaxf(x1.x, x1.y), fmaxf(x1.z, x1.w)),
                       fmaxf(fmaxf(fmaxf(x2.x, x2.y), fmaxf(x2.z, x2.w)),
                             fmaxf(fmaxf(x3.x, x3.y), fmaxf(x3.z, x3.w)))));
            mx = fmaxf(mx, __shfl_xor_sync(0xffffffff, mx, 1));
            mx = fmaxf(mx, __shfl_xor_sync(0xffffffff, mx, 2));
            float mold = fs[OM + row];
            float mnew = fmaxf(mold, mx);
            float alpha = __expf(mold - mnew);
            float sum = 0.0f;
            #pragma unroll
            for (int q = 0; q < 4; q++) {
                float4* xp = (q == 0) ? &x0 : (q == 1) ? &x1 : (q == 2) ? &x2 : &x3;
                xp->x = __expf(xp->x - mnew); sum += xp->x; xp->x = tf32r(xp->x);
                xp->y = __expf(xp->y - mnew); sum += xp->y; xp->y = tf32r(xp->y);
                xp->z = __expf(xp->z - mnew); sum += xp->z; xp->z = tf32r(xp->z);
                xp->w = __expf(xp->w - mnew); sum += xp->w; xp->w = tf32r(xp->w);
            }
            ((float4*)Sr)[0] = x0; ((float4*)Sr)[1] = x1;
            ((float4*)Sr)[2] = x2; ((float4*)Sr)[3] = x3;
            sum += __shfl_xor_sync(0xffffffff, sum, 1);
            sum += __shfl_xor_sync(0xffffffff, sum, 2);
            if (seg == 0) {
                fs[OL + row] = fs[OL + row] * alpha + sum;
                fs[OM + row] = mnew;
                fs[OA + row] = alpha;
            }
        }
        if (more) { CP_WAIT1(); } else { CP_WAIT0(); }   // V(c) landed
        __syncthreads();   // (C) P + alpha + V visible

        // ---- PV: warp (rg,h): O[16rg..+15][128h..+127] += P * V ----
        {
            float al0 = fs[OA + 16 * rg + lrow];
            float al8 = fs[OA + 16 * rg + lrow + 8];
            #pragma unroll
            for (int nb = 0; nb < 16; nb++) {
                ofrag[nb][0] *= al0; ofrag[nb][1] *= al0;
                ofrag[nb][2] *= al8; ofrag[nb][3] *= al8;
            }
            int prow = 16 * rg + lrow;
            #pragma unroll
            for (int kb = 0; kb < 8; kb++) {
                int kk = kb * 8 + lcol;
                uint32_t a[4];
                a[0] = f2u(fs[OS + prow * SSTR + kk]);
                a[1] = f2u(fs[OS + (prow + 8) * SSTR + kk]);
                a[2] = f2u(fs[OS + prow * SSTR + kk + 4]);
                a[3] = f2u(fs[OS + (prow + 8) * SSTR + kk + 4]);
                #pragma unroll
                for (int nb = 0; nb < 16; nb++) {
                    int ncol = 128 * h + nb * 8 + lrow;
                    uint32_t bf[2];
                    bf[0] = f2u(fs[OV + kk * VSTR + ncol]);
                    bf[1] = f2u(fs[OV + (kk + 4) * VSTR + ncol]);
                    mma8(ofrag[nb], a, bf);
                }
            }
        }
        __syncthreads();   // (D) V buffer free

        // ---- issue V(c+1) ----
        if (more) {
            const float* Vn = VB + (size_t)(k0 + FBK) * DD;
            #pragma unroll
            for (int p = 0; p < 16; p++) {
                int idx = tid + p * 256;
                int r = idx >> 6, c4 = idx & 63;
                cp16(sb + (uint32_t)(OV + r * VSTR + c4 * 4) * 4, Vn + (size_t)r * DD + c4 * 4);
            }
            CP_COMMIT();
        }
    }

    // ---- epilogue ----
    {
        int row = 16 * rg + lrow;
        float inv0 = 1.0f / fs[OL + row];
        float inv8 = 1.0f / fs[OL + row + 8];
        float* Or0 = Og + ((size_t)b * SS + q0 + row) * DD;
        float* Or8 = Or0 + 8 * DD;
        #pragma unroll
        for (int nb = 0; nb < 16; nb++) {
            int col = 128 * h + nb * 8 + 2 * lcol;
            *(float2*)&Or0[col] = make_float2(ofrag[nb][0] * inv0, ofrag[nb][1] * inv0);
            *(float2*)&Or8[col] = make_float2(ofrag[nb][2] * inv8, ofrag[nb][3] * inv8);
        }
    }
}

// ============================================================
// tf32 HMMA GEMM v4: BM=128, BN=128, BK=32, cp.async 3-STAGE
// pipeline, coalesced staging. 256 threads (8 warps = 4m x 2n),
// warp tile 32x64. Dynamic smem 107.5KB -> 2 CTAs/SM.
// ROUND: output v = tf32r(v * oscale) (pre-rounding for flash).
// ============================================================
// dyn smem floats: As[3] at s*4608 (128*36); Ws[3] at 13824 + s*4352 (32*136)
#define GEMM_SMEM_FLOATS 26880

template<int BIAS, int LEAKY, int ROUND>
__global__ void __launch_bounds__(256, 2)
gemm_tc(const float* __restrict__ A, const float* __restrict__ W,
        const float* __restrict__ bias, float* __restrict__ C,
        int M, int N, int K, float oscale) {
    extern __shared__ float gs[];
    uint32_t sb = smem_u32(gs);
    int tid = threadIdx.x;
    int wid = tid >> 5, lane = tid & 31;
    int wm = wid & 3, wn = wid >> 2;
    int lrow = lane >> 2, lcol = lane & 3;
    int rb = blockIdx.y * 128, cb = blockIdx.x * 128;

    float cfr[2][8][4];
    #pragma unroll
    for (int mt = 0; mt < 2; mt++)
        #pragma unroll
        for (int nb = 0; nb < 8; nb++)
            #pragma unroll
            for (int j = 0; j < 4; j++) cfr[mt][nb][j] = 0.0f;

    int NI = (K + 31) / 32;

    #define STAGE(buf, k0s) do {                                                  \
        int _k0 = (k0s);                                                          \
        _Pragma("unroll")                                                         \
        for (int p = 0; p < 4; p++) {                                             \
            int idx = tid + p * 256;                                              \
            int r = idx >> 3, c4 = idx & 7;                                       \
            int col = _k0 + c4 * 4;                                               \
            bool ok = col < K;                                                    \
            const float* src = A + (size_t)(rb + r) * K + (ok ? col : 0);         \
            cp16z(sb + (uint32_t)((buf) * 4608 + r * 36 + c4 * 4) * 4, src, ok);  \
        }                                                                         \
        _Pragma("unroll")                                                         \
        for (int p = 0; p < 4; p++) {                                             \
            int idx = tid + p * 256;                                              \
            int r = idx >> 5, c4 = idx & 31;                                      \
            int row = _k0 + r, col = cb + c4 * 4;                                 \
            bool ok = (row < K) && (col < N);                                     \
            const float* src = W + (ok ? ((size_t)row * N + col) : 0);            \
            cp16z(sb + (uint32_t)(13824 + (buf) * 4352 + r * 136 + c4 * 4) * 4, src, ok); \
        }                                                                         \
    } while (0)

    STAGE(0, 0);
    CP_COMMIT();
    if (NI > 1) { STAGE(1, 32); }
    CP_COMMIT();
    if (NI > 2) { STAGE(2, 64); }
    CP_COMMIT();

    for (int it = 0; it < NI; it++) {
        CP_WAIT2();
        __syncthreads();
        int s = it % 3;
        int Ab = s * 4608;
        int Wb = 13824 + s * 4352;
        #pragma unroll
        for (int kb = 0; kb < 4; kb++) {
            int kk = kb * 8 + lcol;
            uint32_t a[2][4];
            #pragma unroll
            for (int mt = 0; mt < 2; mt++) {
                int row = 32 * wm + 16 * mt + lrow;
                a[mt][0] = f2u(tf32r(gs[Ab + row * 36 + kk]));
                a[mt][1] = f2u(tf32r(gs[Ab + (row + 8) * 36 + kk]));
                a[mt][2] = f2u(tf32r(gs[Ab + row * 36 + kk + 4]));
                a[mt][3] = f2u(tf32r(gs[Ab + (row + 8) * 36 + kk + 4]));
            }
            #pragma unroll
            for (int nb = 0; nb < 8; nb++) {
                int ncol = 64 * wn + 8 * nb + lrow;
                uint32_t b2[2];
                b2[0] = f2u(tf32r(gs[Wb + kk * 136 + ncol]));
                b2[1] = f2u(tf32r(gs[Wb + (kk + 4) * 136 + ncol]));
                mma8(cfr[0][nb], a[0], b2);
                mma8(cfr[1][nb], a[1], b2);
            }
        }
        __syncthreads();
        if (it + 3 < NI) { STAGE(s, (it + 3) * 32); CP_COMMIT(); }
    }
    #undef STAGE

    // ---- epilogue ----
    #pragma unroll
    for (int mt = 0; mt < 2; mt++) {
        int r0 = rb + 32 * wm + 16 * mt + lrow;
        #pragma unroll
        for (int nb = 0; nb < 8; nb++) {
            int col = cb + 64 * wn + 8 * nb + 2 * lcol;
            if (col < N) {
                float v00 = cfr[mt][nb][0], v01 = cfr[mt][nb][1];
                float v10 = cfr[mt][nb][2], v11 = cfr[mt][nb][3];
                if (BIAS) {
                    float b0 = bias[col], b1 = bias[col + 1];
                    v00 += b0; v01 += b1; v10 += b0; v11 += b1;
                }
                if (LEAKY) {
                    v00 = (v00 > 0.0f) ? v00 : 0.2f * v00;
                    v01 = (v01 > 0.0f) ? v01 : 0.2f * v01;
                    v10 = (v10 > 0.0f) ? v10 : 0.2f * v10;
                    v11 = (v11 > 0.0f) ? v11 : 0.2f * v11;
                }
                if (ROUND) {
                    v00 = tf32r(v00 * oscale); v01 = tf32r(v01 * oscale);
                    v10 = tf32r(v10 * oscale); v11 = tf32r(v11 * oscale);
                }
                *(float2*)&C[(size_t)r0 * N + col] = make_float2(v00, v01);
                *(float2*)&C[(size_t)(r0 + 8) * N + col] = make_float2(v10, v11);
            }
        }
    }
}

// ============================================================
// out = LayerNorm(a + b), eps = 1e-3.  One warp per row (8 rows/block).
// ============================================================
__global__ void __launch_bounds__(256)
add_ln_kernel(const float* __restrict__ a, const float* __restrict__ bvec,
              const float* __restrict__ gamma, const float* __restrict__ beta,
              float* __restrict__ out) {
    int wid = threadIdx.x >> 5, lane = threadIdx.x & 31;
    int row = blockIdx.x * 8 + wid;
    const float4* ar = (const float4*)(a + (size_t)row * DD);
    const float4* br = (const float4*)(bvec + (size_t)row * DD);
    float4 v0 = ar[lane];        float4 w0 = br[lane];
    float4 v1 = ar[lane + 32];   float4 w1 = br[lane + 32];
    v0.x += w0.x; v0.y += w0.y; v0.z += w0.z; v0.w += w0.w;
    v1.x += w1.x; v1.y += w1.y; v1.z += w1.z; v1.w += w1.w;

    float sum = v0.x + v0.y + v0.z + v0.w + v1.x + v1.y + v1.z + v1.w;
    #pragma unroll
    for (int off = 16; off > 0; off >>= 1) sum += __shfl_xor_sync(0xffffffff, sum, off);
    float mu = sum * (1.0f / DD);

    float sq = (v0.x - mu) * (v0.x - mu) + (v0.y - mu) * (v0.y - mu)
             + (v0.z - mu) * (v0.z - mu) + (v0.w - mu) * (v0.w - mu)
             + (v1.x - mu) * (v1.x - mu) + (v1.y - mu) * (v1.y - mu)
             + (v1.z - mu) * (v1.z - mu) + (v1.w - mu) * (v1.w - mu);
    #pragma unroll
    for (int off = 16; off > 0; off >>= 1) sq += __shfl_xor_sync(0xffffffff, sq, off);
    float rs = rsqrtf(sq * (1.0f / DD) + 1e-3f);

    const float4* g4 = (const float4*)gamma;
    const float4* b4 = (const float4*)beta;
    float4 g0 = g4[lane], g1 = g4[lane + 32];
    float4 e0 = b4[lane], e1 = b4[lane + 32];
    float4 o0, o1;
    o0.x = (v0.x - mu) * rs * g0.x + e0.x;
    o0.y = (v0.y - mu) * rs * g0.y + e0.y;
    o0.z = (v0.z - mu) * rs * g0.z + e0.z;
    o0.w = (v0.w - mu) * rs * g0.w + e0.w;
    o1.x = (v1.x - mu) * rs * g1.x + e1.x;
    o1.y = (v1.y - mu) * rs * g1.y + e1.y;
    o1.z = (v1.z - mu) * rs * g1.z + e1.z;
    o1.w = (v1.w - mu) * rs * g1.w + e1.w;
    float4* orow = (float4*)(out + (size_t)row * DD);
    orow[lane] = o0;
    orow[lane + 32] = o1;
}

// ============================================================
extern "C" void kernel_launch(void* const* d_in, const int* in_sizes, int n_in,
                              void* d_out, int out_size) {
    const float* inputs = (const float*)d_in[0];
    const float* ctx    = (const float*)d_in[1];
    const float* sa_Wk  = (const float*)d_in[2];
    const float* sa_Wv  = (const float*)d_in[3];
    const float* sa_Wq  = (const float*)d_in[4];
    const float* ca_Wk  = (const float*)d_in[5];
    const float* ca_Wv  = (const float*)d_in[6];
    const float* ca_Wq  = (const float*)d_in[7];
    const float* W1     = (const float*)d_in[8];
    const float* b1     = (const float*)d_in[9];
    const float* W2     = (const float*)d_in[10];
    const float* b2     = (const float*)d_in[11];
    const float* gamma  = (const float*)d_in[12];
    const float* beta   = (const float*)d_in[13];
    float* out = (float*)d_out;

    float *Qp, *Kp, *Vp, *Tp, *Xp, *Yp, *Hp;
    cudaGetSymbolAddress((void**)&Qp, g_Q);
    cudaGetSymbolAddress((void**)&Kp, g_K);
    cudaGetSymbolAddress((void**)&Vp, g_V);
    cudaGetSymbolAddress((void**)&Tp, g_T);
    cudaGetSymbolAddress((void**)&Xp, g_X);
    cudaGetSymbolAddress((void**)&Yp, g_Y);
    cudaGetSymbolAddress((void**)&Hp, g_H);

    const int flash_smem = FL_FLOATS * 4;
    const int gemm_smem = GEMM_SMEM_FLOATS * 4;
    cudaFuncSetAttribute(flash_mma, cudaFuncAttributeMaxDynamicSharedMemorySize, flash_smem);
    cudaFuncSetAttribute(gemm_tc<0, 0, 1>, cudaFuncAttributeMaxDynamicSharedMemorySize, gemm_smem);
    cudaFuncSetAttribute(gemm_tc<1, 1, 0>, cudaFuncAttributeMaxDynamicSharedMemorySize, gemm_smem);
    cudaFuncSetAttribute(gemm_tc<1, 0, 0>, cudaFuncAttributeMaxDynamicSharedMemorySize, gemm_smem);

    dim3 gD(DD / 128, BSROWS / 128);            // N=256: (2,128)
    dim3 gH((HH + 127) / 128, BSROWS / 128);    // N=400: (4,128)
    dim3 fg(SS / FBQ, BB);
    int lnB = BSROWS / 8;

    const float qs = 0.015625f;   // 1/sqrt(4096)

    // 1) self-attention (causal)
    gemm_tc<0, 0, 1><<<gD, 256, gemm_smem>>>(inputs, sa_Wk, nullptr, Kp, BSROWS, DD, DD, 1.0f);
    gemm_tc<0, 0, 1><<<gD, 256, gemm_smem>>>(inputs, sa_Wv, nullptr, Vp, BSROWS, DD, DD, 1.0f);
    gemm_tc<0, 0, 1><<<gD, 256, gemm_smem>>>(inputs, sa_Wq, nullptr, Qp, BSROWS, DD, DD, qs);
    flash_mma<<<fg, 256, flash_smem>>>(Qp, Kp, Vp, Tp, 1);
    add_ln_kernel<<<lnB, 256>>>(Tp, inputs, gamma, beta, Xp);

    // 2) cross-attention
    gemm_tc<0, 0, 1><<<gD, 256, gemm_smem>>>(ctx, ca_Wk, nullptr, Kp, BSROWS, DD, DD, 1.0f);
    gemm_tc<0, 0, 1><<<gD, 256, gemm_smem>>>(ctx, ca_Wv, nullptr, Vp, BSROWS, DD, DD, 1.0f);
    gemm_tc<0, 0, 1><<<gD, 256, gemm_smem>>>(Xp, ca_Wq, nullptr, Qp, BSROWS, DD, DD, qs);
    flash_mma<<<fg, 256, flash_smem>>>(Qp, Kp, Vp, Tp, 0);
    add_ln_kernel<<<lnB, 256>>>(Tp, Xp, gamma, beta, Yp);

    // 3) FFN
    gemm_tc<1, 1, 0><<<gH, 256, gemm_smem>>>(Yp, W1, b1, Hp, BSROWS, HH, DD, 1.0f);
    gemm_tc<1, 0, 0><<<gD, 256, gemm_smem>>>(Hp, W2, b2, Tp, BSROWS, DD, HH, 1.0f);
    add_ln_kernel<<<lnB, 256>>>(Tp, Yp, gamma, beta, out);
}

// round 12
// speedup vs baseline: 1.4174x; 1.0214x over previous
#include <cuda_runtime.h>
#include <cstdint>
#include <math.h>

#define BB 4
#define SS 4096
#define DD 256
#define HH 400
#define BSROWS (BB*SS)

// ---- scratch ----
__device__ float g_Q[BSROWS*DD];
__device__ float g_K[BSROWS*DD];
__device__ float g_V[BSROWS*DD];
__device__ float g_K2[BSROWS*DD];
__device__ float g_V2[BSROWS*DD];
__device__ float g_T[BSROWS*DD];
__device__ float g_X[BSROWS*DD];
__device__ float g_Xr[BSROWS*DD];
__device__ float g_Y[BSROWS*DD];
__device__ float g_Yr[BSROWS*DD];
__device__ float g_H[BSROWS*HH];
__device__ float g_WB[598016];     // rounded weights

// ============================================================
// helpers
// ============================================================
__device__ __forceinline__ float tf32r(float x) {
    float r; asm("cvt.rna.tf32.f32 %0, %1;" : "=f"(r) : "f"(x)); return r;
}
__device__ __forceinline__ uint32_t smem_u32(const void* p) {
    uint32_t a;
    asm("{ .reg .u64 t; cvta.to.shared.u64 t, %1; cvt.u32.u64 %0, t; }" : "=r"(a) : "l"(p));
    return a;
}
__device__ __forceinline__ void mma8(float c[4], const uint32_t a[4], const uint32_t b[2]) {
    asm volatile(
        "mma.sync.aligned.m16n8k8.row.col.f32.tf32.tf32.f32 "
        "{%0,%1,%2,%3}, {%4,%5,%6,%7}, {%8,%9}, {%0,%1,%2,%3};"
        : "+f"(c[0]), "+f"(c[1]), "+f"(c[2]), "+f"(c[3])
        : "r"(a[0]), "r"(a[1]), "r"(a[2]), "r"(a[3]), "r"(b[0]), "r"(b[1]));
}
__device__ __forceinline__ uint32_t f2u(float x) { return __float_as_uint(x); }

__device__ __forceinline__ void cp16(uint32_t dst, const void* src) {
    asm volatile("cp.async.cg.shared.global [%0], [%1], 16;" :: "r"(dst), "l"(src));
}
__device__ __forceinline__ void cp16z(uint32_t dst, const void* src, bool ok) {
    int sz = ok ? 16 : 0;
    asm volatile("cp.async.cg.shared.global [%0], [%1], 16, %2;" :: "r"(dst), "l"(src), "r"(sz));
}
#define CP_COMMIT() asm volatile("cp.async.commit_group;" ::: "memory")
#define CP_WAIT0()  asm volatile("cp.async.wait_group 0;" ::: "memory")
#define CP_WAIT1()  asm volatile("cp.async.wait_group 1;" ::: "memory")
#define CP_WAIT2()  asm volatile("cp.async.wait_group 2;" ::: "memory")

// ============================================================
// Flash attention, tf32 HMMA (R11, unchanged — proven).
// ============================================================
#define FBQ 64
#define FBK 64
#define QSTR 260
#define KSTR 260
#define VSTR 264
#define SSTR 68
#define OQ 0
#define OKo 16640
#define OV 33280
#define OS 50176
#define OM 54528
#define OL 54592
#define OA 54656
#define FL_FLOATS 54720           // *4 = 218880 bytes

__global__ void __launch_bounds__(256, 1)
flash_mma(const float* __restrict__ Qg, const float* __restrict__ Kg,
          const float* __restrict__ Vg, float* __restrict__ Og, int causal) {
    extern __shared__ float fs[];
    uint32_t sb = smem_u32(fs);
    int tid = threadIdx.x;
    int wid = tid >> 5, lane = tid & 31;
    int rg = wid & 3;
    int h  = wid >> 2;
    int lrow = lane >> 2;
    int lcol = lane & 3;
    int b = blockIdx.y;
    int qb = causal ? ((int)gridDim.x - 1 - (int)blockIdx.x) : (int)blockIdx.x;
    int q0 = qb * FBQ;
    int nc = causal ? (qb + 1) : (SS / FBK);

    const float* QB = Qg + ((size_t)b * SS + q0) * DD;
    const float* KB = Kg + (size_t)b * SS * DD;
    const float* VB = Vg + (size_t)b * SS * DD;

    {
        #pragma unroll
        for (int p = 0; p < 16; p++) {
            int idx = tid + p * 256;
            int r = idx >> 6, c4 = idx & 63;
            cp16(sb + (uint32_t)(OQ + r * QSTR + c4 * 4) * 4, QB + (size_t)r * DD + c4 * 4);
        }
        #pragma unroll
        for (int p = 0; p < 16; p++) {
            int idx = tid + p * 256;
            int r = idx >> 6, c4 = idx & 63;
            cp16(sb + (uint32_t)(OKo + r * KSTR + c4 * 4) * 4, KB + (size_t)r * DD + c4 * 4);
        }
        CP_COMMIT();
        #pragma unroll
        for (int p = 0; p < 16; p++) {
            int idx = tid + p * 256;
            int r = idx >> 6, c4 = idx & 63;
            cp16(sb + (uint32_t)(OV + r * VSTR + c4 * 4) * 4, VB + (size_t)r * DD + c4 * 4);
        }
        CP_COMMIT();
    }
    if (tid < FBQ) { fs[OM + tid] = -INFINITY; fs[OL + tid] = 0.0f; }

    float ofrag[16][4];
    #pragma unroll
    for (int nb = 0; nb < 16; nb++)
        #pragma unroll
        for (int j = 0; j < 4; j++) ofrag[nb][j] = 0.0f;

    for (int c = 0; c < nc; c++) {
        int k0 = c * FBK;
        bool maskc = causal && (k0 == q0);
        bool more = (c + 1) < nc;

        CP_WAIT1();
        __syncthreads();   // (A)

        {
            float sfrag[4][4];
            #pragma unroll
            for (int nb = 0; nb < 4; nb++)
                #pragma unroll
                for (int j = 0; j < 4; j++) sfrag[nb][j] = 0.0f;

            int qrow = 16 * rg + lrow;
            #pragma unroll 4
            for (int kb = 0; kb < 32; kb++) {
                int kk = kb * 8 + lcol;
                uint32_t a[4];
                a[0] = f2u(fs[OQ + qrow * QSTR + kk]);
                a[1] = f2u(fs[OQ + (qrow + 8) * QSTR + kk]);
                a[2] = f2u(fs[OQ + qrow * QSTR + kk + 4]);
                a[3] = f2u(fs[OQ + (qrow + 8) * QSTR + kk + 4]);
                #pragma unroll
                for (int nb = 0; nb < 4; nb++) {
                    int nrow = 32 * h + nb * 8 + lrow;
                    uint32_t bf[2];
                    bf[0] = f2u(fs[OKo + nrow * KSTR + kk]);
                    bf[1] = f2u(fs[OKo + nrow * KSTR + kk + 4]);
                    mma8(sfrag[nb], a, bf);
                }
            }
            int grow0 = q0 + 16 * rg + lrow;
            #pragma unroll
            for (int nb = 0; nb < 4; nb++) {
                int cb0 = 32 * h + nb * 8 + 2 * lcol;
                float2 v0 = make_float2(sfrag[nb][0], sfrag[nb][1]);
                float2 v1 = make_float2(sfrag[nb][2], sfrag[nb][3]);
                if (maskc) {
                    int g = k0 + cb0;
                    if (g > grow0)         v0.x = -1e30f;
                    if (g + 1 > grow0)     v0.y = -1e30f;
                    if (g > grow0 + 8)     v1.x = -1e30f;
                    if (g + 1 > grow0 + 8) v1.y = -1e30f;
                }
                *(float2*)&fs[OS + (16 * rg + lrow) * SSTR + cb0] = v0;
                *(float2*)&fs[OS + (16 * rg + lrow + 8) * SSTR + cb0] = v1;
            }
        }
        __syncthreads();   // (B)

        if (more) {
            const float* Kn = KB + (size_t)(k0 + FBK) * DD;
            #pragma unroll
            for (int p = 0; p < 16; p++) {
                int idx = tid + p * 256;
                int r = idx >> 6, c4 = idx & 63;
                cp16(sb + (uint32_t)(OKo + r * KSTR + c4 * 4) * 4, Kn + (size_t)r * DD + c4 * 4);
            }
            CP_COMMIT();
        }

        {
            int row = tid >> 2, seg = tid & 3;
            float* Sr = &fs[OS + row * SSTR + seg * 16];
            float4 x0 = ((float4*)Sr)[0];
            float4 x1 = ((float4*)Sr)[1];
            float4 x2 = ((float4*)Sr)[2];
            float4 x3 = ((float4*)Sr)[3];
            float mx = fmaxf(fmaxf(fmaxf(x0.x, x0.y), fmaxf(x0.z, x0.w)),
                       fmaxf(fmaxf(fmaxf(x1.x, x1.y), fmaxf(x1.z, x1.w)),
                       fmaxf(fmaxf(fmaxf(x2.x, x2.y), fmaxf(x2.z, x2.w)),
                             fmaxf(fmaxf(x3.x, x3.y), fmaxf(x3.z, x3.w)))));
            mx = fmaxf(mx, __shfl_xor_sync(0xffffffff, mx, 1));
            mx = fmaxf(mx, __shfl_xor_sync(0xffffffff, mx, 2));
            float mold = fs[OM + row];
            float mnew = fmaxf(mold, mx);
            float alpha = __expf(mold - mnew);
            float sum = 0.0f;
            #pragma unroll
            for (int q = 0; q < 4; q++) {
                float4* xp = (q == 0) ? &x0 : (q == 1) ? &x1 : (q == 2) ? &x2 : &x3;
                xp->x = __expf(xp->x - mnew); sum += xp->x; xp->x = tf32r(xp->x);
                xp->y = __expf(xp->y - mnew); sum += xp->y; xp->y = tf32r(xp->y);
                xp->z = __expf(xp->z - mnew); sum += xp->z; xp->z = tf32r(xp->z);
                xp->w = __expf(xp->w - mnew); sum += xp->w; xp->w = tf32r(xp->w);
            }
            ((float4*)Sr)[0] = x0; ((float4*)Sr)[1] = x1;
            ((float4*)Sr)[2] = x2; ((float4*)Sr)[3] = x3;
            sum += __shfl_xor_sync(0xffffffff, sum, 1);
            sum += __shfl_xor_sync(0xffffffff, sum, 2);
            if (seg == 0) {
                fs[OL + row] = fs[OL + row] * alpha + sum;
                fs[OM + row] = mnew;
                fs[OA + row] = alpha;
            }
        }
        if (more) { CP_WAIT1(); } else { CP_WAIT0(); }
        __syncthreads();   // (C)

        {
            float al0 = fs[OA + 16 * rg + lrow];
            float al8 = fs[OA + 16 * rg + lrow + 8];
            #pragma unroll
            for (int nb = 0; nb < 16; nb++) {
                ofrag[nb][0] *= al0; ofrag[nb][1] *= al0;
                ofrag[nb][2] *= al8; ofrag[nb][3] *= al8;
            }
            int prow = 16 * rg + lrow;
            #pragma unroll
            for (int kb = 0; kb < 8; kb++) {
                int kk = kb * 8 + lcol;
                uint32_t a[4];
                a[0] = f2u(fs[OS + prow * SSTR + kk]);
                a[1] = f2u(fs[OS + (prow + 8) * SSTR + kk]);
                a[2] = f2u(fs[OS + prow * SSTR + kk + 4]);
                a[3] = f2u(fs[OS + (prow + 8) * SSTR + kk + 4]);
                #pragma unroll
                for (int nb = 0; nb < 16; nb++) {
                    int ncol = 128 * h + nb * 8 + lrow;
                    uint32_t bf[2];
                    bf[0] = f2u(fs[OV + kk * VSTR + ncol]);
                    bf[1] = f2u(fs[OV + (kk + 4) * VSTR + ncol]);
                    mma8(ofrag[nb], a, bf);
                }
            }
        }
        __syncthreads();   // (D)

        if (more) {
            const float* Vn = VB + (size_t)(k0 + FBK) * DD;
            #pragma unroll
            for (int p = 0; p < 16; p++) {
                int idx = tid + p * 256;
                int r = idx >> 6, c4 = idx & 63;
                cp16(sb + (uint32_t)(OV + r * VSTR + c4 * 4) * 4, Vn + (size_t)r * DD + c4 * 4);
            }
            CP_COMMIT();
        }
    }

    {
        int row = 16 * rg + lrow;
        float inv0 = 1.0f / fs[OL + row];
        float inv8 = 1.0f / fs[OL + row + 8];
        float* Or0 = Og + ((size_t)b * SS + q0 + row) * DD;
        float* Or8 = Or0 + 8 * DD;
        #pragma unroll
        for (int nb = 0; nb < 16; nb++) {
            int col = 128 * h + nb * 8 + 2 * lcol;
            *(float2*)&Or0[col] = make_float2(ofrag[nb][0] * inv0, ofrag[nb][1] * inv0);
            *(float2*)&Or8[col] = make_float2(ofrag[nb][2] * inv8, ofrag[nb][3] * inv8);
        }
    }
}

// ============================================================
// GEMM body (R11 v4 pipeline). W is PRE-ROUNDED; A rounded at
// read only if CVTA (raw inputs). BM=128,BN=128,BK=32, 3-stage.
// ============================================================
#define GEMM_SMEM_FLOATS 26880

template<int BIAS, int LEAKY, int ROUND, int CVTA>
__device__ __forceinline__ void gemm_body(
    const float* __restrict__ A, const float* __restrict__ W,
    const float* __restrict__ bias, float* __restrict__ C,
    int N, int K, float oscale, float* gs, uint32_t sb, int bx, int by) {
    int tid = threadIdx.x;
    int wid = tid >> 5, lane = tid & 31;
    int wm = wid & 3, wn = wid >> 2;
    int lrow = lane >> 2, lcol = lane & 3;
    int rb = by * 128, cb = bx * 128;

    float cfr[2][8][4];
    #pragma unroll
    for (int mt = 0; mt < 2; mt++)
        #pragma unroll
        for (int nb = 0; nb < 8; nb++)
            #pragma unroll
            for (int j = 0; j < 4; j++) cfr[mt][nb][j] = 0.0f;

    int NI = (K + 31) / 32;

    #define STAGE(buf, k0s) do {                                                  \
        int _k0 = (k0s);                                                          \
        _Pragma("unroll")                                                         \
        for (int p = 0; p < 4; p++) {                                             \
            int idx = tid + p * 256;                                              \
            int r = idx >> 3, c4 = idx & 7;                                       \
            int col = _k0 + c4 * 4;                                               \
            bool ok = col < K;                                                    \
            const float* src = A + (size_t)(rb + r) * K + (ok ? col : 0);         \
            cp16z(sb + (uint32_t)((buf) * 4608 + r * 36 + c4 * 4) * 4, src, ok);  \
        }                                                                         \
        _Pragma("unroll")                                                         \
        for (int p = 0; p < 4; p++) {                                             \
            int idx = tid + p * 256;                                              \
            int r = idx >> 5, c4 = idx & 31;                                      \
            int row = _k0 + r, col = cb + c4 * 4;                                 \
            bool ok = (row < K) && (col < N);                                     \
            const float* src = W + (ok ? ((size_t)row * N + col) : 0);            \
            cp16z(sb + (uint32_t)(13824 + (buf) * 4352 + r * 136 + c4 * 4) * 4, src, ok); \
        }                                                                         \
    } while (0)

    STAGE(0, 0);
    CP_COMMIT();
    if (NI > 1) { STAGE(1, 32); }
    CP_COMMIT();
    if (NI > 2) { STAGE(2, 64); }
    CP_COMMIT();

    for (int it = 0; it < NI; it++) {
        CP_WAIT2();
        __syncthreads();
        int s = it % 3;
        int Ab = s * 4608;
        int Wb = 13824 + s * 4352;
        #pragma unroll
        for (int kb = 0; kb < 4; kb++) {
            int kk = kb * 8 + lcol;
            uint32_t a[2][4];
            #pragma unroll
            for (int mt = 0; mt < 2; mt++) {
                int row = 32 * wm + 16 * mt + lrow;
                if (CVTA) {
                    a[mt][0] = f2u(tf32r(gs[Ab + row * 36 + kk]));
                    a[mt][1] = f2u(tf32r(gs[Ab + (row + 8) * 36 + kk]));
                    a[mt][2] = f2u(tf32r(gs[Ab + row * 36 + kk + 4]));
                    a[mt][3] = f2u(tf32r(gs[Ab + (row + 8) * 36 + kk + 4]));
                } else {
                    a[mt][0] = f2u(gs[Ab + row * 36 + kk]);
                    a[mt][1] = f2u(gs[Ab + (row + 8) * 36 + kk]);
                    a[mt][2] = f2u(gs[Ab + row * 36 + kk + 4]);
                    a[mt][3] = f2u(gs[Ab + (row + 8) * 36 + kk + 4]);
                }
            }
            #pragma unroll
            for (int nb = 0; nb < 8; nb++) {
                int ncol = 64 * wn + 8 * nb + lrow;
                uint32_t b2[2];
                b2[0] = f2u(gs[Wb + kk * 136 + ncol]);
                b2[1] = f2u(gs[Wb + (kk + 4) * 136 + ncol]);
                mma8(cfr[0][nb], a[0], b2);
                mma8(cfr[1][nb], a[1], b2);
            }
        }
        __syncthreads();
        if (it + 3 < NI) { STAGE(s, (it + 3) * 32); CP_COMMIT(); }
    }
    #undef STAGE

    #pragma unroll
    for (int mt = 0; mt < 2; mt++) {
        int r0 = rb + 32 * wm + 16 * mt + lrow;
        #pragma unroll
        for (int nb = 0; nb < 8; nb++) {
            int col = cb + 64 * wn + 8 * nb + 2 * lcol;
            if (col < N) {
                float v00 = cfr[mt][nb][0], v01 = cfr[mt][nb][1];
                float v10 = cfr[mt][nb][2], v11 = cfr[mt][nb][3];
                if (BIAS) {
                    float b0 = bias[col], b1 = bias[col + 1];
                    v00 += b0; v01 += b1; v10 += b0; v11 += b1;
                }
                if (LEAKY) {
                    v00 = (v00 > 0.0f) ? v00 : 0.2f * v00;
                    v01 = (v01 > 0.0f) ? v01 : 0.2f * v01;
                    v10 = (v10 > 0.0f) ? v10 : 0.2f * v10;
                    v11 = (v11 > 0.0f) ? v11 : 0.2f * v11;
                }
                if (ROUND) {
                    v00 = tf32r(v00 * oscale); v01 = tf32r(v01 * oscale);
                    v10 = tf32r(v10 * oscale); v11 = tf32r(v11 * oscale);
                }
                *(float2*)&C[(size_t)r0 * N + col] = make_float2(v00, v01);
                *(float2*)&C[(size_t)(r0 + 8) * N + col] = make_float2(v10, v11);
            }
        }
    }
}

template<int BIAS, int LEAKY, int ROUND, int CVTA>
__global__ void __launch_bounds__(256, 2)
gemm_tc(const float* __restrict__ A, const float* __restrict__ W,
        const float* __restrict__ bias, float* __restrict__ C,
        int N, int K, float oscale) {
    extern __shared__ float gs[];
    gemm_body<BIAS, LEAKY, ROUND, CVTA>(A, W, bias, C, N, K, oscale,
                                        gs, smem_u32(gs), blockIdx.x, blockIdx.y);
}

// ---- batched 5-projection GEMM (one launch) ----
struct Proj5Args {
    const float* A[5];
    const float* W[5];
    float* C[5];
    float s[5];
};

__global__ void __launch_bounds__(256, 2)
proj5_tc(Proj5Args pa) {
    extern __shared__ float gs[];
    int z = blockIdx.z;
    gemm_body<0, 0, 1, 1>(pa.A[z], pa.W[z], nullptr, pa.C[z], DD, DD, pa.s[z],
                          gs, smem_u32(gs), blockIdx.x, blockIdx.y);
}

// ---- weight pre-rounding (one launch, 8 matrices) ----
struct RW8Args {
    const float* src[8];
    float* dst[8];
    int n[8];
};

__global__ void __launch_bounds__(256)
round_w8(RW8Args wa) {
    int z = blockIdx.z;
    int off = (blockIdx.x * 256 + threadIdx.x) * 4;
    if (off < wa.n[z]) {
        float4 v = *(const float4*)(wa.src[z] + off);
        v.x = tf32r(v.x); v.y = tf32r(v.y); v.z = tf32r(v.z); v.w = tf32r(v.w);
        *(float4*)(wa.dst[z] + off) = v;
    }
}

// ============================================================
// out = LayerNorm(a + b), eps = 1e-3. Warp per row.
// Optionally also writes tf32-rounded copy (rout) for GEMM A use.
// ============================================================
__global__ void __launch_bounds__(256)
add_ln_kernel(const float* __restrict__ a, const float* __restrict__ bvec,
              const float* __restrict__ gamma, const float* __restrict__ beta,
              float* __restrict__ out, float* __restrict__ rout) {
    int wid = threadIdx.x >> 5, lane = threadIdx.x & 31;
    int row = blockIdx.x * 8 + wid;
    const float4* ar = (const float4*)(a + (size_t)row * DD);
    const float4* br = (const float4*)(bvec + (size_t)row * DD);
    float4 v0 = ar[lane];        float4 w0 = br[lane];
    float4 v1 = ar[lane + 32];   float4 w1 = br[lane + 32];
    v0.x += w0.x; v0.y += w0.y; v0.z += w0.z; v0.w += w0.w;
    v1.x += w1.x; v1.y += w1.y; v1.z += w1.z; v1.w += w1.w;

    float sum = v0.x + v0.y + v0.z + v0.w + v1.x + v1.y + v1.z + v1.w;
    #pragma unroll
    for (int off = 16; off > 0; off >>= 1) sum += __shfl_xor_sync(0xffffffff, sum, off);
    float mu = sum * (1.0f / DD);

    float sq = (v0.x - mu) * (v0.x - mu) + (v0.y - mu) * (v0.y - mu)
             + (v0.z - mu) * (v0.z - mu) + (v0.w - mu) * (v0.w - mu)
             + (v1.x - mu) * (v1.x - mu) + (v1.y - mu) * (v1.y - mu)
             + (v1.z - mu) * (v1.z - mu) + (v1.w - mu) * (v1.w - mu);
    #pragma unroll
    for (int off = 16; off > 0; off >>= 1) sq += __shfl_xor_sync(0xffffffff, sq, off);
    float rs = rsqrtf(sq * (1.0f / DD) + 1e-3f);

    const float4* g4 = (const float4*)gamma;
    const float4* b4 = (const float4*)beta;
    float4 g0 = g4[lane], g1 = g4[lane + 32];
    float4 e0 = b4[lane], e1 = b4[lane + 32];
    float4 o0, o1;
    o0.x = (v0.x - mu) * rs * g0.x + e0.x;
    o0.y = (v0.y - mu) * rs * g0.y + e0.y;
    o0.z = (v0.z - mu) * rs * g0.z + e0.z;
    o0.w = (v0.w - mu) * rs * g0.w + e0.w;
    o1.x = (v1.x - mu) * rs * g1.x + e1.x;
    o1.y = (v1.y - mu) * rs * g1.y + e1.y;
    o1.z = (v1.z - mu) * rs * g1.z + e1.z;
    o1.w = (v1.w - mu) * rs * g1.w + e1.w;
    float4* orow = (float4*)(out + (size_t)row * DD);
    orow[lane] = o0;
    orow[lane + 32] = o1;
    if (rout) {
        float4 r0, r1;
        r0.x = tf32r(o0.x); r0.y = tf32r(o0.y); r0.z = tf32r(o0.z); r0.w = tf32r(o0.w);
        r1.x = tf32r(o1.x); r1.y = tf32r(o1.y); r1.z = tf32r(o1.z); r1.w = tf32r(o1.w);
        float4* rrow = (float4*)(rout + (size_t)row * DD);
        rrow[lane] = r0;
        rrow[lane + 32] = r1;
    }
}

// ============================================================
extern "C" void kernel_launch(void* const* d_in, const int* in_sizes, int n_in,
                              void* d_out, int out_size) {
    const float* inputs = (const float*)d_in[0];
    const float* ctx    = (const float*)d_in[1];
    const float* sa_Wk  = (const float*)d_in[2];
    const float* sa_Wv  = (const float*)d_in[3];
    const float* sa_Wq  = (const float*)d_in[4];
    const float* ca_Wk  = (const float*)d_in[5];
    const float* ca_Wv  = (const float*)d_in[6];
    const float* ca_Wq  = (const float*)d_in[7];
    const float* W1     = (const float*)d_in[8];
    const float* b1     = (const float*)d_in[9];
    const float* W2     = (const float*)d_in[10];
    const float* b2     = (const float*)d_in[11];
    const float* gamma  = (const float*)d_in[12];
    const float* beta   = (const float*)d_in[13];
    float* out = (float*)d_out;

    float *Qp, *Kp, *Vp, *K2, *V2, *Tp, *Xp, *Xr, *Yp, *Yr, *Hp, *WB;
    cudaGetSymbolAddress((void**)&Qp, g_Q);
    cudaGetSymbolAddress((void**)&Kp, g_K);
    cudaGetSymbolAddress((void**)&Vp, g_V);
    cudaGetSymbolAddress((void**)&K2, g_K2);
    cudaGetSymbolAddress((void**)&V2, g_V2);
    cudaGetSymbolAddress((void**)&Tp, g_T);
    cudaGetSymbolAddress((void**)&Xp, g_X);
    cudaGetSymbolAddress((void**)&Xr, g_Xr);
    cudaGetSymbolAddress((void**)&Yp, g_Y);
    cudaGetSymbolAddress((void**)&Yr, g_Yr);
    cudaGetSymbolAddress((void**)&Hp, g_H);
    cudaGetSymbolAddress((void**)&WB, g_WB);

    // rounded-weight offsets in g_WB
    float* r_saWk = WB + 0;
    float* r_saWv = WB + 65536;
    float* r_saWq = WB + 131072;
    float* r_caWk = WB + 196608;
    float* r_caWv = WB + 262144;
    float* r_caWq = WB + 327680;
    float* r_W1   = WB + 393216;
    float* r_W2   = WB + 495616;

    const int flash_smem = FL_FLOATS * 4;
    const int gemm_smem = GEMM_SMEM_FLOATS * 4;
    cudaFuncSetAttribute(flash_mma, cudaFuncAttributeMaxDynamicSharedMemorySize, flash_smem);
    cudaFuncSetAttribute(proj5_tc, cudaFuncAttributeMaxDynamicSharedMemorySize, gemm_smem);
    cudaFuncSetAttribute(gemm_tc<0, 0, 1, 0>, cudaFuncAttributeMaxDynamicSharedMemorySize, gemm_smem);
    cudaFuncSetAttribute(gemm_tc<1, 1, 1, 0>, cudaFuncAttributeMaxDynamicSharedMemorySize, gemm_smem);
    cudaFuncSetAttribute(gemm_tc<1, 0, 0, 0>, cudaFuncAttributeMaxDynamicSharedMemorySize, gemm_smem);

    const float qs = 0.015625f;   // 1/sqrt(4096)

    // 0) pre-round all weights (one small launch)
    {
        RW8Args wa;
        wa.src[0] = sa_Wk; wa.dst[0] = r_saWk; wa.n[0] = DD * DD;
        wa.src[1] = sa_Wv; wa.dst[1] = r_saWv; wa.n[1] = DD * DD;
        wa.src[2] = sa_Wq; wa.dst[2] = r_saWq; wa.n[2] = DD * DD;
        wa.src[3] = ca_Wk; wa.dst[3] = r_caWk; wa.n[3] = DD * DD;
        wa.src[4] = ca_Wv; wa.dst[4] = r_caWv; wa.n[4] = DD * DD;
        wa.src[5] = ca_Wq; wa.dst[5] = r_caWq; wa.n[5] = DD * DD;
        wa.src[6] = W1;    wa.dst[6] = r_W1;   wa.n[6] = DD * HH;
        wa.src[7] = W2;    wa.dst[7] = r_W2;   wa.n[7] = HH * DD;
        dim3 rg((DD * HH + 1023) / 1024, 1, 8);
        round_w8<<<rg, 256>>>(wa);
    }

    // 1) fused 5-projection batch: sa_K, sa_V, sa_Q, ca_K, ca_V
    {
        Proj5Args pa;
        pa.A[0] = inputs; pa.W[0] = r_saWk; pa.C[0] = Kp; pa.s[0] = 1.0f;
        pa.A[1] = inputs; pa.W[1] = r_saWv; pa.C[1] = Vp; pa.s[1] = 1.0f;
        pa.A[2] = inputs; pa.W[2] = r_saWq; pa.C[2] = Qp; pa.s[2] = qs;
        pa.A[3] = ctx;    pa.W[3] = r_caWk; pa.C[3] = K2; pa.s[3] = 1.0f;
        pa.A[4] = ctx;    pa.W[4] = r_caWv; pa.C[4] = V2; pa.s[4] = 1.0f;
        dim3 pg(DD / 128, BSROWS / 128, 5);
        proj5_tc<<<pg, 256, gemm_smem>>>(pa);
    }

    dim3 gD(DD / 128, BSROWS / 128);
    dim3 gH((HH + 127) / 128, BSROWS / 128);
    dim3 fg(SS / FBQ, BB);
    int lnB = BSROWS / 8;

    // 2) self-attention (causal) + LN1
    flash_mma<<<fg, 256, flash_smem>>>(Qp, Kp, Vp, Tp, 1);
    add_ln_kernel<<<lnB, 256>>>(Tp, inputs, gamma, beta, Xp, Xr);

    // 3) cross-attention + LN2
    gemm_tc<0, 0, 1, 0><<<gD, 256, gemm_smem>>>(Xr, r_caWq, nullptr, Qp, DD, DD, qs);
    flash_mma<<<fg, 256, flash_smem>>>(Qp, K2, V2, Tp, 0);
    add_ln_kernel<<<lnB, 256>>>(Tp, Xp, gamma, beta, Yp, Yr);

    // 4) FFN + LN3
    gemm_tc<1, 1, 1, 0><<<gH, 256, gemm_smem>>>(Yr, r_W1, b1, Hp, HH, DD, 1.0f);
    gemm_tc<1, 0, 0, 0><<<gD, 256, gemm_smem>>>(Hp, r_W2, b2, Tp, DD, HH, 1.0f);
    add_ln_kernel<<<lnB, 256>>>(Tp, Yp, gamma, beta, out, nullptr);
}

// round 13
// speedup vs baseline: 1.4639x; 1.0328x over previous
#include <cuda_runtime.h>
#include <cstdint>
#include <math.h>

#define BB 4
#define SS 4096
#define DD 256
#define HH 400
#define BSROWS (BB*SS)

// ---- scratch ----
__device__ float g_Q[BSROWS*DD];
__device__ float g_K[BSROWS*DD];
__device__ float g_V[BSROWS*DD];
__device__ float g_K2[BSROWS*DD];
__device__ float g_V2[BSROWS*DD];
__device__ float g_T[BSROWS*DD];
__device__ float g_X[BSROWS*DD];
__device__ float g_Xr[BSROWS*DD];
__device__ float g_Y[BSROWS*DD];
__device__ float g_Yr[BSROWS*DD];
__device__ float g_H[BSROWS*HH];
__device__ float g_WB[598016];     // rounded weights

// ============================================================
// helpers
// ============================================================
__device__ __forceinline__ float tf32r(float x) {
    float r; asm("cvt.rna.tf32.f32 %0, %1;" : "=f"(r) : "f"(x)); return r;
}
__device__ __forceinline__ uint32_t smem_u32(const void* p) {
    uint32_t a;
    asm("{ .reg .u64 t; cvta.to.shared.u64 t, %1; cvt.u32.u64 %0, t; }" : "=r"(a) : "l"(p));
    return a;
}
__device__ __forceinline__ void mma8(float c[4], const uint32_t a[4], const uint32_t b[2]) {
    asm volatile(
        "mma.sync.aligned.m16n8k8.row.col.f32.tf32.tf32.f32 "
        "{%0,%1,%2,%3}, {%4,%5,%6,%7}, {%8,%9}, {%0,%1,%2,%3};"
        : "+f"(c[0]), "+f"(c[1]), "+f"(c[2]), "+f"(c[3])
        : "r"(a[0]), "r"(a[1]), "r"(a[2]), "r"(a[3]), "r"(b[0]), "r"(b[1]));
}
__device__ __forceinline__ uint32_t f2u(float x) { return __float_as_uint(x); }

__device__ __forceinline__ void cp16(uint32_t dst, const void* src) {
    asm volatile("cp.async.cg.shared.global [%0], [%1], 16;" :: "r"(dst), "l"(src));
}
__device__ __forceinline__ void cp16z(uint32_t dst, const void* src, bool ok) {
    int sz = ok ? 16 : 0;
    asm volatile("cp.async.cg.shared.global [%0], [%1], 16, %2;" :: "r"(dst), "l"(src), "r"(sz));
}
#define CP_COMMIT() asm volatile("cp.async.commit_group;" ::: "memory")
#define CP_WAIT0()  asm volatile("cp.async.wait_group 0;" ::: "memory")
#define CP_WAIT1()  asm volatile("cp.async.wait_group 1;" ::: "memory")
#define CP_WAIT2()  asm volatile("cp.async.wait_group 2;" ::: "memory")

// ============================================================
// Flash attention, tf32 HMMA. R11 pipeline, R13 warp layout:
// 8 warps = 2 row-groups (32 rows) x 4 col-quarters.
// Scores: warp tile 32x16.  PV: warp tile 32x64.
// Crossbar words/thread/chunk: 576 (was 672 in R4H2).
// ============================================================
#define FBQ 64
#define FBK 64
#define QSTR 260
#define KSTR 260
#define VSTR 264
#define SSTR 68
#define OQ 0
#define OKo 16640
#define OV 33280
#define OS 50176
#define OM 54528
#define OL 54592
#define OA 54656
#define FL_FLOATS 54720           // *4 = 218880 bytes

__global__ void __launch_bounds__(256, 1)
flash_mma(const float* __restrict__ Qg, const float* __restrict__ Kg,
          const float* __restrict__ Vg, float* __restrict__ Og, int causal) {
    extern __shared__ float fs[];
    uint32_t sb = smem_u32(fs);
    int tid = threadIdx.x;
    int wid = tid >> 5, lane = tid & 31;
    int rg = wid & 1;          // row-group: rows 32*rg .. +31
    int h  = wid >> 1;         // quarter: score cols 16h..+15 / O cols 64h..+63
    int lrow = lane >> 2;
    int lcol = lane & 3;
    int b = blockIdx.y;
    int qb = causal ? ((int)gridDim.x - 1 - (int)blockIdx.x) : (int)blockIdx.x;
    int q0 = qb * FBQ;
    int nc = causal ? (qb + 1) : (SS / FBK);

    const float* QB = Qg + ((size_t)b * SS + q0) * DD;
    const float* KB = Kg + (size_t)b * SS * DD;
    const float* VB = Vg + (size_t)b * SS * DD;

    // ---- prologue: cp.async Q + K0 (group 1), V0 (group 2) ----
    {
        #pragma unroll
        for (int p = 0; p < 16; p++) {
            int idx = tid + p * 256;
            int r = idx >> 6, c4 = idx & 63;
            cp16(sb + (uint32_t)(OQ + r * QSTR + c4 * 4) * 4, QB + (size_t)r * DD + c4 * 4);
        }
        #pragma unroll
        for (int p = 0; p < 16; p++) {
            int idx = tid + p * 256;
            int r = idx >> 6, c4 = idx & 63;
            cp16(sb + (uint32_t)(OKo + r * KSTR + c4 * 4) * 4, KB + (size_t)r * DD + c4 * 4);
        }
        CP_COMMIT();
        #pragma unroll
        for (int p = 0; p < 16; p++) {
            int idx = tid + p * 256;
            int r = idx >> 6, c4 = idx & 63;
            cp16(sb + (uint32_t)(OV + r * VSTR + c4 * 4) * 4, VB + (size_t)r * DD + c4 * 4);
        }
        CP_COMMIT();
    }
    if (tid < FBQ) { fs[OM + tid] = -INFINITY; fs[OL + tid] = 0.0f; }

    // O accumulator: 2 m-tiles x 8 n-tiles (warp tile 32x64)
    float ofrag[2][8][4];
    #pragma unroll
    for (int mt = 0; mt < 2; mt++)
        #pragma unroll
        for (int nb = 0; nb < 8; nb++)
            #pragma unroll
            for (int j = 0; j < 4; j++) ofrag[mt][nb][j] = 0.0f;

    for (int c = 0; c < nc; c++) {
        int k0 = c * FBK;
        bool maskc = causal && (k0 == q0);
        bool more = (c + 1) < nc;

        CP_WAIT1();
        __syncthreads();   // (A) K(c) (and Q on c==0) visible

        // ---- scores: warp (rg,h): S[32rg..+31][16h..+15] ----
        {
            float sfrag[2][2][4];
            #pragma unroll
            for (int mt = 0; mt < 2; mt++)
                #pragma unroll
                for (int nb = 0; nb < 2; nb++)
                    #pragma unroll
                    for (int j = 0; j < 4; j++) sfrag[mt][nb][j] = 0.0f;

            #pragma unroll 4
            for (int kb = 0; kb < 32; kb++) {
                int kk = kb * 8 + lcol;
                uint32_t a[2][4];
                #pragma unroll
                for (int mt = 0; mt < 2; mt++) {
                    int row = 32 * rg + 16 * mt + lrow;
                    a[mt][0] = f2u(fs[OQ + row * QSTR + kk]);
                    a[mt][1] = f2u(fs[OQ + (row + 8) * QSTR + kk]);
                    a[mt][2] = f2u(fs[OQ + row * QSTR + kk + 4]);
                    a[mt][3] = f2u(fs[OQ + (row + 8) * QSTR + kk + 4]);
                }
                #pragma unroll
                for (int nb = 0; nb < 2; nb++) {
                    int nrow = 16 * h + 8 * nb + lrow;
                    uint32_t bf[2];
                    bf[0] = f2u(fs[OKo + nrow * KSTR + kk]);
                    bf[1] = f2u(fs[OKo + nrow * KSTR + kk + 4]);
                    mma8(sfrag[0][nb], a[0], bf);
                    mma8(sfrag[1][nb], a[1], bf);
                }
            }
            #pragma unroll
            for (int mt = 0; mt < 2; mt++) {
                int r0 = 32 * rg + 16 * mt + lrow;
                int grow0 = q0 + r0;
                #pragma unroll
                for (int nb = 0; nb < 2; nb++) {
                    int cb0 = 16 * h + 8 * nb + 2 * lcol;
                    float2 v0 = make_float2(sfrag[mt][nb][0], sfrag[mt][nb][1]);
                    float2 v1 = make_float2(sfrag[mt][nb][2], sfrag[mt][nb][3]);
                    if (maskc) {
                        int g = k0 + cb0;
                        if (g > grow0)         v0.x = -1e30f;
                        if (g + 1 > grow0)     v0.y = -1e30f;
                        if (g > grow0 + 8)     v1.x = -1e30f;
                        if (g + 1 > grow0 + 8) v1.y = -1e30f;
                    }
                    *(float2*)&fs[OS + r0 * SSTR + cb0] = v0;
                    *(float2*)&fs[OS + (r0 + 8) * SSTR + cb0] = v1;
                }
            }
        }
        __syncthreads();   // (B) scores visible; K buffer free

        // ---- early-issue K(c+1) ----
        if (more) {
            const float* Kn = KB + (size_t)(k0 + FBK) * DD;
            #pragma unroll
            for (int p = 0; p < 16; p++) {
                int idx = tid + p * 256;
                int r = idx >> 6, c4 = idx & 63;
                cp16(sb + (uint32_t)(OKo + r * KSTR + c4 * 4) * 4, Kn + (size_t)r * DD + c4 * 4);
            }
            CP_COMMIT();
        }

        // ---- online softmax: 4 threads per row, 16 cols each ----
        {
            int row = tid >> 2, seg = tid & 3;
            float* Sr = &fs[OS + row * SSTR + seg * 16];
            float4 x0 = ((float4*)Sr)[0];
            float4 x1 = ((float4*)Sr)[1];
            float4 x2 = ((float4*)Sr)[2];
            float4 x3 = ((float4*)Sr)[3];
            float mx = fmaxf(fmaxf(fmaxf(x0.x, x0.y), fmaxf(x0.z, x0.w)),
                       fmaxf(fmaxf(fmaxf(x1.x, x1.y), fmaxf(x1.z, x1.w)),
                       fmaxf(fmaxf(fmaxf(x2.x, x2.y), fmaxf(x2.z, x2.w)),
                             fmaxf(fmaxf(x3.x, x3.y), fmaxf(x3.z, x3.w)))));
            mx = fmaxf(mx, __shfl_xor_sync(0xffffffff, mx, 1));
            mx = fmaxf(mx, __shfl_xor_sync(0xffffffff, mx, 2));
            float mold = fs[OM + row];
            float mnew = fmaxf(mold, mx);
            float alpha = __expf(mold - mnew);
            float sum = 0.0f;
            #pragma unroll
            for (int q = 0; q < 4; q++) {
                float4* xp = (q == 0) ? &x0 : (q == 1) ? &x1 : (q == 2) ? &x2 : &x3;
                xp->x = __expf(xp->x - mnew); sum += xp->x; xp->x = tf32r(xp->x);
                xp->y = __expf(xp->y - mnew); sum += xp->y; xp->y = tf32r(xp->y);
                xp->z = __expf(xp->z - mnew); sum += xp->z; xp->z = tf32r(xp->z);
                xp->w = __expf(xp->w - mnew); sum += xp->w; xp->w = tf32r(xp->w);
            }
            ((float4*)Sr)[0] = x0; ((float4*)Sr)[1] = x1;
            ((float4*)Sr)[2] = x2; ((float4*)Sr)[3] = x3;
            sum += __shfl_xor_sync(0xffffffff, sum, 1);
            sum += __shfl_xor_sync(0xffffffff, sum, 2);
            if (seg == 0) {
                fs[OL + row] = fs[OL + row] * alpha + sum;
                fs[OM + row] = mnew;
                fs[OA + row] = alpha;
            }
        }
        if (more) { CP_WAIT1(); } else { CP_WAIT0(); }
        __syncthreads();   // (C) P + alpha + V visible

        // ---- PV: warp (rg,h): O[32rg..+31][64h..+63] += P * V ----
        {
            float al[2][2];
            #pragma unroll
            for (int mt = 0; mt < 2; mt++) {
                al[mt][0] = fs[OA + 32 * rg + 16 * mt + lrow];
                al[mt][1] = fs[OA + 32 * rg + 16 * mt + lrow + 8];
            }
            #pragma unroll
            for (int mt = 0; mt < 2; mt++)
                #pragma unroll
                for (int nb = 0; nb < 8; nb++) {
                    ofrag[mt][nb][0] *= al[mt][0]; ofrag[mt][nb][1] *= al[mt][0];
                    ofrag[mt][nb][2] *= al[mt][1]; ofrag[mt][nb][3] *= al[mt][1];
                }
            #pragma unroll
            for (int kb = 0; kb < 8; kb++) {
                int kk = kb * 8 + lcol;
                uint32_t pa[2][4];
                #pragma unroll
                for (int mt = 0; mt < 2; mt++) {
                    int pr = 32 * rg + 16 * mt + lrow;
                    pa[mt][0] = f2u(fs[OS + pr * SSTR + kk]);
                    pa[mt][1] = f2u(fs[OS + (pr + 8) * SSTR + kk]);
                    pa[mt][2] = f2u(fs[OS + pr * SSTR + kk + 4]);
                    pa[mt][3] = f2u(fs[OS + (pr + 8) * SSTR + kk + 4]);
                }
                #pragma unroll
                for (int nb = 0; nb < 8; nb++) {
                    int ncol = 64 * h + 8 * nb + lrow;
                    uint32_t bf[2];
                    bf[0] = f2u(fs[OV + kk * VSTR + ncol]);
                    bf[1] = f2u(fs[OV + (kk + 4) * VSTR + ncol]);
                    mma8(ofrag[0][nb], pa[0], bf);
                    mma8(ofrag[1][nb], pa[1], bf);
                }
            }
        }
        __syncthreads();   // (D) V buffer free

        if (more) {
            const float* Vn = VB + (size_t)(k0 + FBK) * DD;
            #pragma unroll
            for (int p = 0; p < 16; p++) {
                int idx = tid + p * 256;
                int r = idx >> 6, c4 = idx & 63;
                cp16(sb + (uint32_t)(OV + r * VSTR + c4 * 4) * 4, Vn + (size_t)r * DD + c4 * 4);
            }
            CP_COMMIT();
        }
    }

    // ---- epilogue ----
    #pragma unroll
    for (int mt = 0; mt < 2; mt++) {
        int row = 32 * rg + 16 * mt + lrow;
        float inv0 = 1.0f / fs[OL + row];
        float inv8 = 1.0f / fs[OL + row + 8];
        float* Or0 = Og + ((size_t)b * SS + q0 + row) * DD;
        float* Or8 = Or0 + 8 * DD;
        #pragma unroll
        for (int nb = 0; nb < 8; nb++) {
            int col = 64 * h + 8 * nb + 2 * lcol;
            *(float2*)&Or0[col] = make_float2(ofrag[mt][nb][0] * inv0, ofrag[mt][nb][1] * inv0);
            *(float2*)&Or8[col] = make_float2(ofrag[mt][nb][2] * inv8, ofrag[mt][nb][3] * inv8);
        }
    }
}

// ============================================================
// GEMM body (R12, unchanged). BM=128,BN=128,BK=32, 3-stage cp.async.
// ============================================================
#define GEMM_SMEM_FLOATS 26880

template<int BIAS, int LEAKY, int ROUND, int CVTA>
__device__ __forceinline__ void gemm_body(
    const float* __restrict__ A, const float* __restrict__ W,
    const float* __restrict__ bias, float* __restrict__ C,
    int N, int K, float oscale, float* gs, uint32_t sb, int bx, int by) {
    int tid = threadIdx.x;
    int wid = tid >> 5, lane = tid & 31;
    int wm = wid & 3, wn = wid >> 2;
    int lrow = lane >> 2, lcol = lane & 3;
    int rb = by * 128, cb = bx * 128;

    float cfr[2][8][4];
    #pragma unroll
    for (int mt = 0; mt < 2; mt++)
        #pragma unroll
        for (int nb = 0; nb < 8; nb++)
            #pragma unroll
            for (int j = 0; j < 4; j++) cfr[mt][nb][j] = 0.0f;

    int NI = (K + 31) / 32;

    #define STAGE(buf, k0s) do {                                                  \
        int _k0 = (k0s);                                                          \
        _Pragma("unroll")                                                         \
        for (int p = 0; p < 4; p++) {                                             \
            int idx = tid + p * 256;                                              \
            int r = idx >> 3, c4 = idx & 7;                                       \
            int col = _k0 + c4 * 4;                                               \
            bool ok = col < K;                                                    \
            const float* src = A + (size_t)(rb + r) * K + (ok ? col : 0);         \
            cp16z(sb + (uint32_t)((buf) * 4608 + r * 36 + c4 * 4) * 4, src, ok);  \
        }                                                                         \
        _Pragma("unroll")                                                         \
        for (int p = 0; p < 4; p++) {                                             \
            int idx = tid + p * 256;                                              \
            int r = idx >> 5, c4 = idx & 31;                                      \
            int row = _k0 + r, col = cb + c4 * 4;                                 \
            bool ok = (row < K) && (col < N);                                     \
            const float* src = W + (ok ? ((size_t)row * N + col) : 0);            \
            cp16z(sb + (uint32_t)(13824 + (buf) * 4352 + r * 136 + c4 * 4) * 4, src, ok); \
        }                                                                         \
    } while (0)

    STAGE(0, 0);
    CP_COMMIT();
    if (NI > 1) { STAGE(1, 32); }
    CP_COMMIT();
    if (NI > 2) { STAGE(2, 64); }
    CP_COMMIT();

    for (int it = 0; it < NI; it++) {
        CP_WAIT2();
        __syncthreads();
        int s = it % 3;
        int Ab = s * 4608;
        int Wb = 13824 + s * 4352;
        #pragma unroll
        for (int kb = 0; kb < 4; kb++) {
            int kk = kb * 8 + lcol;
            uint32_t a[2][4];
            #pragma unroll
            for (int mt = 0; mt < 2; mt++) {
                int row = 32 * wm + 16 * mt + lrow;
                if (CVTA) {
                    a[mt][0] = f2u(tf32r(gs[Ab + row * 36 + kk]));
                    a[mt][1] = f2u(tf32r(gs[Ab + (row + 8) * 36 + kk]));
                    a[mt][2] = f2u(tf32r(gs[Ab + row * 36 + kk + 4]));
                    a[mt][3] = f2u(tf32r(gs[Ab + (row + 8) * 36 + kk + 4]));
                } else {
                    a[mt][0] = f2u(gs[Ab + row * 36 + kk]);
                    a[mt][1] = f2u(gs[Ab + (row + 8) * 36 + kk]);
                    a[mt][2] = f2u(gs[Ab + row * 36 + kk + 4]);
                    a[mt][3] = f2u(gs[Ab + (row + 8) * 36 + kk + 4]);
                }
            }
            #pragma unroll
            for (int nb = 0; nb < 8; nb++) {
                int ncol = 64 * wn + 8 * nb + lrow;
                uint32_t b2[2];
                b2[0] = f2u(gs[Wb + kk * 136 + ncol]);
                b2[1] = f2u(gs[Wb + (kk + 4) * 136 + ncol]);
                mma8(cfr[0][nb], a[0], b2);
                mma8(cfr[1][nb], a[1], b2);
            }
        }
        __syncthreads();
        if (it + 3 < NI) { STAGE(s, (it + 3) * 32); CP_COMMIT(); }
    }
    #undef STAGE

    #pragma unroll
    for (int mt = 0; mt < 2; mt++) {
        int r0 = rb + 32 * wm + 16 * mt + lrow;
        #pragma unroll
        for (int nb = 0; nb < 8; nb++) {
            int col = cb + 64 * wn + 8 * nb + 2 * lcol;
            if (col < N) {
                float v00 = cfr[mt][nb][0], v01 = cfr[mt][nb][1];
                float v10 = cfr[mt][nb][2], v11 = cfr[mt][nb][3];
                if (BIAS) {
                    float b0 = bias[col], b1 = bias[col + 1];
                    v00 += b0; v01 += b1; v10 += b0; v11 += b1;
                }
                if (LEAKY) {
                    v00 = (v00 > 0.0f) ? v00 : 0.2f * v00;
                    v01 = (v01 > 0.0f) ? v01 : 0.2f * v01;
                    v10 = (v10 > 0.0f) ? v10 : 0.2f * v10;
                    v11 = (v11 > 0.0f) ? v11 : 0.2f * v11;
                }
                if (ROUND) {
                    v00 = tf32r(v00 * oscale); v01 = tf32r(v01 * oscale);
                    v10 = tf32r(v10 * oscale); v11 = tf32r(v11 * oscale);
                }
                *(float2*)&C[(size_t)r0 * N + col] = make_float2(v00, v01);
                *(float2*)&C[(size_t)(r0 + 8) * N + col] = make_float2(v10, v11);
            }
        }
    }
}

template<int BIAS, int LEAKY, int ROUND, int CVTA>
__global__ void __launch_bounds__(256, 2)
gemm_tc(const float* __restrict__ A, const float* __restrict__ W,
        const float* __restrict__ bias, float* __restrict__ C,
        int N, int K, float oscale) {
    extern __shared__ float gs[];
    gemm_body<BIAS, LEAKY, ROUND, CVTA>(A, W, bias, C, N, K, oscale,
                                        gs, smem_u32(gs), blockIdx.x, blockIdx.y);
}

// ---- batched 5-projection GEMM (one launch) ----
struct Proj5Args {
    const float* A[5];
    const float* W[5];
    float* C[5];
    float s[5];
};

__global__ void __launch_bounds__(256, 2)
proj5_tc(Proj5Args pa) {
    extern __shared__ float gs[];
    int z = blockIdx.z;
    gemm_body<0, 0, 1, 1>(pa.A[z], pa.W[z], nullptr, pa.C[z], DD, DD, pa.s[z],
                          gs, smem_u32(gs), blockIdx.x, blockIdx.y);
}

// ---- weight pre-rounding (one launch, 8 matrices) ----
struct RW8Args {
    const float* src[8];
    float* dst[8];
    int n[8];
};

__global__ void __launch_bounds__(256)
round_w8(RW8Args wa) {
    int z = blockIdx.z;
    int off = (blockIdx.x * 256 + threadIdx.x) * 4;
    if (off < wa.n[z]) {
        float4 v = *(const float4*)(wa.src[z] + off);
        v.x = tf32r(v.x); v.y = tf32r(v.y); v.z = tf32r(v.z); v.w = tf32r(v.w);
        *(float4*)(wa.dst[z] + off) = v;
    }
}

// ============================================================
// out = LayerNorm(a + b), eps = 1e-3. Warp per row.
// Optionally also writes tf32-rounded copy (rout).
// ============================================================
__global__ void __launch_bounds__(256)
add_ln_kernel(const float* __restrict__ a, const float* __restrict__ bvec,
              const float* __restrict__ gamma, const float* __restrict__ beta,
              float* __restrict__ out, float* __restrict__ rout) {
    int wid = threadIdx.x >> 5, lane = threadIdx.x & 31;
    int row = blockIdx.x * 8 + wid;
    const float4* ar = (const float4*)(a + (size_t)row * DD);
    const float4* br = (const float4*)(bvec + (size_t)row * DD);
    float4 v0 = ar[lane];        float4 w0 = br[lane];
    float4 v1 = ar[lane + 32];   float4 w1 = br[lane + 32];
    v0.x += w0.x; v0.y += w0.y; v0.z += w0.z; v0.w += w0.w;
    v1.x += w1.x; v1.y += w1.y; v1.z += w1.z; v1.w += w1.w;

    float sum = v0.x + v0.y + v0.z + v0.w + v1.x + v1.y + v1.z + v1.w;
    #pragma unroll
    for (int off = 16; off > 0; off >>= 1) sum += __shfl_xor_sync(0xffffffff, sum, off);
    float mu = sum * (1.0f / DD);

    float sq = (v0.x - mu) * (v0.x - mu) + (v0.y - mu) * (v0.y - mu)
             + (v0.z - mu) * (v0.z - mu) + (v0.w - mu) * (v0.w - mu)
             + (v1.x - mu) * (v1.x - mu) + (v1.y - mu) * (v1.y - mu)
             + (v1.z - mu) * (v1.z - mu) + (v1.w - mu) * (v1.w - mu);
    #pragma unroll
    for (int off = 16; off > 0; off >>= 1) sq += __shfl_xor_sync(0xffffffff, sq, off);
    float rs = rsqrtf(sq * (1.0f / DD) + 1e-3f);

    const float4* g4 = (const float4*)gamma;
    const float4* b4 = (const float4*)beta;
    float4 g0 = g4[lane], g1 = g4[lane + 32];
    float4 e0 = b4[lane], e1 = b4[lane + 32];
    float4 o0, o1;
    o0.x = (v0.x - mu) * rs * g0.x + e0.x;
    o0.y = (v0.y - mu) * rs * g0.y + e0.y;
    o0.z = (v0.z - mu) * rs * g0.z + e0.z;
    o0.w = (v0.w - mu) * rs * g0.w + e0.w;
    o1.x = (v1.x - mu) * rs * g1.x + e1.x;
    o1.y = (v1.y - mu) * rs * g1.y + e1.y;
    o1.z = (v1.z - mu) * rs * g1.z + e1.z;
    o1.w = (v1.w - mu) * rs * g1.w + e1.w;
    float4* orow = (float4*)(out + (size_t)row * DD);
    orow[lane] = o0;
    orow[lane + 32] = o1;
    if (rout) {
        float4 r0, r1;
        r0.x = tf32r(o0.x); r0.y = tf32r(o0.y); r0.z = tf32r(o0.z); r0.w = tf32r(o0.w);
        r1.x = tf32r(o1.x); r1.y = tf32r(o1.y); r1.z = tf32r(o1.z); r1.w = tf32r(o1.w);
        float4* rrow = (float4*)(rout + (size_t)row * DD);
        rrow[lane] = r0;
        rrow[lane + 32] = r1;
    }
}

// ============================================================
extern "C" void kernel_launch(void* const* d_in, const int* in_sizes, int n_in,
                              void* d_out, int out_size) {
    const float* inputs = (const float*)d_in[0];
    const float* ctx    = (const float*)d_in[1];
    const float* sa_Wk  = (const float*)d_in[2];
    const float* sa_Wv  = (const float*)d_in[3];
    const float* sa_Wq  = (const float*)d_in[4];
    const float* ca_Wk  = (const float*)d_in[5];
    const float* ca_Wv  = (const float*)d_in[6];
    const float* ca_Wq  = (const float*)d_in[7];
    const float* W1     = (const float*)d_in[8];
    const float* b1     = (const float*)d_in[9];
    const float* W2     = (const float*)d_in[10];
    const float* b2     = (const float*)d_in[11];
    const float* gamma  = (const float*)d_in[12];
    const float* beta   = (const float*)d_in[13];
    float* out = (float*)d_out;

    float *Qp, *Kp, *Vp, *K2, *V2, *Tp, *Xp, *Xr, *Yp, *Yr, *Hp, *WB;
    cudaGetSymbolAddress((void**)&Qp, g_Q);
    cudaGetSymbolAddress((void**)&Kp, g_K);
    cudaGetSymbolAddress((void**)&Vp, g_V);
    cudaGetSymbolAddress((void**)&K2, g_K2);
    cudaGetSymbolAddress((void**)&V2, g_V2);
    cudaGetSymbolAddress((void**)&Tp, g_T);
    cudaGetSymbolAddress((void**)&Xp, g_X);
    cudaGetSymbolAddress((void**)&Xr, g_Xr);
    cudaGetSymbolAddress((void**)&Yp, g_Y);
    cudaGetSymbolAddress((void**)&Yr, g_Yr);
    cudaGetSymbolAddress((void**)&Hp, g_H);
    cudaGetSymbolAddress((void**)&WB, g_WB);

    float* r_saWk = WB + 0;
    float* r_saWv = WB + 65536;
    float* r_saWq = WB + 131072;
    float* r_caWk = WB + 196608;
    float* r_caWv = WB + 262144;
    float* r_caWq = WB + 327680;
    float* r_W1   = WB + 393216;
    float* r_W2   = WB + 495616;

    const int flash_smem = FL_FLOATS * 4;
    const int gemm_smem = GEMM_SMEM_FLOATS * 4;
    cudaFuncSetAttribute(flash_mma, cudaFuncAttributeMaxDynamicSharedMemorySize, flash_smem);
    cudaFuncSetAttribute(proj5_tc, cudaFuncAttributeMaxDynamicSharedMemorySize, gemm_smem);
    cudaFuncSetAttribute(gemm_tc<0, 0, 1, 0>, cudaFuncAttributeMaxDynamicSharedMemorySize, gemm_smem);
    cudaFuncSetAttribute(gemm_tc<1, 1, 1, 0>, cudaFuncAttributeMaxDynamicSharedMemorySize, gemm_smem);
    cudaFuncSetAttribute(gemm_tc<1, 0, 0, 0>, cudaFuncAttributeMaxDynamicSharedMemorySize, gemm_smem);

    const float qs = 0.015625f;   // 1/sqrt(4096)

    // 0) pre-round all weights
    {
        RW8Args wa;
        wa.src[0] = sa_Wk; wa.dst[0] = r_saWk; wa.n[0] = DD * DD;
        wa.src[1] = sa_Wv; wa.dst[1] = r_saWv; wa.n[1] = DD * DD;
        wa.src[2] = sa_Wq; wa.dst[2] = r_saWq; wa.n[2] = DD * DD;
        wa.src[3] = ca_Wk; wa.dst[3] = r_caWk; wa.n[3] = DD * DD;
        wa.src[4] = ca_Wv; wa.dst[4] = r_caWv; wa.n[4] = DD * DD;
        wa.src[5] = ca_Wq; wa.dst[5] = r_caWq; wa.n[5] = DD * DD;
        wa.src[6] = W1;    wa.dst[6] = r_W1;   wa.n[6] = DD * HH;
        wa.src[7] = W2;    wa.dst[7] = r_W2;   wa.n[7] = HH * DD;
        dim3 rg((DD * HH + 1023) / 1024, 1, 8);
        round_w8<<<rg, 256>>>(wa);
    }

    // 1) fused 5-projection batch
    {
        Proj5Args pa;
        pa.A[0] = inputs; pa.W[0] = r_saWk; pa.C[0] = Kp; pa.s[0] = 1.0f;
        pa.A[1] = inputs; pa.W[1] = r_saWv; pa.C[1] = Vp; pa.s[1] = 1.0f;
        pa.A[2] = inputs; pa.W[2] = r_saWq; pa.C[2] = Qp; pa.s[2] = qs;
        pa.A[3] = ctx;    pa.W[3] = r_caWk; pa.C[3] = K2; pa.s[3] = 1.0f;
        pa.A[4] = ctx;    pa.W[4] = r_caWv; pa.C[4] = V2; pa.s[4] = 1.0f;
        dim3 pg(DD / 128, BSROWS / 128, 5);
        proj5_tc<<<pg, 256, gemm_smem>>>(pa);
    }

    dim3 gD(DD / 128, BSROWS / 128);
    dim3 gH((HH + 127) / 128, BSROWS / 128);
    dim3 fg(SS / FBQ, BB);
    int lnB = BSROWS / 8;

    // 2) self-attention (causal) + LN1
    flash_mma<<<fg, 256, flash_smem>>>(Qp, Kp, Vp, Tp, 1);
    add_ln_kernel<<<lnB, 256>>>(Tp, inputs, gamma, beta, Xp, Xr);

    // 3) cross-attention + LN2
    gemm_tc<0, 0, 1, 0><<<gD, 256, gemm_smem>>>(Xr, r_caWq, nullptr, Qp, DD, DD, qs);
    flash_mma<<<fg, 256, flash_smem>>>(Qp, K2, V2, Tp, 0);
    add_ln_kernel<<<lnB, 256>>>(Tp, Xp, gamma, beta, Yp, Yr);

    // 4) FFN + LN3
    gemm_tc<1, 1, 1, 0><<<gH, 256, gemm_smem>>>(Yr, r_W1, b1, Hp, HH, DD, 1.0f);
    gemm_tc<1, 0, 0, 0><<<gD, 256, gemm_smem>>>(Hp, r_W2, b2, Tp, DD, HH, 1.0f);
    add_ln_kernel<<<lnB, 256>>>(Tp, Yp, gamma, beta, out, nullptr);
}

// round 14
// speedup vs baseline: 2.3689x; 1.6183x over previous
#include <cuda_runtime.h>
#include <cuda_fp16.h>
#include <cstdint>
#include <math.h>

#define BB 4
#define SS 4096
#define DD 256
#define HH 400
#define BSROWS (BB*SS)

// ---- scratch ----
__device__ __half g_Qh[BSROWS*DD];
__device__ __half g_Kh[BSROWS*DD];
__device__ __half g_Vth[BB*DD*SS];     // [b][d][s]
__device__ __half g_K2h[BSROWS*DD];
__device__ __half g_V2th[BB*DD*SS];
__device__ __half g_Ih[BSROWS*DD];     // half(inputs)
__device__ __half g_Ch[BSROWS*DD];     // half(ctx)
__device__ __half g_Xrh[BSROWS*DD];
__device__ __half g_Yrh[BSROWS*DD];
__device__ __half g_Hh[BSROWS*HH];
__device__ __half g_WTh[598016];       // transposed half weights
__device__ float  g_T[BSROWS*DD];
__device__ float  g_X[BSROWS*DD];
__device__ float  g_Y[BSROWS*DD];

// ============================================================
// helpers
// ============================================================
__device__ __forceinline__ uint32_t smem_u32(const void* p) {
    uint32_t a;
    asm("{ .reg .u64 t; cvta.to.shared.u64 t, %1; cvt.u32.u64 %0, t; }" : "=r"(a) : "l"(p));
    return a;
}
__device__ __forceinline__ void mmah(float c[4], const uint32_t a[4], const uint32_t b[2]) {
    asm volatile(
        "mma.sync.aligned.m16n8k16.row.col.f32.f16.f16.f32 "
        "{%0,%1,%2,%3}, {%4,%5,%6,%7}, {%8,%9}, {%0,%1,%2,%3};"
        : "+f"(c[0]), "+f"(c[1]), "+f"(c[2]), "+f"(c[3])
        : "r"(a[0]), "r"(a[1]), "r"(a[2]), "r"(a[3]), "r"(b[0]), "r"(b[1]));
}
__device__ __forceinline__ uint32_t packh2(float lo, float hi) {
    __half2 h = __floats2half2_rn(lo, hi);
    return *(uint32_t*)&h;
}
__device__ __forceinline__ void cp16(uint32_t dst, const void* src) {
    asm volatile("cp.async.cg.shared.global [%0], [%1], 16;" :: "r"(dst), "l"(src));
}
__device__ __forceinline__ void cp16z(uint32_t dst, const void* src, bool ok) {
    int sz = ok ? 16 : 0;
    asm volatile("cp.async.cg.shared.global [%0], [%1], 16, %2;" :: "r"(dst), "l"(src), "r"(sz));
}
#define CP_COMMIT() asm volatile("cp.async.commit_group;" ::: "memory")
#define CP_WAIT0()  asm volatile("cp.async.wait_group 0;" ::: "memory")
#define CP_WAIT1()  asm volatile("cp.async.wait_group 1;" ::: "memory")
#define CP_WAIT2()  asm volatile("cp.async.wait_group 2;" ::: "memory")

// ============================================================
// Flash attention, fp16 HMMA m16n8k16, fp32 softmax/accum.
// 8 warps = 2 row-groups x 4 col-quarters (R2H4). FBQ=FBK=64.
// Q/K half [s][d]; V half TRANSPOSED [d][s]; P half in smem.
// ============================================================
#define FBQ 64
#define FBK 64
#define QSTR 132    // half2 words per Q/K row (128 + 4 pad)
#define VTSTR 36    // half2 words per Vt row (32 + 4 pad)
#define SSTR 68     // fp32 score row stride
#define PSTR 36     // half2 words per P row (32 + 4 pad)
// word offsets in dynamic smem
#define OQ  0
#define OKo 8448
#define OVT 16896
#define OS  26112
#define OP  30464
#define OM  32768
#define OL  32832
#define OA  32896
#define FL_WORDS 32960          // *4 = 131840 bytes

__global__ void __launch_bounds__(256, 1)
flash_h(const __half* __restrict__ Qg, const __half* __restrict__ Kg,
        const __half* __restrict__ Vtg, float* __restrict__ Og, int causal) {
    extern __shared__ float fs[];
    uint32_t* fsu = (uint32_t*)fs;
    uint32_t sb = smem_u32(fs);
    int tid = threadIdx.x;
    int wid = tid >> 5, lane = tid & 31;
    int rg = wid & 1;          // rows 32*rg..+31
    int h  = wid >> 1;         // score cols 16h..+15 / O cols 64h..+63
    int lrow = lane >> 2;
    int lcol = lane & 3;
    int b = blockIdx.y;
    int qb = causal ? ((int)gridDim.x - 1 - (int)blockIdx.x) : (int)blockIdx.x;
    int q0 = qb * FBQ;
    int nc = causal ? (qb + 1) : (SS / FBK);

    const __half* QB  = Qg  + ((size_t)b * SS + q0) * DD;
    const __half* KB  = Kg  + (size_t)b * SS * DD;
    const __half* VtB = Vtg + (size_t)b * DD * SS;

    // ---- prologue: Q + K0 (group 1), V0 (group 2) ----
    {
        #pragma unroll
        for (int p = 0; p < 8; p++) {
            int idx = tid + p * 256;
            int r = idx >> 5, c = idx & 31;
            cp16(sb + (uint32_t)(OQ + r * QSTR + c * 4) * 4, QB + (size_t)r * DD + c * 8);
        }
        #pragma unroll
        for (int p = 0; p < 8; p++) {
            int idx = tid + p * 256;
            int r = idx >> 5, c = idx & 31;
            cp16(sb + (uint32_t)(OKo + r * QSTR + c * 4) * 4, KB + (size_t)r * DD + c * 8);
        }
        CP_COMMIT();
        #pragma unroll
        for (int p = 0; p < 8; p++) {
            int idx = tid + p * 256;
            int r = idx >> 3, c = idx & 7;
            cp16(sb + (uint32_t)(OVT + r * VTSTR + c * 4) * 4, VtB + (size_t)r * SS + c * 8);
        }
        CP_COMMIT();
    }
    if (tid < FBQ) { fs[OM + tid] = -INFINITY; fs[OL + tid] = 0.0f; }

    float ofrag[2][8][4];
    #pragma unroll
    for (int mt = 0; mt < 2; mt++)
        #pragma unroll
        for (int nb = 0; nb < 8; nb++)
            #pragma unroll
            for (int j = 0; j < 4; j++) ofrag[mt][nb][j] = 0.0f;

    for (int c = 0; c < nc; c++) {
        int k0 = c * FBK;
        bool maskc = causal && (k0 == q0);
        bool more = (c + 1) < nc;

        CP_WAIT1();
        __syncthreads();   // (A)

        // ---- scores: warp (rg,h): S[32rg..+31][16h..+15] ----
        {
            float sfrag[2][2][4];
            #pragma unroll
            for (int mt = 0; mt < 2; mt++)
                #pragma unroll
                for (int nb = 0; nb < 2; nb++)
                    #pragma unroll
                    for (int j = 0; j < 4; j++) sfrag[mt][nb][j] = 0.0f;

            #pragma unroll 4
            for (int kb = 0; kb < 16; kb++) {
                int kw = kb * 8 + lcol;
                uint32_t a[2][4];
                #pragma unroll
                for (int mt = 0; mt < 2; mt++) {
                    int row = 32 * rg + 16 * mt + lrow;
                    a[mt][0] = fsu[OQ + row * QSTR + kw];
                    a[mt][1] = fsu[OQ + (row + 8) * QSTR + kw];
                    a[mt][2] = fsu[OQ + row * QSTR + kw + 4];
                    a[mt][3] = fsu[OQ + (row + 8) * QSTR + kw + 4];
                }
                #pragma unroll
                for (int nb = 0; nb < 2; nb++) {
                    int nrow = 16 * h + 8 * nb + lrow;
                    uint32_t b2[2];
                    b2[0] = fsu[OKo + nrow * QSTR + kw];
                    b2[1] = fsu[OKo + nrow * QSTR + kw + 4];
                    mmah(sfrag[0][nb], a[0], b2);
                    mmah(sfrag[1][nb], a[1], b2);
                }
            }
            #pragma unroll
            for (int mt = 0; mt < 2; mt++) {
                int r0 = 32 * rg + 16 * mt + lrow;
                int grow0 = q0 + r0;
                #pragma unroll
                for (int nb = 0; nb < 2; nb++) {
                    int cb0 = 16 * h + 8 * nb + 2 * lcol;
                    float2 v0 = make_float2(sfrag[mt][nb][0], sfrag[mt][nb][1]);
                    float2 v1 = make_float2(sfrag[mt][nb][2], sfrag[mt][nb][3]);
                    if (maskc) {
                        int g = k0 + cb0;
                        if (g > grow0)         v0.x = -1e30f;
                        if (g + 1 > grow0)     v0.y = -1e30f;
                        if (g > grow0 + 8)     v1.x = -1e30f;
                        if (g + 1 > grow0 + 8) v1.y = -1e30f;
                    }
                    *(float2*)&fs[OS + r0 * SSTR + cb0] = v0;
                    *(float2*)&fs[OS + (r0 + 8) * SSTR + cb0] = v1;
                }
            }
        }
        __syncthreads();   // (B) scores visible; K buffer free

        if (more) {
            const __half* Kn = KB + (size_t)(k0 + FBK) * DD;
            #pragma unroll
            for (int p = 0; p < 8; p++) {
                int idx = tid + p * 256;
                int r = idx >> 5, cc = idx & 31;
                cp16(sb + (uint32_t)(OKo + r * QSTR + cc * 4) * 4, Kn + (size_t)r * DD + cc * 8);
            }
            CP_COMMIT();
        }

        // ---- online softmax: 4 threads/row, 16 cols each; P -> half ----
        {
            int row = tid >> 2, seg = tid & 3;
            float* Sr = &fs[OS + row * SSTR + seg * 16];
            float4 x0 = ((float4*)Sr)[0];
            float4 x1 = ((float4*)Sr)[1];
            float4 x2 = ((float4*)Sr)[2];
            float4 x3 = ((float4*)Sr)[3];
            float mx = fmaxf(fmaxf(fmaxf(x0.x, x0.y), fmaxf(x0.z, x0.w)),
                       fmaxf(fmaxf(fmaxf(x1.x, x1.y), fmaxf(x1.z, x1.w)),
                       fmaxf(fmaxf(fmaxf(x2.x, x2.y), fmaxf(x2.z, x2.w)),
                             fmaxf(fmaxf(x3.x, x3.y), fmaxf(x3.z, x3.w)))));
            mx = fmaxf(mx, __shfl_xor_sync(0xffffffff, mx, 1));
            mx = fmaxf(mx, __shfl_xor_sync(0xffffffff, mx, 2));
            float mold = fs[OM + row];
            float mnew = fmaxf(mold, mx);
            float alpha = __expf(mold - mnew);
            x0.x = __expf(x0.x - mnew); x0.y = __expf(x0.y - mnew);
            x0.z = __expf(x0.z - mnew); x0.w = __expf(x0.w - mnew);
            x1.x = __expf(x1.x - mnew); x1.y = __expf(x1.y - mnew);
            x1.z = __expf(x1.z - mnew); x1.w = __expf(x1.w - mnew);
            x2.x = __expf(x2.x - mnew); x2.y = __expf(x2.y - mnew);
            x2.z = __expf(x2.z - mnew); x2.w = __expf(x2.w - mnew);
            x3.x = __expf(x3.x - mnew); x3.y = __expf(x3.y - mnew);
            x3.z = __expf(x3.z - mnew); x3.w = __expf(x3.w - mnew);
            float sum = x0.x + x0.y + x0.z + x0.w + x1.x + x1.y + x1.z + x1.w
                      + x2.x + x2.y + x2.z + x2.w + x3.x + x3.y + x3.z + x3.w;
            uint32_t* Pr = &fsu[OP + row * PSTR + seg * 8];
            Pr[0] = packh2(x0.x, x0.y); Pr[1] = packh2(x0.z, x0.w);
            Pr[2] = packh2(x1.x, x1.y); Pr[3] = packh2(x1.z, x1.w);
            Pr[4] = packh2(x2.x, x2.y); Pr[5] = packh2(x2.z, x2.w);
            Pr[6] = packh2(x3.x, x3.y); Pr[7] = packh2(x3.z, x3.w);
            sum += __shfl_xor_sync(0xffffffff, sum, 1);
            sum += __shfl_xor_sync(0xffffffff, sum, 2);
            if (seg == 0) {
                fs[OL + row] = fs[OL + row] * alpha + sum;
                fs[OM + row] = mnew;
                fs[OA + row] = alpha;
            }
        }
        if (more) { CP_WAIT1(); } else { CP_WAIT0(); }
        __syncthreads();   // (C) P + alpha + V visible

        // ---- PV: warp (rg,h): O[32rg..+31][64h..+63] += P * V ----
        {
            float al[2][2];
            #pragma unroll
            for (int mt = 0; mt < 2; mt++) {
                al[mt][0] = fs[OA + 32 * rg + 16 * mt + lrow];
                al[mt][1] = fs[OA + 32 * rg + 16 * mt + lrow + 8];
            }
            #pragma unroll
            for (int mt = 0; mt < 2; mt++)
                #pragma unroll
                for (int nb = 0; nb < 8; nb++) {
                    ofrag[mt][nb][0] *= al[mt][0]; ofrag[mt][nb][1] *= al[mt][0];
                    ofrag[mt][nb][2] *= al[mt][1]; ofrag[mt][nb][3] *= al[mt][1];
                }
            #pragma unroll
            for (int kb = 0; kb < 4; kb++) {
                int kw = kb * 8 + lcol;
                uint32_t pa[2][4];
                #pragma unroll
                for (int mt = 0; mt < 2; mt++) {
                    int pr = 32 * rg + 16 * mt + lrow;
                    pa[mt][0] = fsu[OP + pr * PSTR + kw];
                    pa[mt][1] = fsu[OP + (pr + 8) * PSTR + kw];
                    pa[mt][2] = fsu[OP + pr * PSTR + kw + 4];
                    pa[mt][3] = fsu[OP + (pr + 8) * PSTR + kw + 4];
                }
                #pragma unroll
                for (int nb = 0; nb < 8; nb++) {
                    int ncol = 64 * h + 8 * nb + lrow;
                    uint32_t b2[2];
                    b2[0] = fsu[OVT + ncol * VTSTR + kw];
                    b2[1] = fsu[OVT + ncol * VTSTR + kw + 4];
                    mmah(ofrag[0][nb], pa[0], b2);
                    mmah(ofrag[1][nb], pa[1], b2);
                }
            }
        }
        __syncthreads();   // (D) V buffer free

        if (more) {
            const __half* Vn = VtB;
            int kn = k0 + FBK;
            #pragma unroll
            for (int p = 0; p < 8; p++) {
                int idx = tid + p * 256;
                int r = idx >> 3, cc = idx & 7;
                cp16(sb + (uint32_t)(OVT + r * VTSTR + cc * 4) * 4,
                     Vn + (size_t)r * SS + kn + cc * 8);
            }
            CP_COMMIT();
        }
    }

    // ---- epilogue (fp32 out) ----
    #pragma unroll
    for (int mt = 0; mt < 2; mt++) {
        int row = 32 * rg + 16 * mt + lrow;
        float inv0 = 1.0f / fs[OL + row];
        float inv8 = 1.0f / fs[OL + row + 8];
        float* Or0 = Og + ((size_t)b * SS + q0 + row) * DD;
        float* Or8 = Or0 + 8 * DD;
        #pragma unroll
        for (int nb = 0; nb < 8; nb++) {
            int col = 64 * h + 8 * nb + 2 * lcol;
            *(float2*)&Or0[col] = make_float2(ofrag[mt][nb][0] * inv0, ofrag[mt][nb][1] * inv0);
            *(float2*)&Or8[col] = make_float2(ofrag[mt][nb][2] * inv8, ofrag[mt][nb][3] * inv8);
        }
    }
}

// ============================================================
// fp16 HMMA GEMM: BM=128,BN=128,BK=32 halves, 3-stage cp.async.
// A half [M][K]; W pre-transposed half Wt[n][k].
// OUTF32: fp32 out; else omode 1 = half (scaled), 2 = half transposed [d][s].
// ============================================================
#define GEMM_H_WORDS 15360   // *4 = 61440 bytes; As[3]@s*2560, Wts[3]@7680+s*2560

template<int BIAS, int LEAKY, int OUTF32>
__device__ __forceinline__ void gemm_h_body(
    const __half* __restrict__ A, const __half* __restrict__ Wt,
    const float* __restrict__ bias, void* Cv,
    int N, int K, float oscale, int omode,
    uint32_t* su, uint32_t sb, int bx, int by) {
    int tid = threadIdx.x;
    int wid = tid >> 5, lane = tid & 31;
    int wm = wid & 3, wn = wid >> 2;
    int lrow = lane >> 2, lcol = lane & 3;
    int rb = by * 128, cb = bx * 128;

    float cfr[2][8][4];
    #pragma unroll
    for (int mt = 0; mt < 2; mt++)
        #pragma unroll
        for (int nb = 0; nb < 8; nb++)
            #pragma unroll
            for (int j = 0; j < 4; j++) cfr[mt][nb][j] = 0.0f;

    int NI = (K + 31) / 32;

    #define STAGEH(buf, k0s) do {                                                 \
        int _k0 = (k0s);                                                          \
        _Pragma("unroll")                                                         \
        for (int p = 0; p < 2; p++) {                                             \
            int idx = tid + p * 256;                                              \
            int r = idx >> 2, c = idx & 3;                                        \
            int col = _k0 + c * 8;                                                \
            bool ok = col < K;                                                    \
            const __half* src = A + (size_t)(rb + r) * K + (ok ? col : 0);        \
            cp16z(sb + (uint32_t)((buf) * 2560 + r * 20 + c * 4) * 4, src, ok);   \
        }                                                                         \
        _Pragma("unroll")                                                         \
        for (int p = 0; p < 2; p++) {                                             \
            int idx = tid + p * 256;                                              \
            int r = idx >> 2, c = idx & 3;                                        \
            int col = _k0 + c * 8;                                                \
            int nrow = cb + r;                                                    \
            bool ok = (col < K) && (nrow < N);                                    \
            const __half* src = Wt + (ok ? ((size_t)nrow * K + col) : 0);         \
            cp16z(sb + (uint32_t)(7680 + (buf) * 2560 + r * 20 + c * 4) * 4, src, ok); \
        }                                                                         \
    } while (0)

    STAGEH(0, 0);
    CP_COMMIT();
    if (NI > 1) { STAGEH(1, 32); }
    CP_COMMIT();
    if (NI > 2) { STAGEH(2, 64); }
    CP_COMMIT();

    for (int it = 0; it < NI; it++) {
        CP_WAIT2();
        __syncthreads();
        int s = it % 3;
        int Ab = s * 2560;
        int Wb = 7680 + s * 2560;
        #pragma unroll
        for (int kb = 0; kb < 2; kb++) {
            int kw = kb * 8 + lcol;
            uint32_t a[2][4];
            #pragma unroll
            for (int mt = 0; mt < 2; mt++) {
                int row = 32 * wm + 16 * mt + lrow;
                a[mt][0] = su[Ab + row * 20 + kw];
                a[mt][1] = su[Ab + (row + 8) * 20 + kw];
                a[mt][2] = su[Ab + row * 20 + kw + 4];
                a[mt][3] = su[Ab + (row + 8) * 20 + kw + 4];
            }
            #pragma unroll
            for (int nb = 0; nb < 8; nb++) {
                int ncol = 64 * wn + 8 * nb + lrow;
                uint32_t b2[2];
                b2[0] = su[Wb + ncol * 20 + kw];
                b2[1] = su[Wb + ncol * 20 + kw + 4];
                mmah(cfr[0][nb], a[0], b2);
                mmah(cfr[1][nb], a[1], b2);
            }
        }
        __syncthreads();
        if (it + 3 < NI) { STAGEH(s, (it + 3) * 32); CP_COMMIT(); }
    }
    #undef STAGEH

    // ---- epilogue ----
    #pragma unroll
    for (int mt = 0; mt < 2; mt++) {
        int r0 = rb + 32 * wm + 16 * mt + lrow;
        #pragma unroll
        for (int nb = 0; nb < 8; nb++) {
            int col = cb + 64 * wn + 8 * nb + 2 * lcol;
            if (col < N) {
                float v00 = cfr[mt][nb][0], v01 = cfr[mt][nb][1];
                float v10 = cfr[mt][nb][2], v11 = cfr[mt][nb][3];
                if (BIAS) {
                    float b0 = bias[col], b1 = bias[col + 1];
                    v00 += b0; v01 += b1; v10 += b0; v11 += b1;
                }
                if (LEAKY) {
                    v00 = (v00 > 0.0f) ? v00 : 0.2f * v00;
                    v01 = (v01 > 0.0f) ? v01 : 0.2f * v01;
                    v10 = (v10 > 0.0f) ? v10 : 0.2f * v10;
                    v11 = (v11 > 0.0f) ? v11 : 0.2f * v11;
                }
                if (OUTF32) {
                    float* C = (float*)Cv;
                    *(float2*)&C[(size_t)r0 * N + col] = make_float2(v00, v01);
                    *(float2*)&C[(size_t)(r0 + 8) * N + col] = make_float2(v10, v11);
                } else if (omode == 1) {
                    __half* C = (__half*)Cv;
                    __half2 h0 = __floats2half2_rn(v00 * oscale, v01 * oscale);
                    __half2 h1 = __floats2half2_rn(v10 * oscale, v11 * oscale);
                    *(__half2*)&C[(size_t)r0 * N + col] = h0;
                    *(__half2*)&C[(size_t)(r0 + 8) * N + col] = h1;
                } else {
                    // transposed half: Ct[b][d=col][s=r0]
                    __half* Ct = (__half*)Cv;
                    int bb = r0 >> 12, ss = r0 & 4095;
                    size_t base0 = ((size_t)(bb * DD + col)) * SS;
                    size_t base1 = ((size_t)(bb * DD + col + 1)) * SS;
                    Ct[base0 + ss]     = __float2half_rn(v00);
                    Ct[base1 + ss]     = __float2half_rn(v01);
                    Ct[base0 + ss + 8] = __float2half_rn(v10);
                    Ct[base1 + ss + 8] = __float2half_rn(v11);
                }
            }
        }
    }
}

template<int BIAS, int LEAKY, int OUTF32>
__global__ void __launch_bounds__(256, 2)
gemm_h(const __half* __restrict__ A, const __half* __restrict__ Wt,
       const float* __restrict__ bias, void* Cv,
       int N, int K, float oscale, int omode) {
    extern __shared__ float gs[];
    gemm_h_body<BIAS, LEAKY, OUTF32>(A, Wt, bias, Cv, N, K, oscale, omode,
                                     (uint32_t*)gs, smem_u32(gs), blockIdx.x, blockIdx.y);
}

// ---- batched 5-projection (one launch) ----
struct Proj5Args {
    const __half* A[5];
    const __half* W[5];
    void* C[5];
    float s[5];
    int mode[5];
};

__global__ void __launch_bounds__(256, 2)
proj5_h(Proj5Args pa) {
    extern __shared__ float gs[];
    int z = blockIdx.z;
    gemm_h_body<0, 0, 0>(pa.A[z], pa.W[z], nullptr, pa.C[z], DD, DD, pa.s[z], pa.mode[z],
                         (uint32_t*)gs, smem_u32(gs), blockIdx.x, blockIdx.y);
}

// ---- prep: convert inputs/ctx to half ----
__global__ void __launch_bounds__(256)
cvt2h(const float* __restrict__ a, const float* __restrict__ b,
      __half* __restrict__ ah, __half* __restrict__ bh, int n) {
    int i = (blockIdx.x * 256 + threadIdx.x) * 4;
    const float* s = blockIdx.y ? b : a;
    __half* d = blockIdx.y ? bh : ah;
    if (i < n) {
        float4 v = *(const float4*)(s + i);
        *(__half2*)(d + i)     = __floats2half2_rn(v.x, v.y);
        *(__half2*)(d + i + 2) = __floats2half2_rn(v.z, v.w);
    }
}

// ---- prep: transpose+round weights -> Wt[n][k] half ----
struct WT8 {
    const float* src[8];
    __half* dst[8];
    int K[8];
    int N[8];
};

__global__ void __launch_bounds__(256)
wtrans8(WT8 w) {
    int z = blockIdx.z;
    int K = w.K[z], N = w.N[z];
    int idx = blockIdx.x * 256 + threadIdx.x;
    if (idx < K * N) {
        int n = idx / K, k = idx - n * K;
        w.dst[z][idx] = __float2half_rn(w.src[z][(size_t)k * N + n]);
    }
}

// ============================================================
// out = LayerNorm(a + b), eps = 1e-3. Warp per row.
// Optionally writes half copy (rout) for downstream GEMM A.
// ============================================================
__global__ void __launch_bounds__(256)
add_ln_kernel(const float* __restrict__ a, const float* __restrict__ bvec,
              const float* __restrict__ gamma, const float* __restrict__ beta,
              float* __restrict__ out, __half* __restrict__ rout) {
    int wid = threadIdx.x >> 5, lane = threadIdx.x & 31;
    int row = blockIdx.x * 8 + wid;
    const float4* ar = (const float4*)(a + (size_t)row * DD);
    const float4* br = (const float4*)(bvec + (size_t)row * DD);
    float4 v0 = ar[lane];        float4 w0 = br[lane];
    float4 v1 = ar[lane + 32];   float4 w1 = br[lane + 32];
    v0.x += w0.x; v0.y += w0.y; v0.z += w0.z; v0.w += w0.w;
    v1.x += w1.x; v1.y += w1.y; v1.z += w1.z; v1.w += w1.w;

    float sum = v0.x + v0.y + v0.z + v0.w + v1.x + v1.y + v1.z + v1.w;
    #pragma unroll
    for (int off = 16; off > 0; off >>= 1) sum += __shfl_xor_sync(0xffffffff, sum, off);
    float mu = sum * (1.0f / DD);

    float sq = (v0.x - mu) * (v0.x - mu) + (v0.y - mu) * (v0.y - mu)
             + (v0.z - mu) * (v0.z - mu) + (v0.w - mu) * (v0.w - mu)
             + (v1.x - mu) * (v1.x - mu) + (v1.y - mu) * (v1.y - mu)
             + (v1.z - mu) * (v1.z - mu) + (v1.w - mu) * (v1.w - mu);
    #pragma unroll
    for (int off = 16; off > 0; off >>= 1) sq += __shfl_xor_sync(0xffffffff, sq, off);
    float rs = rsqrtf(sq * (1.0f / DD) + 1e-3f);

    const float4* g4 = (const float4*)gamma;
    const float4* b4 = (const float4*)beta;
    float4 g0 = g4[lane], g1 = g4[lane + 32];
    float4 e0 = b4[lane], e1 = b4[lane + 32];
    float4 o0, o1;
    o0.x = (v0.x - mu) * rs * g0.x + e0.x;
    o0.y = (v0.y - mu) * rs * g0.y + e0.y;
    o0.z = (v0.z - mu) * rs * g0.z + e0.z;
    o0.w = (v0.w - mu) * rs * g0.w + e0.w;
    o1.x = (v1.x - mu) * rs * g1.x + e1.x;
    o1.y = (v1.y - mu) * rs * g1.y + e1.y;
    o1.z = (v1.z - mu) * rs * g1.z + e1.z;
    o1.w = (v1.w - mu) * rs * g1.w + e1.w;
    float4* orow = (float4*)(out + (size_t)row * DD);
    orow[lane] = o0;
    orow[lane + 32] = o1;
    if (rout) {
        __half2* rrow = (__half2*)(rout + (size_t)row * DD);
        rrow[lane * 2]            = __floats2half2_rn(o0.x, o0.y);
        rrow[lane * 2 + 1]        = __floats2half2_rn(o0.z, o0.w);
        rrow[(lane + 32) * 2]     = __floats2half2_rn(o1.x, o1.y);
        rrow[(lane + 32) * 2 + 1] = __floats2half2_rn(o1.z, o1.w);
    }
}

// ============================================================
extern "C" void kernel_launch(void* const* d_in, const int* in_sizes, int n_in,
                              void* d_out, int out_size) {
    const float* inputs = (const float*)d_in[0];
    const float* ctx    = (const float*)d_in[1];
    const float* sa_Wk  = (const float*)d_in[2];
    const float* sa_Wv  = (const float*)d_in[3];
    const float* sa_Wq  = (const float*)d_in[4];
    const float* ca_Wk  = (const float*)d_in[5];
    const float* ca_Wv  = (const float*)d_in[6];
    const float* ca_Wq  = (const float*)d_in[7];
    const float* W1     = (const float*)d_in[8];
    const float* b1     = (const float*)d_in[9];
    const float* W2     = (const float*)d_in[10];
    const float* b2     = (const float*)d_in[11];
    const float* gamma  = (const float*)d_in[12];
    const float* beta   = (const float*)d_in[13];
    float* out = (float*)d_out;

    __half *Qh, *Kh, *Vth, *K2h, *V2th, *Ih, *Ch, *Xrh, *Yrh, *Hh, *WT;
    float *Tp, *Xp, *Yp;
    cudaGetSymbolAddress((void**)&Qh,  g_Qh);
    cudaGetSymbolAddress((void**)&Kh,  g_Kh);
    cudaGetSymbolAddress((void**)&Vth, g_Vth);
    cudaGetSymbolAddress((void**)&K2h, g_K2h);
    cudaGetSymbolAddress((void**)&V2th,g_V2th);
    cudaGetSymbolAddress((void**)&Ih,  g_Ih);
    cudaGetSymbolAddress((void**)&Ch,  g_Ch);
    cudaGetSymbolAddress((void**)&Xrh, g_Xrh);
    cudaGetSymbolAddress((void**)&Yrh, g_Yrh);
    cudaGetSymbolAddress((void**)&Hh,  g_Hh);
    cudaGetSymbolAddress((void**)&WT,  g_WTh);
    cudaGetSymbolAddress((void**)&Tp,  g_T);
    cudaGetSymbolAddress((void**)&Xp,  g_X);
    cudaGetSymbolAddress((void**)&Yp,  g_Y);

    __half* t_saWk = WT + 0;
    __half* t_saWv = WT + 65536;
    __half* t_saWq = WT + 131072;
    __half* t_caWk = WT + 196608;
    __half* t_caWv = WT + 262144;
    __half* t_caWq = WT + 327680;
    __half* t_W1   = WT + 393216;   // Wt[400][256]
    __half* t_W2   = WT + 495616;   // Wt[256][400]

    const int flash_smem = FL_WORDS * 4;
    const int gemm_smem = GEMM_H_WORDS * 4;
    cudaFuncSetAttribute(flash_h, cudaFuncAttributeMaxDynamicSharedMemorySize, flash_smem);
    cudaFuncSetAttribute(proj5_h, cudaFuncAttributeMaxDynamicSharedMemorySize, gemm_smem);
    cudaFuncSetAttribute(gemm_h<0, 0, 0>, cudaFuncAttributeMaxDynamicSharedMemorySize, gemm_smem);
    cudaFuncSetAttribute(gemm_h<1, 1, 0>, cudaFuncAttributeMaxDynamicSharedMemorySize, gemm_smem);
    cudaFuncSetAttribute(gemm_h<1, 0, 1>, cudaFuncAttributeMaxDynamicSharedMemorySize, gemm_smem);

    const float qs = 0.015625f;   // 1/sqrt(4096)

    // 0a) inputs/ctx -> half
    {
        dim3 cg((BSROWS * DD / 4 + 255) / 256, 2);
        cvt2h<<<cg, 256>>>(inputs, ctx, Ih, Ch, BSROWS * DD);
    }
    // 0b) weights -> transposed half
    {
        WT8 w;
        w.src[0] = sa_Wk; w.dst[0] = t_saWk; w.K[0] = DD; w.N[0] = DD;
        w.src[1] = sa_Wv; w.dst[1] = t_saWv; w.K[1] = DD; w.N[1] = DD;
        w.src[2] = sa_Wq; w.dst[2] = t_saWq; w.K[2] = DD; w.N[2] = DD;
        w.src[3] = ca_Wk; w.dst[3] = t_caWk; w.K[3] = DD; w.N[3] = DD;
        w.src[4] = ca_Wv; w.dst[4] = t_caWv; w.K[4] = DD; w.N[4] = DD;
        w.src[5] = ca_Wq; w.dst[5] = t_caWq; w.K[5] = DD; w.N[5] = DD;
        w.src[6] = W1;    w.dst[6] = t_W1;   w.K[6] = DD; w.N[6] = HH;  // Wt[400][256]
        w.src[7] = W2;    w.dst[7] = t_W2;   w.K[7] = HH; w.N[7] = DD;  // Wt[256][400]
        dim3 wg((DD * HH + 255) / 256, 1, 8);
        wtrans8<<<wg, 256>>>(w);
    }

    // 1) fused 5-projection batch
    {
        Proj5Args pa;
        pa.A[0] = Ih; pa.W[0] = t_saWk; pa.C[0] = Kh;   pa.s[0] = 1.0f; pa.mode[0] = 1;
        pa.A[1] = Ih; pa.W[1] = t_saWv; pa.C[1] = Vth;  pa.s[1] = 1.0f; pa.mode[1] = 2;
        pa.A[2] = Ih; pa.W[2] = t_saWq; pa.C[2] = Qh;   pa.s[2] = qs;   pa.mode[2] = 1;
        pa.A[3] = Ch; pa.W[3] = t_caWk; pa.C[3] = K2h;  pa.s[3] = 1.0f; pa.mode[3] = 1;
        pa.A[4] = Ch; pa.W[4] = t_caWv; pa.C[4] = V2th; pa.s[4] = 1.0f; pa.mode[4] = 2;
        dim3 pg(DD / 128, BSROWS / 128, 5);
        proj5_h<<<pg, 256, gemm_smem>>>(pa);
    }

    dim3 gD(DD / 128, BSROWS / 128);
    dim3 gH((HH + 127) / 128, BSROWS / 128);
    dim3 fg(SS / FBQ, BB);
    int lnB = BSROWS / 8;

    // 2) self-attention (causal) + LN1
    flash_h<<<fg, 256, flash_smem>>>(Qh, Kh, Vth, Tp, 1);
    add_ln_kernel<<<lnB, 256>>>(Tp, inputs, gamma, beta, Xp, Xrh);

    // 3) cross-attention + LN2
    gemm_h<0, 0, 0><<<gD, 256, gemm_smem>>>(Xrh, t_caWq, nullptr, Qh, DD, DD, qs, 1);
    flash_h<<<fg, 256, flash_smem>>>(Qh, K2h, V2th, Tp, 0);
    add_ln_kernel<<<lnB, 256>>>(Tp, Xp, gamma, beta, Yp, Yrh);

    // 4) FFN + LN3
    gemm_h<1, 1, 0><<<gH, 256, gemm_smem>>>(Yrh, t_W1, b1, Hh, HH, DD, 1.0f, 1);
    gemm_h<1, 0, 1><<<gD, 256, gemm_smem>>>(Hh, t_W2, b2, Tp, DD, HH, 1.0f, 1);
    add_ln_kernel<<<lnB, 256>>>(Tp, Yp, gamma, beta, out, nullptr);
}

// round 15
// speedup vs baseline: 2.5037x; 1.0569x over previous
#include <cuda_runtime.h>
#include <cuda_fp16.h>
#include <cstdint>
#include <math.h>

#define BB 4
#define SS 4096
#define DD 256
#define HH 400
#define BSROWS (BB*SS)

// ---- scratch ----
__device__ __half g_Qh[BSROWS*DD];
__device__ __half g_Kh[BSROWS*DD];
__device__ __half g_Vth[BB*DD*SS];     // [b][d][s]
__device__ __half g_K2h[BSROWS*DD];
__device__ __half g_V2th[BB*DD*SS];
__device__ __half g_Ih[BSROWS*DD];
__device__ __half g_Ch[BSROWS*DD];
__device__ __half g_Xrh[BSROWS*DD];
__device__ __half g_Yrh[BSROWS*DD];
__device__ __half g_Hh[BSROWS*HH];
__device__ __half g_WTh[598016];
__device__ float  g_T[BSROWS*DD];
__device__ float  g_X[BSROWS*DD];
__device__ float  g_Y[BSROWS*DD];

// ============================================================
// helpers
// ============================================================
__device__ __forceinline__ uint32_t smem_u32(const void* p) {
    uint32_t a;
    asm("{ .reg .u64 t; cvta.to.shared.u64 t, %1; cvt.u32.u64 %0, t; }" : "=r"(a) : "l"(p));
    return a;
}
__device__ __forceinline__ void mmah(float c[4], const uint32_t a[4], const uint32_t b[2]) {
    asm volatile(
        "mma.sync.aligned.m16n8k16.row.col.f32.f16.f16.f32 "
        "{%0,%1,%2,%3}, {%4,%5,%6,%7}, {%8,%9}, {%0,%1,%2,%3};"
        : "+f"(c[0]), "+f"(c[1]), "+f"(c[2]), "+f"(c[3])
        : "r"(a[0]), "r"(a[1]), "r"(a[2]), "r"(a[3]), "r"(b[0]), "r"(b[1]));
}
__device__ __forceinline__ uint32_t packh2(float lo, float hi) {
    __half2 h = __floats2half2_rn(lo, hi);
    return *(uint32_t*)&h;
}
__device__ __forceinline__ void cp16(uint32_t dst, const void* src) {
    asm volatile("cp.async.cg.shared.global [%0], [%1], 16;" :: "r"(dst), "l"(src));
}
__device__ __forceinline__ void cp16z(uint32_t dst, const void* src, bool ok) {
    int sz = ok ? 16 : 0;
    asm volatile("cp.async.cg.shared.global [%0], [%1], 16, %2;" :: "r"(dst), "l"(src), "r"(sz));
}
#define CP_COMMIT() asm volatile("cp.async.commit_group;" ::: "memory")
#define CP_WAIT0()  asm volatile("cp.async.wait_group 0;" ::: "memory")
#define CP_WAIT1()  asm volatile("cp.async.wait_group 1;" ::: "memory")
#define CP_WAIT2()  asm volatile("cp.async.wait_group 2;" ::: "memory")

// ============================================================
// Flash attention, fp16 HMMA m16n8k16, fp32 softmax/accum.
// FBQ=64, FBK=128 (halved chunk count, halved Q-redundancy/key).
// 8 warps = 2 row-groups x 4 col-quarters.
// Q/K half [s][d]; V half transposed [d][s]; P half in smem.
// SMEM 222.9 KB.
// ============================================================
#define FBQ 64
#define FBK 128
#define QSTR 132    // uint32 words per Q/K row (256 halves = 128 + 4 pad)
#define VTSTR 68    // words per Vt row (128 halves = 64 + 4 pad)
#define SSTR 132    // fp32 score row stride (128 + 4 pad)
#define PSTR 68     // words per P row (128 halves = 64 + 4 pad)
// word offsets in dynamic smem
#define OQ  0
#define OKo 8448
#define OVT 25344
#define OS  42752
#define OP  51200
#define OM  55552
#define OL  55616
#define OA  55680
#define FL_WORDS 55744          // *4 = 222976 bytes

__global__ void __launch_bounds__(256, 1)
flash_h(const __half* __restrict__ Qg, const __half* __restrict__ Kg,
        const __half* __restrict__ Vtg, float* __restrict__ Og, int causal) {
    extern __shared__ float fs[];
    uint32_t* fsu = (uint32_t*)fs;
    uint32_t sb = smem_u32(fs);
    int tid = threadIdx.x;
    int wid = tid >> 5, lane = tid & 31;
    int rg = wid & 1;          // rows 32*rg..+31
    int h  = wid >> 1;         // score cols 32h..+31 / O cols 64h..+63
    int lrow = lane >> 2;
    int lcol = lane & 3;
    int b = blockIdx.y;
    int qb = causal ? ((int)gridDim.x - 1 - (int)blockIdx.x) : (int)blockIdx.x;
    int q0 = qb * FBQ;
    int nc = causal ? ((q0 + FBQ + FBK - 1) / FBK) : (SS / FBK);

    const __half* QB  = Qg  + ((size_t)b * SS + q0) * DD;
    const __half* KB  = Kg  + (size_t)b * SS * DD;
    const __half* VtB = Vtg + (size_t)b * DD * SS;

    // ---- prologue: Q + K0 (group 1), V0 (group 2) ----
    {
        #pragma unroll
        for (int p = 0; p < 8; p++) {
            int idx = tid + p * 256;
            int r = idx >> 5, c = idx & 31;
            cp16(sb + (uint32_t)(OQ + r * QSTR + c * 4) * 4, QB + (size_t)r * DD + c * 8);
        }
        #pragma unroll
        for (int p = 0; p < 16; p++) {
            int idx = tid + p * 256;
            int r = idx >> 5, c = idx & 31;
            cp16(sb + (uint32_t)(OKo + r * QSTR + c * 4) * 4, KB + (size_t)r * DD + c * 8);
        }
        CP_COMMIT();
        #pragma unroll
        for (int p = 0; p < 16; p++) {
            int idx = tid + p * 256;
            int r = idx >> 4, c = idx & 15;
            cp16(sb + (uint32_t)(OVT + r * VTSTR + c * 4) * 4, VtB + (size_t)r * SS + c * 8);
        }
        CP_COMMIT();
    }
    if (tid < FBQ) { fs[OM + tid] = -INFINITY; fs[OL + tid] = 0.0f; }

    float ofrag[2][8][4];
    #pragma unroll
    for (int mt = 0; mt < 2; mt++)
        #pragma unroll
        for (int nb = 0; nb < 8; nb++)
            #pragma unroll
            for (int j = 0; j < 4; j++) ofrag[mt][nb][j] = 0.0f;

    for (int c = 0; c < nc; c++) {
        int k0 = c * FBK;
        bool maskc = causal && (k0 + FBK - 1 > q0);
        bool more = (c + 1) < nc;

        CP_WAIT1();
        __syncthreads();   // (A) K(c) (and Q on c==0) visible

        // ---- scores: warp (rg,h): S[32rg..+31][32h..+31] ----
        {
            float sfrag[2][4][4];
            #pragma unroll
            for (int mt = 0; mt < 2; mt++)
                #pragma unroll
                for (int nb = 0; nb < 4; nb++)
                    #pragma unroll
                    for (int j = 0; j < 4; j++) sfrag[mt][nb][j] = 0.0f;

            #pragma unroll 4
            for (int kb = 0; kb < 16; kb++) {
                int kw = kb * 8 + lcol;
                uint32_t a[2][4];
                #pragma unroll
                for (int mt = 0; mt < 2; mt++) {
                    int row = 32 * rg + 16 * mt + lrow;
                    a[mt][0] = fsu[OQ + row * QSTR + kw];
                    a[mt][1] = fsu[OQ + (row + 8) * QSTR + kw];
                    a[mt][2] = fsu[OQ + row * QSTR + kw + 4];
                    a[mt][3] = fsu[OQ + (row + 8) * QSTR + kw + 4];
                }
                #pragma unroll
                for (int nb = 0; nb < 4; nb++) {
                    int nrow = 32 * h + 8 * nb + lrow;
                    uint32_t b2[2];
                    b2[0] = fsu[OKo + nrow * QSTR + kw];
                    b2[1] = fsu[OKo + nrow * QSTR + kw + 4];
                    mmah(sfrag[0][nb], a[0], b2);
                    mmah(sfrag[1][nb], a[1], b2);
                }
            }
            #pragma unroll
            for (int mt = 0; mt < 2; mt++) {
                int r0 = 32 * rg + 16 * mt + lrow;
                int grow0 = q0 + r0;
                #pragma unroll
                for (int nb = 0; nb < 4; nb++) {
                    int cb0 = 32 * h + 8 * nb + 2 * lcol;
                    float2 v0 = make_float2(sfrag[mt][nb][0], sfrag[mt][nb][1]);
                    float2 v1 = make_float2(sfrag[mt][nb][2], sfrag[mt][nb][3]);
                    if (maskc) {
                        int g = k0 + cb0;
                        if (g > grow0)         v0.x = -1e30f;
                        if (g + 1 > grow0)     v0.y = -1e30f;
                        if (g > grow0 + 8)     v1.x = -1e30f;
                        if (g + 1 > grow0 + 8) v1.y = -1e30f;
                    }
                    *(float2*)&fs[OS + r0 * SSTR + cb0] = v0;
                    *(float2*)&fs[OS + (r0 + 8) * SSTR + cb0] = v1;
                }
            }
        }
        __syncthreads();   // (B) scores visible; K buffer free

        // ---- early-issue K(c+1) ----
        if (more) {
            const __half* Kn = KB + (size_t)(k0 + FBK) * DD;
            #pragma unroll
            for (int p = 0; p < 16; p++) {
                int idx = tid + p * 256;
                int r = idx >> 5, cc = idx & 31;
                cp16(sb + (uint32_t)(OKo + r * QSTR + cc * 4) * 4, Kn + (size_t)r * DD + cc * 8);
            }
            CP_COMMIT();
        }

        // ---- online softmax: 4 threads/row, 32 cols each; P -> half ----
        {
            int row = tid >> 2, seg = tid & 3;
            float* Sr = &fs[OS + row * SSTR + seg * 32];
            float4 x[8];
            #pragma unroll
            for (int i = 0; i < 8; i++) x[i] = ((float4*)Sr)[i];
            float mx = -INFINITY;
            #pragma unroll
            for (int i = 0; i < 8; i++)
                mx = fmaxf(mx, fmaxf(fmaxf(x[i].x, x[i].y), fmaxf(x[i].z, x[i].w)));
            mx = fmaxf(mx, __shfl_xor_sync(0xffffffff, mx, 1));
            mx = fmaxf(mx, __shfl_xor_sync(0xffffffff, mx, 2));
            float mold = fs[OM + row];
            float mnew = fmaxf(mold, mx);
            float alpha = __expf(mold - mnew);
            float sum = 0.0f;
            uint32_t* Pr = &fsu[OP + row * PSTR + seg * 16];
            #pragma unroll
            for (int i = 0; i < 8; i++) {
                x[i].x = __expf(x[i].x - mnew); x[i].y = __expf(x[i].y - mnew);
                x[i].z = __expf(x[i].z - mnew); x[i].w = __expf(x[i].w - mnew);
                sum += x[i].x + x[i].y + x[i].z + x[i].w;
                Pr[2 * i]     = packh2(x[i].x, x[i].y);
                Pr[2 * i + 1] = packh2(x[i].z, x[i].w);
            }
            sum += __shfl_xor_sync(0xffffffff, sum, 1);
            sum += __shfl_xor_sync(0xffffffff, sum, 2);
            if (seg == 0) {
                fs[OL + row] = fs[OL + row] * alpha + sum;
                fs[OM + row] = mnew;
                fs[OA + row] = alpha;
            }
        }
        if (more) { CP_WAIT1(); } else { CP_WAIT0(); }
        __syncthreads();   // (C) P + alpha + V visible

        // ---- PV: warp (rg,h): O[32rg..+31][64h..+63] += P * V ----
        {
            float al[2][2];
            #pragma unroll
            for (int mt = 0; mt < 2; mt++) {
                al[mt][0] = fs[OA + 32 * rg + 16 * mt + lrow];
                al[mt][1] = fs[OA + 32 * rg + 16 * mt + lrow + 8];
            }
            #pragma unroll
            for (int mt = 0; mt < 2; mt++)
                #pragma unroll
                for (int nb = 0; nb < 8; nb++) {
                    ofrag[mt][nb][0] *= al[mt][0]; ofrag[mt][nb][1] *= al[mt][0];
                    ofrag[mt][nb][2] *= al[mt][1]; ofrag[mt][nb][3] *= al[mt][1];
                }
            #pragma unroll
            for (int kb = 0; kb < 8; kb++) {
                int kw = kb * 8 + lcol;
                uint32_t pa[2][4];
                #pragma unroll
                for (int mt = 0; mt < 2; mt++) {
                    int pr = 32 * rg + 16 * mt + lrow;
                    pa[mt][0] = fsu[OP + pr * PSTR + kw];
                    pa[mt][1] = fsu[OP + (pr + 8) * PSTR + kw];
                    pa[mt][2] = fsu[OP + pr * PSTR + kw + 4];
                    pa[mt][3] = fsu[OP + (pr + 8) * PSTR + kw + 4];
                }
                #pragma unroll
                for (int nb = 0; nb < 8; nb++) {
                    int ncol = 64 * h + 8 * nb + lrow;
                    uint32_t b2[2];
                    b2[0] = fsu[OVT + ncol * VTSTR + kw];
                    b2[1] = fsu[OVT + ncol * VTSTR + kw + 4];
                    mmah(ofrag[0][nb], pa[0], b2);
                    mmah(ofrag[1][nb], pa[1], b2);
                }
            }
        }
        __syncthreads();   // (D) V buffer free

        if (more) {
            int kn = k0 + FBK;
            #pragma unroll
            for (int p = 0; p < 16; p++) {
                int idx = tid + p * 256;
                int r = idx >> 4, cc = idx & 15;
                cp16(sb + (uint32_t)(OVT + r * VTSTR + cc * 4) * 4,
                     VtB + (size_t)r * SS + kn + cc * 8);
            }
            CP_COMMIT();
        }
    }

    // ---- epilogue (fp32 out) ----
    #pragma unroll
    for (int mt = 0; mt < 2; mt++) {
        int row = 32 * rg + 16 * mt + lrow;
        float inv0 = 1.0f / fs[OL + row];
        float inv8 = 1.0f / fs[OL + row + 8];
        float* Or0 = Og + ((size_t)b * SS + q0 + row) * DD;
        float* Or8 = Or0 + 8 * DD;
        #pragma unroll
        for (int nb = 0; nb < 8; nb++) {
            int col = 64 * h + 8 * nb + 2 * lcol;
            *(float2*)&Or0[col] = make_float2(ofrag[mt][nb][0] * inv0, ofrag[mt][nb][1] * inv0);
            *(float2*)&Or8[col] = make_float2(ofrag[mt][nb][2] * inv8, ofrag[mt][nb][3] * inv8);
        }
    }
}

// ============================================================
// fp16 HMMA GEMM (R14, unchanged): BM=128,BN=128,BK=32 halves,
// 3-stage cp.async. A half [M][K]; W pre-transposed half Wt[n][k].
// ============================================================
#define GEMM_H_WORDS 15360

template<int BIAS, int LEAKY, int OUTF32>
__device__ __forceinline__ void gemm_h_body(
    const __half* __restrict__ A, const __half* __restrict__ Wt,
    const float* __restrict__ bias, void* Cv,
    int N, int K, float oscale, int omode,
    uint32_t* su, uint32_t sb, int bx, int by) {
    int tid = threadIdx.x;
    int wid = tid >> 5, lane = tid & 31;
    int wm = wid & 3, wn = wid >> 2;
    int lrow = lane >> 2, lcol = lane & 3;
    int rb = by * 128, cb = bx * 128;

    float cfr[2][8][4];
    #pragma unroll
    for (int mt = 0; mt < 2; mt++)
        #pragma unroll
        for (int nb = 0; nb < 8; nb++)
            #pragma unroll
            for (int j = 0; j < 4; j++) cfr[mt][nb][j] = 0.0f;

    int NI = (K + 31) / 32;

    #define STAGEH(buf, k0s) do {                                                 \
        int _k0 = (k0s);                                                          \
        _Pragma("unroll")                                                         \
        for (int p = 0; p < 2; p++) {                                             \
            int idx = tid + p * 256;                                              \
            int r = idx >> 2, c = idx & 3;                                        \
            int col = _k0 + c * 8;                                                \
            bool ok = col < K;                                                    \
            const __half* src = A + (size_t)(rb + r) * K + (ok ? col : 0);        \
            cp16z(sb + (uint32_t)((buf) * 2560 + r * 20 + c * 4) * 4, src, ok);   \
        }                                                                         \
        _Pragma("unroll")                                                         \
        for (int p = 0; p < 2; p++) {                                             \
            int idx = tid + p * 256;                                              \
            int r = idx >> 2, c = idx & 3;                                        \
            int col = _k0 + c * 8;                                                \
            int nrow = cb + r;                                                    \
            bool ok = (col < K) && (nrow < N);                                    \
            const __half* src = Wt + (ok ? ((size_t)nrow * K + col) : 0);         \
            cp16z(sb + (uint32_t)(7680 + (buf) * 2560 + r * 20 + c * 4) * 4, src, ok); \
        }                                                                         \
    } while (0)

    STAGEH(0, 0);
    CP_COMMIT();
    if (NI > 1) { STAGEH(1, 32); }
    CP_COMMIT();
    if (NI > 2) { STAGEH(2, 64); }
    CP_COMMIT();

    for (int it = 0; it < NI; it++) {
        CP_WAIT2();
        __syncthreads();
        int s = it % 3;
        int Ab = s * 2560;
        int Wb = 7680 + s * 2560;
        #pragma unroll
        for (int kb = 0; kb < 2; kb++) {
            int kw = kb * 8 + lcol;
            uint32_t a[2][4];
            #pragma unroll
            for (int mt = 0; mt < 2; mt++) {
                int row = 32 * wm + 16 * mt + lrow;
                a[mt][0] = su[Ab + row * 20 + kw];
                a[mt][1] = su[Ab + (row + 8) * 20 + kw];
                a[mt][2] = su[Ab + row * 20 + kw + 4];
                a[mt][3] = su[Ab + (row + 8) * 20 + kw + 4];
            }
            #pragma unroll
            for (int nb = 0; nb < 8; nb++) {
                int ncol = 64 * wn + 8 * nb + lrow;
                uint32_t b2[2];
                b2[0] = su[Wb + ncol * 20 + kw];
                b2[1] = su[Wb + ncol * 20 + kw + 4];
                mmah(cfr[0][nb], a[0], b2);
                mmah(cfr[1][nb], a[1], b2);
            }
        }
        __syncthreads();
        if (it + 3 < NI) { STAGEH(s, (it + 3) * 32); CP_COMMIT(); }
    }
    #undef STAGEH

    #pragma unroll
    for (int mt = 0; mt < 2; mt++) {
        int r0 = rb + 32 * wm + 16 * mt + lrow;
        #pragma unroll
        for (int nb = 0; nb < 8; nb++) {
            int col = cb + 64 * wn + 8 * nb + 2 * lcol;
            if (col < N) {
                float v00 = cfr[mt][nb][0], v01 = cfr[mt][nb][1];
                float v10 = cfr[mt][nb][2], v11 = cfr[mt][nb][3];
                if (BIAS) {
                    float b0 = bias[col], b1 = bias[col + 1];
                    v00 += b0; v01 += b1; v10 += b0; v11 += b1;
                }
                if (LEAKY) {
                    v00 = (v00 > 0.0f) ? v00 : 0.2f * v00;
                    v01 = (v01 > 0.0f) ? v01 : 0.2f * v01;
                    v10 = (v10 > 0.0f) ? v10 : 0.2f * v10;
                    v11 = (v11 > 0.0f) ? v11 : 0.2f * v11;
                }
                if (OUTF32) {
                    float* C = (float*)Cv;
                    *(float2*)&C[(size_t)r0 * N + col] = make_float2(v00, v01);
                    *(float2*)&C[(size_t)(r0 + 8) * N + col] = make_float2(v10, v11);
                } else if (omode == 1) {
                    __half* C = (__half*)Cv;
                    __half2 h0 = __floats2half2_rn(v00 * oscale, v01 * oscale);
                    __half2 h1 = __floats2half2_rn(v10 * oscale, v11 * oscale);
                    *(__half2*)&C[(size_t)r0 * N + col] = h0;
                    *(__half2*)&C[(size_t)(r0 + 8) * N + col] = h1;
                } else {
                    __half* Ct = (__half*)Cv;
                    int bb = r0 >> 12, ss = r0 & 4095;
                    size_t base0 = ((size_t)(bb * DD + col)) * SS;
                    size_t base1 = ((size_t)(bb * DD + col + 1)) * SS;
                    Ct[base0 + ss]     = __float2half_rn(v00);
                    Ct[base1 + ss]     = __float2half_rn(v01);
                    Ct[base0 + ss + 8] = __float2half_rn(v10);
                    Ct[base1 + ss + 8] = __float2half_rn(v11);
                }
            }
        }
    }
}

template<int BIAS, int LEAKY, int OUTF32>
__global__ void __launch_bounds__(256, 2)
gemm_h(const __half* __restrict__ A, const __half* __restrict__ Wt,
       const float* __restrict__ bias, void* Cv,
       int N, int K, float oscale, int omode) {
    extern __shared__ float gs[];
    gemm_h_body<BIAS, LEAKY, OUTF32>(A, Wt, bias, Cv, N, K, oscale, omode,
                                     (uint32_t*)gs, smem_u32(gs), blockIdx.x, blockIdx.y);
}

struct Proj5Args {
    const __half* A[5];
    const __half* W[5];
    void* C[5];
    float s[5];
    int mode[5];
};

__global__ void __launch_bounds__(256, 2)
proj5_h(Proj5Args pa) {
    extern __shared__ float gs[];
    int z = blockIdx.z;
    gemm_h_body<0, 0, 0>(pa.A[z], pa.W[z], nullptr, pa.C[z], DD, DD, pa.s[z], pa.mode[z],
                         (uint32_t*)gs, smem_u32(gs), blockIdx.x, blockIdx.y);
}

__global__ void __launch_bounds__(256)
cvt2h(const float* __restrict__ a, const float* __restrict__ b,
      __half* __restrict__ ah, __half* __restrict__ bh, int n) {
    int i = (blockIdx.x * 256 + threadIdx.x) * 4;
    const float* s = blockIdx.y ? b : a;
    __half* d = blockIdx.y ? bh : ah;
    if (i < n) {
        float4 v = *(const float4*)(s + i);
        *(__half2*)(d + i)     = __floats2half2_rn(v.x, v.y);
        *(__half2*)(d + i + 2) = __floats2half2_rn(v.z, v.w);
    }
}

struct WT8 {
    const float* src[8];
    __half* dst[8];
    int K[8];
    int N[8];
};

__global__ void __launch_bounds__(256)
wtrans8(WT8 w) {
    int z = blockIdx.z;
    int K = w.K[z], N = w.N[z];
    int idx = blockIdx.x * 256 + threadIdx.x;
    if (idx < K * N) {
        int n = idx / K, k = idx - n * K;
        w.dst[z][idx] = __float2half_rn(w.src[z][(size_t)k * N + n]);
    }
}

// ============================================================
// out = LayerNorm(a + b), eps = 1e-3. Warp per row. Optional half copy.
// ============================================================
__global__ void __launch_bounds__(256)
add_ln_kernel(const float* __restrict__ a, const float* __restrict__ bvec,
              const float* __restrict__ gamma, const float* __restrict__ beta,
              float* __restrict__ out, __half* __restrict__ rout) {
    int wid = threadIdx.x >> 5, lane = threadIdx.x & 31;
    int row = blockIdx.x * 8 + wid;
    const float4* ar = (const float4*)(a + (size_t)row * DD);
    const float4* br = (const float4*)(bvec + (size_t)row * DD);
    float4 v0 = ar[lane];        float4 w0 = br[lane];
    float4 v1 = ar[lane + 32];   float4 w1 = br[lane + 32];
    v0.x += w0.x; v0.y += w0.y; v0.z += w0.z; v0.w += w0.w;
    v1.x += w1.x; v1.y += w1.y; v1.z += w1.z; v1.w += w1.w;

    float sum = v0.x + v0.y + v0.z + v0.w + v1.x + v1.y + v1.z + v1.w;
    #pragma unroll
    for (int off = 16; off > 0; off >>= 1) sum += __shfl_xor_sync(0xffffffff, sum, off);
    float mu = sum * (1.0f / DD);

    float sq = (v0.x - mu) * (v0.x - mu) + (v0.y - mu) * (v0.y - mu)
             + (v0.z - mu) * (v0.z - mu) + (v0.w - mu) * (v0.w - mu)
             + (v1.x - mu) * (v1.x - mu) + (v1.y - mu) * (v1.y - mu)
             + (v1.z - mu) * (v1.z - mu) + (v1.w - mu) * (v1.w - mu);
    #pragma unroll
    for (int off = 16; off > 0; off >>= 1) sq += __shfl_xor_sync(0xffffffff, sq, off);
    float rs = rsqrtf(sq * (1.0f / DD) + 1e-3f);

    const float4* g4 = (const float4*)gamma;
    const float4* b4 = (const float4*)beta;
    float4 g0 = g4[lane], g1 = g4[lane + 32];
    float4 e0 = b4[lane], e1 = b4[lane + 32];
    float4 o0, o1;
    o0.x = (v0.x - mu) * rs * g0.x + e0.x;
    o0.y = (v0.y - mu) * rs * g0.y + e0.y;
    o0.z = (v0.z - mu) * rs * g0.z + e0.z;
    o0.w = (v0.w - mu) * rs * g0.w + e0.w;
    o1.x = (v1.x - mu) * rs * g1.x + e1.x;
    o1.y = (v1.y - mu) * rs * g1.y + e1.y;
    o1.z = (v1.z - mu) * rs * g1.z + e1.z;
    o1.w = (v1.w - mu) * rs * g1.w + e1.w;
    float4* orow = (float4*)(out + (size_t)row * DD);
    orow[lane] = o0;
    orow[lane + 32] = o1;
    if (rout) {
        __half2* rrow = (__half2*)(rout + (size_t)row * DD);
        rrow[lane * 2]            = __floats2half2_rn(o0.x, o0.y);
        rrow[lane * 2 + 1]        = __floats2half2_rn(o0.z, o0.w);
        rrow[(lane + 32) * 2]     = __floats2half2_rn(o1.x, o1.y);
        rrow[(lane + 32) * 2 + 1] = __floats2half2_rn(o1.z, o1.w);
    }
}

// ============================================================
extern "C" void kernel_launch(void* const* d_in, const int* in_sizes, int n_in,
                              void* d_out, int out_size) {
    const float* inputs = (const float*)d_in[0];
    const float* ctx    = (const float*)d_in[1];
    const float* sa_Wk  = (const float*)d_in[2];
    const float* sa_Wv  = (const float*)d_in[3];
    const float* sa_Wq  = (const float*)d_in[4];
    const float* ca_Wk  = (const float*)d_in[5];
    const float* ca_Wv  = (const float*)d_in[6];
    const float* ca_Wq  = (const float*)d_in[7];
    const float* W1     = (const float*)d_in[8];
    const float* b1     = (const float*)d_in[9];
    const float* W2     = (const float*)d_in[10];
    const float* b2     = (const float*)d_in[11];
    const float* gamma  = (const float*)d_in[12];
    const float* beta   = (const float*)d_in[13];
    float* out = (float*)d_out;

    __half *Qh, *Kh, *Vth, *K2h, *V2th, *Ih, *Ch, *Xrh, *Yrh, *Hh, *WT;
    float *Tp, *Xp, *Yp;
    cudaGetSymbolAddress((void**)&Qh,  g_Qh);
    cudaGetSymbolAddress((void**)&Kh,  g_Kh);
    cudaGetSymbolAddress((void**)&Vth, g_Vth);
    cudaGetSymbolAddress((void**)&K2h, g_K2h);
    cudaGetSymbolAddress((void**)&V2th,g_V2th);
    cudaGetSymbolAddress((void**)&Ih,  g_Ih);
    cudaGetSymbolAddress((void**)&Ch,  g_Ch);
    cudaGetSymbolAddress((void**)&Xrh, g_Xrh);
    cudaGetSymbolAddress((void**)&Yrh, g_Yrh);
    cudaGetSymbolAddress((void**)&Hh,  g_Hh);
    cudaGetSymbolAddress((void**)&WT,  g_WTh);
    cudaGetSymbolAddress((void**)&Tp,  g_T);
    cudaGetSymbolAddress((void**)&Xp,  g_X);
    cudaGetSymbolAddress((void**)&Yp,  g_Y);

    __half* t_saWk = WT + 0;
    __half* t_saWv = WT + 65536;
    __half* t_saWq = WT + 131072;
    __half* t_caWk = WT + 196608;
    __half* t_caWv = WT + 262144;
    __half* t_caWq = WT + 327680;
    __half* t_W1   = WT + 393216;
    __half* t_W2   = WT + 495616;

    const int flash_smem = FL_WORDS * 4;
    const int gemm_smem = GEMM_H_WORDS * 4;
    cudaFuncSetAttribute(flash_h, cudaFuncAttributeMaxDynamicSharedMemorySize, flash_smem);
    cudaFuncSetAttribute(proj5_h, cudaFuncAttributeMaxDynamicSharedMemorySize, gemm_smem);
    cudaFuncSetAttribute(gemm_h<0, 0, 0>, cudaFuncAttributeMaxDynamicSharedMemorySize, gemm_smem);
    cudaFuncSetAttribute(gemm_h<1, 1, 0>, cudaFuncAttributeMaxDynamicSharedMemorySize, gemm_smem);
    cudaFuncSetAttribute(gemm_h<1, 0, 1>, cudaFuncAttributeMaxDynamicSharedMemorySize, gemm_smem);

    const float qs = 0.015625f;   // 1/sqrt(4096)

    // 0a) inputs/ctx -> half
    {
        dim3 cg((BSROWS * DD / 4 + 255) / 256, 2);
        cvt2h<<<cg, 256>>>(inputs, ctx, Ih, Ch, BSROWS * DD);
    }
    // 0b) weights -> transposed half
    {
        WT8 w;
        w.src[0] = sa_Wk; w.dst[0] = t_saWk; w.K[0] = DD; w.N[0] = DD;
        w.src[1] = sa_Wv; w.dst[1] = t_saWv; w.K[1] = DD; w.N[1] = DD;
        w.src[2] = sa_Wq; w.dst[2] = t_saWq; w.K[2] = DD; w.N[2] = DD;
        w.src[3] = ca_Wk; w.dst[3] = t_caWk; w.K[3] = DD; w.N[3] = DD;
        w.src[4] = ca_Wv; w.dst[4] = t_caWv; w.K[4] = DD; w.N[4] = DD;
        w.src[5] = ca_Wq; w.dst[5] = t_caWq; w.K[5] = DD; w.N[5] = DD;
        w.src[6] = W1;    w.dst[6] = t_W1;   w.K[6] = DD; w.N[6] = HH;
        w.src[7] = W2;    w.dst[7] = t_W2;   w.K[7] = HH; w.N[7] = DD;
        dim3 wg((DD * HH + 255) / 256, 1, 8);
        wtrans8<<<wg, 256>>>(w);
    }

    // 1) fused 5-projection batch
    {
        Proj5Args pa;
        pa.A[0] = Ih; pa.W[0] = t_saWk; pa.C[0] = Kh;   pa.s[0] = 1.0f; pa.mode[0] = 1;
        pa.A[1] = Ih; pa.W[1] = t_saWv; pa.C[1] = Vth;  pa.s[1] = 1.0f; pa.mode[1] = 2;
        pa.A[2] = Ih; pa.W[2] = t_saWq; pa.C[2] = Qh;   pa.s[2] = qs;   pa.mode[2] = 1;
        pa.A[3] = Ch; pa.W[3] = t_caWk; pa.C[3] = K2h;  pa.s[3] = 1.0f; pa.mode[3] = 1;
        pa.A[4] = Ch; pa.W[4] = t_caWv; pa.C[4] = V2th; pa.s[4] = 1.0f; pa.mode[4] = 2;
        dim3 pg(DD / 128, BSROWS / 128, 5);
        proj5_h<<<pg, 256, gemm_smem>>>(pa);
    }

    dim3 gD(DD / 128, BSROWS / 128);
    dim3 gH((HH + 127) / 128, BSROWS / 128);
    dim3 fg(SS / FBQ, BB);
    int lnB = BSROWS / 8;

    // 2) self-attention (causal) + LN1
    flash_h<<<fg, 256, flash_smem>>>(Qh, Kh, Vth, Tp, 1);
    add_ln_kernel<<<lnB, 256>>>(Tp, inputs, gamma, beta, Xp, Xrh);

    // 3) cross-attention + LN2
    gemm_h<0, 0, 0><<<gD, 256, gemm_smem>>>(Xrh, t_caWq, nullptr, Qh, DD, DD, qs, 1);
    flash_h<<<fg, 256, flash_smem>>>(Qh, K2h, V2th, Tp, 0);
    add_ln_kernel<<<lnB, 256>>>(Tp, Xp, gamma, beta, Yp, Yrh);

    // 4) FFN + LN3
    gemm_h<1, 1, 0><<<gH, 256, gemm_smem>>>(Yrh, t_W1, b1, Hh, HH, DD, 1.0f, 1);
    gemm_h<1, 0, 1><<<gD, 256, gemm_smem>>>(Hh, t_W2, b2, Tp, DD, HH, 1.0f, 1);
    add_ln_kernel<<<lnB, 256>>>(Tp, Yp, gamma, beta, out, nullptr);
}

// round 16
// speedup vs baseline: 2.7388x; 1.0939x over previous
#include <cuda_runtime.h>
#include <cuda_fp16.h>
#include <cstdint>
#include <math.h>

#define BB 4
#define SS 4096
#define DD 256
#define HH 400
#define BSROWS (BB*SS)

// ---- scratch ----
__device__ __half g_Qh[BSROWS*DD];
__device__ __half g_Kh[BSROWS*DD];
__device__ __half g_Vth[BB*DD*SS];     // [b][d][s]
__device__ __half g_K2h[BSROWS*DD];
__device__ __half g_V2th[BB*DD*SS];
__device__ __half g_Ih[BSROWS*DD];
__device__ __half g_Ch[BSROWS*DD];
__device__ __half g_Xrh[BSROWS*DD];
__device__ __half g_Yrh[BSROWS*DD];
__device__ __half g_Hh[BSROWS*HH];
__device__ __half g_WTh[598016];
__device__ float  g_T[BSROWS*DD];
__device__ float  g_X[BSROWS*DD];
__device__ float  g_Y[BSROWS*DD];

// ============================================================
// helpers
// ============================================================
__device__ __forceinline__ uint32_t smem_u32(const void* p) {
    uint32_t a;
    asm("{ .reg .u64 t; cvta.to.shared.u64 t, %1; cvt.u32.u64 %0, t; }" : "=r"(a) : "l"(p));
    return a;
}
__device__ __forceinline__ void mmah(float c[4], const uint32_t a[4], const uint32_t b[2]) {
    asm volatile(
        "mma.sync.aligned.m16n8k16.row.col.f32.f16.f16.f32 "
        "{%0,%1,%2,%3}, {%4,%5,%6,%7}, {%8,%9}, {%0,%1,%2,%3};"
        : "+f"(c[0]), "+f"(c[1]), "+f"(c[2]), "+f"(c[3])
        : "r"(a[0]), "r"(a[1]), "r"(a[2]), "r"(a[3]), "r"(b[0]), "r"(b[1]));
}
__device__ __forceinline__ uint32_t packh2(float lo, float hi) {
    __half2 h = __floats2half2_rn(lo, hi);
    return *(uint32_t*)&h;
}
__device__ __forceinline__ void cp16(uint32_t dst, const void* src) {
    asm volatile("cp.async.cg.shared.global [%0], [%1], 16;" :: "r"(dst), "l"(src));
}
__device__ __forceinline__ void cp16z(uint32_t dst, const void* src, bool ok) {
    int sz = ok ? 16 : 0;
    asm volatile("cp.async.cg.shared.global [%0], [%1], 16, %2;" :: "r"(dst), "l"(src), "r"(sz));
}
#define CP_COMMIT() asm volatile("cp.async.commit_group;" ::: "memory")
#define CP_WAIT0()  asm volatile("cp.async.wait_group 0;" ::: "memory")
#define CP_WAIT1()  asm volatile("cp.async.wait_group 1;" ::: "memory")
#define CP_WAIT2()  asm volatile("cp.async.wait_group 2;" ::: "memory")

// ============================================================
// Flash attention, fp16 HMMA, FBQ=64 / FBK=128, fused add+LN epilogue.
// Grid: 1D 256 blocks; causal uses global LPT ordering.
// ============================================================
#define FBQ 64
#define FBK 128
#define QSTR 132
#define VTSTR 68
#define SSTR 132
#define PSTR 68
#define OQ  0
#define OKo 8448
#define OVT 25344
#define OS  42752
#define OP  51200
#define OM  55552
#define OL  55616
#define OA  55680
#define FL_WORDS 55744          // *4 = 222976 bytes

__global__ void __launch_bounds__(256, 1)
flash_h(const __half* __restrict__ Qg, const __half* __restrict__ Kg,
        const __half* __restrict__ Vtg, const float* __restrict__ resid,
        const float* __restrict__ gamma, const float* __restrict__ beta,
        float* __restrict__ outF, __half* __restrict__ outH, int causal) {
    extern __shared__ float fs[];
    uint32_t* fsu = (uint32_t*)fs;
    uint32_t sb = smem_u32(fs);
    int tid = threadIdx.x;
    int wid = tid >> 5, lane = tid & 31;
    int rg = wid & 1;          // rows 32*rg..+31
    int h  = wid >> 1;         // score cols 32h..+31 / O cols 64h..+63
    int lrow = lane >> 2;
    int lcol = lane & 3;
    int bx = blockIdx.x;
    int b = bx & 3;
    int qb = causal ? ((SS / FBQ) - 1 - (bx >> 2)) : (bx >> 2);   // global LPT
    int q0 = qb * FBQ;
    int nc = causal ? ((q0 + FBQ + FBK - 1) / FBK) : (SS / FBK);

    const __half* QB  = Qg  + ((size_t)b * SS + q0) * DD;
    const __half* KB  = Kg  + (size_t)b * SS * DD;
    const __half* VtB = Vtg + (size_t)b * DD * SS;

    // ---- prologue: Q + K0 (group 1), V0 (group 2) ----
    {
        #pragma unroll
        for (int p = 0; p < 8; p++) {
            int idx = tid + p * 256;
            int r = idx >> 5, c = idx & 31;
            cp16(sb + (uint32_t)(OQ + r * QSTR + c * 4) * 4, QB + (size_t)r * DD + c * 8);
        }
        #pragma unroll
        for (int p = 0; p < 16; p++) {
            int idx = tid + p * 256;
            int r = idx >> 5, c = idx & 31;
            cp16(sb + (uint32_t)(OKo + r * QSTR + c * 4) * 4, KB + (size_t)r * DD + c * 8);
        }
        CP_COMMIT();
        #pragma unroll
        for (int p = 0; p < 16; p++) {
            int idx = tid + p * 256;
            int r = idx >> 4, c = idx & 15;
            cp16(sb + (uint32_t)(OVT + r * VTSTR + c * 4) * 4, VtB + (size_t)r * SS + c * 8);
        }
        CP_COMMIT();
    }
    if (tid < FBQ) { fs[OM + tid] = -INFINITY; fs[OL + tid] = 0.0f; }

    float ofrag[2][8][4];
    #pragma unroll
    for (int mt = 0; mt < 2; mt++)
        #pragma unroll
        for (int nb = 0; nb < 8; nb++)
            #pragma unroll
            for (int j = 0; j < 4; j++) ofrag[mt][nb][j] = 0.0f;

    for (int c = 0; c < nc; c++) {
        int k0 = c * FBK;
        bool maskc = causal && (k0 + FBK - 1 > q0);
        bool more = (c + 1) < nc;

        CP_WAIT1();
        __syncthreads();   // (A)

        // ---- scores ----
        {
            float sfrag[2][4][4];
            #pragma unroll
            for (int mt = 0; mt < 2; mt++)
                #pragma unroll
                for (int nb = 0; nb < 4; nb++)
                    #pragma unroll
                    for (int j = 0; j < 4; j++) sfrag[mt][nb][j] = 0.0f;

            #pragma unroll 4
            for (int kb = 0; kb < 16; kb++) {
                int kw = kb * 8 + lcol;
                uint32_t a[2][4];
                #pragma unroll
                for (int mt = 0; mt < 2; mt++) {
                    int row = 32 * rg + 16 * mt + lrow;
                    a[mt][0] = fsu[OQ + row * QSTR + kw];
                    a[mt][1] = fsu[OQ + (row + 8) * QSTR + kw];
                    a[mt][2] = fsu[OQ + row * QSTR + kw + 4];
                    a[mt][3] = fsu[OQ + (row + 8) * QSTR + kw + 4];
                }
                #pragma unroll
                for (int nb = 0; nb < 4; nb++) {
                    int nrow = 32 * h + 8 * nb + lrow;
                    uint32_t b2[2];
                    b2[0] = fsu[OKo + nrow * QSTR + kw];
                    b2[1] = fsu[OKo + nrow * QSTR + kw + 4];
                    mmah(sfrag[0][nb], a[0], b2);
                    mmah(sfrag[1][nb], a[1], b2);
                }
            }
            #pragma unroll
            for (int mt = 0; mt < 2; mt++) {
                int r0 = 32 * rg + 16 * mt + lrow;
                int grow0 = q0 + r0;
                #pragma unroll
                for (int nb = 0; nb < 4; nb++) {
                    int cb0 = 32 * h + 8 * nb + 2 * lcol;
                    float2 v0 = make_float2(sfrag[mt][nb][0], sfrag[mt][nb][1]);
                    float2 v1 = make_float2(sfrag[mt][nb][2], sfrag[mt][nb][3]);
                    if (maskc) {
                        int g = k0 + cb0;
                        if (g > grow0)         v0.x = -1e30f;
                        if (g + 1 > grow0)     v0.y = -1e30f;
                        if (g > grow0 + 8)     v1.x = -1e30f;
                        if (g + 1 > grow0 + 8) v1.y = -1e30f;
                    }
                    *(float2*)&fs[OS + r0 * SSTR + cb0] = v0;
                    *(float2*)&fs[OS + (r0 + 8) * SSTR + cb0] = v1;
                }
            }
        }
        __syncthreads();   // (B)

        if (more) {
            const __half* Kn = KB + (size_t)(k0 + FBK) * DD;
            #pragma unroll
            for (int p = 0; p < 16; p++) {
                int idx = tid + p * 256;
                int r = idx >> 5, cc = idx & 31;
                cp16(sb + (uint32_t)(OKo + r * QSTR + cc * 4) * 4, Kn + (size_t)r * DD + cc * 8);
            }
            CP_COMMIT();
        }

        // ---- online softmax ----
        {
            int row = tid >> 2, seg = tid & 3;
            float* Sr = &fs[OS + row * SSTR + seg * 32];
            float4 x[8];
            #pragma unroll
            for (int i = 0; i < 8; i++) x[i] = ((float4*)Sr)[i];
            float mx = -INFINITY;
            #pragma unroll
            for (int i = 0; i < 8; i++)
                mx = fmaxf(mx, fmaxf(fmaxf(x[i].x, x[i].y), fmaxf(x[i].z, x[i].w)));
            mx = fmaxf(mx, __shfl_xor_sync(0xffffffff, mx, 1));
            mx = fmaxf(mx, __shfl_xor_sync(0xffffffff, mx, 2));
            float mold = fs[OM + row];
            float mnew = fmaxf(mold, mx);
            float alpha = __expf(mold - mnew);
            float sum = 0.0f;
            uint32_t* Pr = &fsu[OP + row * PSTR + seg * 16];
            #pragma unroll
            for (int i = 0; i < 8; i++) {
                x[i].x = __expf(x[i].x - mnew); x[i].y = __expf(x[i].y - mnew);
                x[i].z = __expf(x[i].z - mnew); x[i].w = __expf(x[i].w - mnew);
                sum += x[i].x + x[i].y + x[i].z + x[i].w;
                Pr[2 * i]     = packh2(x[i].x, x[i].y);
                Pr[2 * i + 1] = packh2(x[i].z, x[i].w);
            }
            sum += __shfl_xor_sync(0xffffffff, sum, 1);
            sum += __shfl_xor_sync(0xffffffff, sum, 2);
            if (seg == 0) {
                fs[OL + row] = fs[OL + row] * alpha + sum;
                fs[OM + row] = mnew;
                fs[OA + row] = alpha;
            }
        }
        if (more) { CP_WAIT1(); } else { CP_WAIT0(); }
        __syncthreads();   // (C)

        // ---- PV ----
        {
            float al[2][2];
            #pragma unroll
            for (int mt = 0; mt < 2; mt++) {
                al[mt][0] = fs[OA + 32 * rg + 16 * mt + lrow];
                al[mt][1] = fs[OA + 32 * rg + 16 * mt + lrow + 8];
            }
            #pragma unroll
            for (int mt = 0; mt < 2; mt++)
                #pragma unroll
                for (int nb = 0; nb < 8; nb++) {
                    ofrag[mt][nb][0] *= al[mt][0]; ofrag[mt][nb][1] *= al[mt][0];
                    ofrag[mt][nb][2] *= al[mt][1]; ofrag[mt][nb][3] *= al[mt][1];
                }
            #pragma unroll
            for (int kb = 0; kb < 8; kb++) {
                int kw = kb * 8 + lcol;
                uint32_t pa[2][4];
                #pragma unroll
                for (int mt = 0; mt < 2; mt++) {
                    int pr = 32 * rg + 16 * mt + lrow;
                    pa[mt][0] = fsu[OP + pr * PSTR + kw];
                    pa[mt][1] = fsu[OP + (pr + 8) * PSTR + kw];
                    pa[mt][2] = fsu[OP + pr * PSTR + kw + 4];
                    pa[mt][3] = fsu[OP + (pr + 8) * PSTR + kw + 4];
                }
                #pragma unroll
                for (int nb = 0; nb < 8; nb++) {
                    int ncol = 64 * h + 8 * nb + lrow;
                    uint32_t b2[2];
                    b2[0] = fsu[OVT + ncol * VTSTR + kw];
                    b2[1] = fsu[OVT + ncol * VTSTR + kw + 4];
                    mmah(ofrag[0][nb], pa[0], b2);
                    mmah(ofrag[1][nb], pa[1], b2);
                }
            }
        }
        __syncthreads();   // (D) V + P regions free

        if (more) {
            int kn = k0 + FBK;
            #pragma unroll
            for (int p = 0; p < 16; p++) {
                int idx = tid + p * 256;
                int r = idx >> 4, cc = idx & 15;
                cp16(sb + (uint32_t)(OVT + r * VTSTR + cc * 4) * 4,
                     VtB + (size_t)r * SS + kn + cc * 8);
            }
            CP_COMMIT();
        }
    }

    // ============================================================
    // fused epilogue: v = O/l + resid ; LayerNorm(v) -> outF (f32) + outH (half)
    // row sums via P-region scratch (free after (D)).
    // ============================================================
    {
        // v into ofrag
        #pragma unroll
        for (int mt = 0; mt < 2; mt++) {
            int row = 32 * rg + 16 * mt + lrow;
            float inv0 = 1.0f / fs[OL + row];
            float inv8 = 1.0f / fs[OL + row + 8];
            const float* R0 = resid + ((size_t)b * SS + q0 + row) * DD;
            const float* R8 = R0 + 8 * DD;
            #pragma unroll
            for (int nb = 0; nb < 8; nb++) {
                int col = 64 * h + 8 * nb + 2 * lcol;
                float2 r0 = *(const float2*)&R0[col];
                float2 r8 = *(const float2*)&R8[col];
                ofrag[mt][nb][0] = ofrag[mt][nb][0] * inv0 + r0.x;
                ofrag[mt][nb][1] = ofrag[mt][nb][1] * inv0 + r0.y;
                ofrag[mt][nb][2] = ofrag[mt][nb][2] * inv8 + r8.x;
                ofrag[mt][nb][3] = ofrag[mt][nb][3] * inv8 + r8.y;
            }
        }
        // pass 1: mean
        float s1[2][2] = {{0.f, 0.f}, {0.f, 0.f}};
        #pragma unroll
        for (int mt = 0; mt < 2; mt++)
            #pragma unroll
            for (int nb = 0; nb < 8; nb++) {
                s1[mt][0] += ofrag[mt][nb][0] + ofrag[mt][nb][1];
                s1[mt][1] += ofrag[mt][nb][2] + ofrag[mt][nb][3];
            }
        #pragma unroll
        for (int mt = 0; mt < 2; mt++)
            #pragma unroll
            for (int hh = 0; hh < 2; hh++) {
                s1[mt][hh] += __shfl_xor_sync(0xffffffff, s1[mt][hh], 1);
                s1[mt][hh] += __shfl_xor_sync(0xffffffff, s1[mt][hh], 2);
            }
        if (lcol == 0) {
            #pragma unroll
            for (int mt = 0; mt < 2; mt++)
                #pragma unroll
                for (int hh = 0; hh < 2; hh++) {
                    int row = 32 * rg + 16 * mt + 8 * hh + lrow;
                    fs[OP + row * 4 + h] = s1[mt][hh];
                }
        }
        __syncthreads();
        float mu[2][2];
        #pragma unroll
        for (int mt = 0; mt < 2; mt++)
            #pragma unroll
            for (int hh = 0; hh < 2; hh++) {
                int row = 32 * rg + 16 * mt + 8 * hh + lrow;
                mu[mt][hh] = (fs[OP + row * 4] + fs[OP + row * 4 + 1] +
                              fs[OP + row * 4 + 2] + fs[OP + row * 4 + 3]) * (1.0f / DD);
            }
        // pass 2: variance
        float s2[2][2] = {{0.f, 0.f}, {0.f, 0.f}};
        #pragma unroll
        for (int mt = 0; mt < 2; mt++)
            #pragma unroll
            for (int nb = 0; nb < 8; nb++) {
                float d0 = ofrag[mt][nb][0] - mu[mt][0];
                float d1 = ofrag[mt][nb][1] - mu[mt][0];
                float d2 = ofrag[mt][nb][2] - mu[mt][1];
                float d3 = ofrag[mt][nb][3] - mu[mt][1];
                s2[mt][0] += d0 * d0 + d1 * d1;
                s2[mt][1] += d2 * d2 + d3 * d3;
            }
        #pragma unroll
        for (int mt = 0; mt < 2; mt++)
            #pragma unroll
            for (int hh = 0; hh < 2; hh++) {
                s2[mt][hh] += __shfl_xor_sync(0xffffffff, s2[mt][hh], 1);
                s2[mt][hh] += __shfl_xor_sync(0xffffffff, s2[mt][hh], 2);
            }
        if (lcol == 0) {
            #pragma unroll
            for (int mt = 0; mt < 2; mt++)
                #pragma unroll
                for (int hh = 0; hh < 2; hh++) {
                    int row = 32 * rg + 16 * mt + 8 * hh + lrow;
                    fs[OP + 1024 + row * 4 + h] = s2[mt][hh];
                }
        }
        __syncthreads();
        float rs[2][2];
        #pragma unroll
        for (int mt = 0; mt < 2; mt++)
            #pragma unroll
            for (int hh = 0; hh < 2; hh++) {
                int row = 32 * rg + 16 * mt + 8 * hh + lrow;
                float var = (fs[OP + 1024 + row * 4] + fs[OP + 1024 + row * 4 + 1] +
                             fs[OP + 1024 + row * 4 + 2] + fs[OP + 1024 + row * 4 + 3]) * (1.0f / DD);
                rs[mt][hh] = rsqrtf(var + 1e-3f);
            }
        // write normalized outputs
        #pragma unroll
        for (int mt = 0; mt < 2; mt++) {
            int row = 32 * rg + 16 * mt + lrow;
            float* F0 = outF + ((size_t)b * SS + q0 + row) * DD;
            float* F8 = F0 + 8 * DD;
            __half* H0 = outH + ((size_t)b * SS + q0 + row) * DD;
            __half* H8 = H0 + 8 * DD;
            #pragma unroll
            for (int nb = 0; nb < 8; nb++) {
                int col = 64 * h + 8 * nb + 2 * lcol;
                float2 g = *(const float2*)&gamma[col];
                float2 e = *(const float2*)&beta[col];
                float o0 = (ofrag[mt][nb][0] - mu[mt][0]) * rs[mt][0] * g.x + e.x;
                float o1 = (ofrag[mt][nb][1] - mu[mt][0]) * rs[mt][0] * g.y + e.y;
                float o2 = (ofrag[mt][nb][2] - mu[mt][1]) * rs[mt][1] * g.x + e.x;
                float o3 = (ofrag[mt][nb][3] - mu[mt][1]) * rs[mt][1] * g.y + e.y;
                *(float2*)&F0[col] = make_float2(o0, o1);
                *(float2*)&F8[col] = make_float2(o2, o3);
                *(__half2*)&H0[col] = __floats2half2_rn(o0, o1);
                *(__half2*)&H8[col] = __floats2half2_rn(o2, o3);
            }
        }
    }
}

// ============================================================
// fp16 HMMA GEMM (unchanged from R15)
// ============================================================
#define GEMM_H_WORDS 15360

template<int BIAS, int LEAKY, int OUTF32>
__device__ __forceinline__ void gemm_h_body(
    const __half* __restrict__ A, const __half* __restrict__ Wt,
    const float* __restrict__ bias, void* Cv,
    int N, int K, float oscale, int omode,
    uint32_t* su, uint32_t sb, int bx, int by) {
    int tid = threadIdx.x;
    int wid = tid >> 5, lane = tid & 31;
    int wm = wid & 3, wn = wid >> 2;
    int lrow = lane >> 2, lcol = lane & 3;
    int rb = by * 128, cb = bx * 128;

    float cfr[2][8][4];
    #pragma unroll
    for (int mt = 0; mt < 2; mt++)
        #pragma unroll
        for (int nb = 0; nb < 8; nb++)
            #pragma unroll
            for (int j = 0; j < 4; j++) cfr[mt][nb][j] = 0.0f;

    int NI = (K + 31) / 32;

    #define STAGEH(buf, k0s) do {                                                 \
        int _k0 = (k0s);                                                          \
        _Pragma("unroll")                                                         \
        for (int p = 0; p < 2; p++) {                                             \
            int idx = tid + p * 256;                                              \
            int r = idx >> 2, c = idx & 3;                                        \
            int col = _k0 + c * 8;                                                \
            bool ok = col < K;                                                    \
            const __half* src = A + (size_t)(rb + r) * K + (ok ? col : 0);        \
            cp16z(sb + (uint32_t)((buf) * 2560 + r * 20 + c * 4) * 4, src, ok);   \
        }                                                                         \
        _Pragma("unroll")                                                         \
        for (int p = 0; p < 2; p++) {                                             \
            int idx = tid + p * 256;                                              \
            int r = idx >> 2, c = idx & 3;                                        \
            int col = _k0 + c * 8;                                                \
            int nrow = cb + r;                                                    \
            bool ok = (col < K) && (nrow < N);                                    \
            const __half* src = Wt + (ok ? ((size_t)nrow * K + col) : 0);         \
            cp16z(sb + (uint32_t)(7680 + (buf) * 2560 + r * 20 + c * 4) * 4, src, ok); \
        }                                                                         \
    } while (0)

    STAGEH(0, 0);
    CP_COMMIT();
    if (NI > 1) { STAGEH(1, 32); }
    CP_COMMIT();
    if (NI > 2) { STAGEH(2, 64); }
    CP_COMMIT();

    for (int it = 0; it < NI; it++) {
        CP_WAIT2();
        __syncthreads();
        int s = it % 3;
        int Ab = s * 2560;
        int Wb = 7680 + s * 2560;
        #pragma unroll
        for (int kb = 0; kb < 2; kb++) {
            int kw = kb * 8 + lcol;
            uint32_t a[2][4];
            #pragma unroll
            for (int mt = 0; mt < 2; mt++) {
                int row = 32 * wm + 16 * mt + lrow;
                a[mt][0] = su[Ab + row * 20 + kw];
                a[mt][1] = su[Ab + (row + 8) * 20 + kw];
                a[mt][2] = su[Ab + row * 20 + kw + 4];
                a[mt][3] = su[Ab + (row + 8) * 20 + kw + 4];
            }
            #pragma unroll
            for (int nb = 0; nb < 8; nb++) {
                int ncol = 64 * wn + 8 * nb + lrow;
                uint32_t b2[2];
                b2[0] = su[Wb + ncol * 20 + kw];
                b2[1] = su[Wb + ncol * 20 + kw + 4];
                mmah(cfr[0][nb], a[0], b2);
                mmah(cfr[1][nb], a[1], b2);
            }
        }
        __syncthreads();
        if (it + 3 < NI) { STAGEH(s, (it + 3) * 32); CP_COMMIT(); }
    }
    #undef STAGEH

    #pragma unroll
    for (int mt = 0; mt < 2; mt++) {
        int r0 = rb + 32 * wm + 16 * mt + lrow;
        #pragma unroll
        for (int nb = 0; nb < 8; nb++) {
            int col = cb + 64 * wn + 8 * nb + 2 * lcol;
            if (col < N) {
                float v00 = cfr[mt][nb][0], v01 = cfr[mt][nb][1];
                float v10 = cfr[mt][nb][2], v11 = cfr[mt][nb][3];
                if (BIAS) {
                    float b0 = bias[col], b1 = bias[col + 1];
                    v00 += b0; v01 += b1; v10 += b0; v11 += b1;
                }
                if (LEAKY) {
                    v00 = (v00 > 0.0f) ? v00 : 0.2f * v00;
                    v01 = (v01 > 0.0f) ? v01 : 0.2f * v01;
                    v10 = (v10 > 0.0f) ? v10 : 0.2f * v10;
                    v11 = (v11 > 0.0f) ? v11 : 0.2f * v11;
                }
                if (OUTF32) {
                    float* C = (float*)Cv;
                    *(float2*)&C[(size_t)r0 * N + col] = make_float2(v00, v01);
                    *(float2*)&C[(size_t)(r0 + 8) * N + col] = make_float2(v10, v11);
                } else if (omode == 1) {
                    __half* C = (__half*)Cv;
                    __half2 h0 = __floats2half2_rn(v00 * oscale, v01 * oscale);
                    __half2 h1 = __floats2half2_rn(v10 * oscale, v11 * oscale);
                    *(__half2*)&C[(size_t)r0 * N + col] = h0;
                    *(__half2*)&C[(size_t)(r0 + 8) * N + col] = h1;
                } else {
                    __half* Ct = (__half*)Cv;
                    int bb = r0 >> 12, ss = r0 & 4095;
                    size_t base0 = ((size_t)(bb * DD + col)) * SS;
                    size_t base1 = ((size_t)(bb * DD + col + 1)) * SS;
                    Ct[base0 + ss]     = __float2half_rn(v00);
                    Ct[base1 + ss]     = __float2half_rn(v01);
                    Ct[base0 + ss + 8] = __float2half_rn(v10);
                    Ct[base1 + ss + 8] = __float2half_rn(v11);
                }
            }
        }
    }
}

template<int BIAS, int LEAKY, int OUTF32>
__global__ void __launch_bounds__(256, 2)
gemm_h(const __half* __restrict__ A, const __half* __restrict__ Wt,
       const float* __restrict__ bias, void* Cv,
       int N, int K, float oscale, int omode) {
    extern __shared__ float gs[];
    gemm_h_body<BIAS, LEAKY, OUTF32>(A, Wt, bias, Cv, N, K, oscale, omode,
                                     (uint32_t*)gs, smem_u32(gs), blockIdx.x, blockIdx.y);
}

struct Proj5Args {
    const __half* A[5];
    const __half* W[5];
    void* C[5];
    float s[5];
    int mode[5];
};

__global__ void __launch_bounds__(256, 2)
proj5_h(Proj5Args pa) {
    extern __shared__ float gs[];
    int z = blockIdx.z;
    gemm_h_body<0, 0, 0>(pa.A[z], pa.W[z], nullptr, pa.C[z], DD, DD, pa.s[z], pa.mode[z],
                         (uint32_t*)gs, smem_u32(gs), blockIdx.x, blockIdx.y);
}

__global__ void __launch_bounds__(256)
cvt2h(const float* __restrict__ a, const float* __restrict__ b,
      __half* __restrict__ ah, __half* __restrict__ bh, int n) {
    int i = (blockIdx.x * 256 + threadIdx.x) * 4;
    const float* s = blockIdx.y ? b : a;
    __half* d = blockIdx.y ? bh : ah;
    if (i < n) {
        float4 v = *(const float4*)(s + i);
        *(__half2*)(d + i)     = __floats2half2_rn(v.x, v.y);
        *(__half2*)(d + i + 2) = __floats2half2_rn(v.z, v.w);
    }
}

struct WT8 {
    const float* src[8];
    __half* dst[8];
    int K[8];
    int N[8];
};

__global__ void __launch_bounds__(256)
wtrans8(WT8 w) {
    int z = blockIdx.z;
    int K = w.K[z], N = w.N[z];
    int idx = blockIdx.x * 256 + threadIdx.x;
    if (idx < K * N) {
        int n = idx / K, k = idx - n * K;
        w.dst[z][idx] = __float2half_rn(w.src[z][(size_t)k * N + n]);
    }
}

// ============================================================
// standalone add+LN (used only for final LN3)
// ============================================================
__global__ void __launch_bounds__(256)
add_ln_kernel(const float* __restrict__ a, const float* __restrict__ bvec,
              const float* __restrict__ gamma, const float* __restrict__ beta,
              float* __restrict__ out) {
    int wid = threadIdx.x >> 5, lane = threadIdx.x & 31;
    int row = blockIdx.x * 8 + wid;
    const float4* ar = (const float4*)(a + (size_t)row * DD);
    const float4* br = (const float4*)(bvec + (size_t)row * DD);
    float4 v0 = ar[lane];        float4 w0 = br[lane];
    float4 v1 = ar[lane + 32];   float4 w1 = br[lane + 32];
    v0.x += w0.x; v0.y += w0.y; v0.z += w0.z; v0.w += w0.w;
    v1.x += w1.x; v1.y += w1.y; v1.z += w1.z; v1.w += w1.w;

    float sum = v0.x + v0.y + v0.z + v0.w + v1.x + v1.y + v1.z + v1.w;
    #pragma unroll
    for (int off = 16; off > 0; off >>= 1) sum += __shfl_xor_sync(0xffffffff, sum, off);
    float mu = sum * (1.0f / DD);

    float sq = (v0.x - mu) * (v0.x - mu) + (v0.y - mu) * (v0.y - mu)
             + (v0.z - mu) * (v0.z - mu) + (v0.w - mu) * (v0.w - mu)
             + (v1.x - mu) * (v1.x - mu) + (v1.y - mu) * (v1.y - mu)
             + (v1.z - mu) * (v1.z - mu) + (v1.w - mu) * (v1.w - mu);
    #pragma unroll
    for (int off = 16; off > 0; off >>= 1) sq += __shfl_xor_sync(0xffffffff, sq, off);
    float rs = rsqrtf(sq * (1.0f / DD) + 1e-3f);

    const float4* g4 = (const float4*)gamma;
    const float4* b4 = (const float4*)beta;
    float4 g0 = g4[lane], g1 = g4[lane + 32];
    float4 e0 = b4[lane], e1 = b4[lane + 32];
    float4 o0, o1;
    o0.x = (v0.x - mu) * rs * g0.x + e0.x;
    o0.y = (v0.y - mu) * rs * g0.y + e0.y;
    o0.z = (v0.z - mu) * rs * g0.z + e0.z;
    o0.w = (v0.w - mu) * rs * g0.w + e0.w;
    o1.x = (v1.x - mu) * rs * g1.x + e1.x;
    o1.y = (v1.y - mu) * rs * g1.y + e1.y;
    o1.z = (v1.z - mu) * rs * g1.z + e1.z;
    o1.w = (v1.w - mu) * rs * g1.w + e1.w;
    float4* orow = (float4*)(out + (size_t)row * DD);
    orow[lane] = o0;
    orow[lane + 32] = o1;
}

// ============================================================
extern "C" void kernel_launch(void* const* d_in, const int* in_sizes, int n_in,
                              void* d_out, int out_size) {
    const float* inputs = (const float*)d_in[0];
    const float* ctx    = (const float*)d_in[1];
    const float* sa_Wk  = (const float*)d_in[2];
    const float* sa_Wv  = (const float*)d_in[3];
    const float* sa_Wq  = (const float*)d_in[4];
    const float* ca_Wk  = (const float*)d_in[5];
    const float* ca_Wv  = (const float*)d_in[6];
    const float* ca_Wq  = (const float*)d_in[7];
    const float* W1     = (const float*)d_in[8];
    const float* b1     = (const float*)d_in[9];
    const float* W2     = (const float*)d_in[10];
    const float* b2     = (const float*)d_in[11];
    const float* gamma  = (const float*)d_in[12];
    const float* beta   = (const float*)d_in[13];
    float* out = (float*)d_out;

    __half *Qh, *Kh, *Vth, *K2h, *V2th, *Ih, *Ch, *Xrh, *Yrh, *Hh, *WT;
    float *Tp, *Xp, *Yp;
    cudaGetSymbolAddress((void**)&Qh,  g_Qh);
    cudaGetSymbolAddress((void**)&Kh,  g_Kh);
    cudaGetSymbolAddress((void**)&Vth, g_Vth);
    cudaGetSymbolAddress((void**)&K2h, g_K2h);
    cudaGetSymbolAddress((void**)&V2th,g_V2th);
    cudaGetSymbolAddress((void**)&Ih,  g_Ih);
    cudaGetSymbolAddress((void**)&Ch,  g_Ch);
    cudaGetSymbolAddress((void**)&Xrh, g_Xrh);
    cudaGetSymbolAddress((void**)&Yrh, g_Yrh);
    cudaGetSymbolAddress((void**)&Hh,  g_Hh);
    cudaGetSymbolAddress((void**)&WT,  g_WTh);
    cudaGetSymbolAddress((void**)&Tp,  g_T);
    cudaGetSymbolAddress((void**)&Xp,  g_X);
    cudaGetSymbolAddress((void**)&Yp,  g_Y);

    __half* t_saWk = WT + 0;
    __half* t_saWv = WT + 65536;
    __half* t_saWq = WT + 131072;
    __half* t_caWk = WT + 196608;
    __half* t_caWv = WT + 262144;
    __half* t_caWq = WT + 327680;
    __half* t_W1   = WT + 393216;
    __half* t_W2   = WT + 495616;

    const int flash_smem = FL_WORDS * 4;
    const int gemm_smem = GEMM_H_WORDS * 4;
    cudaFuncSetAttribute(flash_h, cudaFuncAttributeMaxDynamicSharedMemorySize, flash_smem);
    cudaFuncSetAttribute(proj5_h, cudaFuncAttributeMaxDynamicSharedMemorySize, gemm_smem);
    cudaFuncSetAttribute(gemm_h<0, 0, 0>, cudaFuncAttributeMaxDynamicSharedMemorySize, gemm_smem);
    cudaFuncSetAttribute(gemm_h<1, 1, 0>, cudaFuncAttributeMaxDynamicSharedMemorySize, gemm_smem);
    cudaFuncSetAttribute(gemm_h<1, 0, 1>, cudaFuncAttributeMaxDynamicSharedMemorySize, gemm_smem);

    const float qs = 0.015625f;   // 1/sqrt(4096)

    // 0a) inputs/ctx -> half
    {
        dim3 cg((BSROWS * DD / 4 + 255) / 256, 2);
        cvt2h<<<cg, 256>>>(inputs, ctx, Ih, Ch, BSROWS * DD);
    }
    // 0b) weights -> transposed half
    {
        WT8 w;
        w.src[0] = sa_Wk; w.dst[0] = t_saWk; w.K[0] = DD; w.N[0] = DD;
        w.src[1] = sa_Wv; w.dst[1] = t_saWv; w.K[1] = DD; w.N[1] = DD;
        w.src[2] = sa_Wq; w.dst[2] = t_saWq; w.K[2] = DD; w.N[2] = DD;
        w.src[3] = ca_Wk; w.dst[3] = t_caWk; w.K[3] = DD; w.N[3] = DD;
        w.src[4] = ca_Wv; w.dst[4] = t_caWv; w.K[4] = DD; w.N[4] = DD;
        w.src[5] = ca_Wq; w.dst[5] = t_caWq; w.K[5] = DD; w.N[5] = DD;
        w.src[6] = W1;    w.dst[6] = t_W1;   w.K[6] = DD; w.N[6] = HH;
        w.src[7] = W2;    w.dst[7] = t_W2;   w.K[7] = HH; w.N[7] = DD;
        dim3 wg((DD * HH + 255) / 256, 1, 8);
        wtrans8<<<wg, 256>>>(w);
    }

    // 1) fused 5-projection batch
    {
        Proj5Args pa;
        pa.A[0] = Ih; pa.W[0] = t_saWk; pa.C[0] = Kh;   pa.s[0] = 1.0f; pa.mode[0] = 1;
        pa.A[1] = Ih; pa.W[1] = t_saWv; pa.C[1] = Vth;  pa.s[1] = 1.0f; pa.mode[1] = 2;
        pa.A[2] = Ih; pa.W[2] = t_saWq; pa.C[2] = Qh;   pa.s[2] = qs;   pa.mode[2] = 1;
        pa.A[3] = Ch; pa.W[3] = t_caWk; pa.C[3] = K2h;  pa.s[3] = 1.0f; pa.mode[3] = 1;
        pa.A[4] = Ch; pa.W[4] = t_caWv; pa.C[4] = V2th; pa.s[4] = 1.0f; pa.mode[4] = 2;
        dim3 pg(DD / 128, BSROWS / 128, 5);
        proj5_h<<<pg, 256, gemm_smem>>>(pa);
    }

    dim3 gD(DD / 128, BSROWS / 128);
    dim3 gH((HH + 127) / 128, BSROWS / 128);
    int fgrid = (SS / FBQ) * BB;   // 256, 1D; LPT inside kernel
    int lnB = BSROWS / 8;

    // 2) self-attention (causal) + fused LN1 -> X (f32), Xrh (half)
    flash_h<<<fgrid, 256, flash_smem>>>(Qh, Kh, Vth, inputs, gamma, beta, Xp, Xrh, 1);

    // 3) cross-attention + fused LN2 -> Y (f32), Yrh (half)
    gemm_h<0, 0, 0><<<gD, 256, gemm_smem>>>(Xrh, t_caWq, nullptr, Qh, DD, DD, qs, 1);
    flash_h<<<fgrid, 256, flash_smem>>>(Qh, K2h, V2th, Xp, gamma, beta, Yp, Yrh, 0);

    // 4) FFN + LN3
    gemm_h<1, 1, 0><<<gH, 256, gemm_smem>>>(Yrh, t_W1, b1, Hh, HH, DD, 1.0f, 1);
    gemm_h<1, 0, 1><<<gD, 256, gemm_smem>>>(Hh, t_W2, b2, Tp, DD, HH, 1.0f, 1);
    add_ln_kernel<<<lnB, 256>>>(Tp, Yp, gamma, beta, out);
}

// round 17
// speedup vs baseline: 3.0450x; 1.1118x over previous
#include <cuda_runtime.h>
#include <cuda_fp16.h>
#include <cstdint>
#include <math.h>

#define BB 4
#define SS 4096
#define DD 256
#define HH 400
#define BSROWS (BB*SS)

// ---- scratch ----
__device__ __half g_Qh[BSROWS*DD];
__device__ __half g_Kh[BSROWS*DD];
__device__ __half g_Vth[BB*DD*SS];     // [b][d][s]
__device__ __half g_K2h[BSROWS*DD];
__device__ __half g_V2th[BB*DD*SS];
__device__ __half g_Ih[BSROWS*DD];
__device__ __half g_Ch[BSROWS*DD];
__device__ __half g_Xrh[BSROWS*DD];
__device__ __half g_Yrh[BSROWS*DD];
__device__ __half g_Hh[BSROWS*HH];
__device__ __half g_WTh[598016];
__device__ float  g_T[BSROWS*DD];
__device__ float  g_X[BSROWS*DD];
__device__ float  g_Y[BSROWS*DD];

// ============================================================
// helpers
// ============================================================
__device__ __forceinline__ uint32_t smem_u32(const void* p) {
    uint32_t a;
    asm("{ .reg .u64 t; cvta.to.shared.u64 t, %1; cvt.u32.u64 %0, t; }" : "=r"(a) : "l"(p));
    return a;
}
__device__ __forceinline__ void mmah(float c[4], const uint32_t a[4], const uint32_t b[2]) {
    asm volatile(
        "mma.sync.aligned.m16n8k16.row.col.f32.f16.f16.f32 "
        "{%0,%1,%2,%3}, {%4,%5,%6,%7}, {%8,%9}, {%0,%1,%2,%3};"
        : "+f"(c[0]), "+f"(c[1]), "+f"(c[2]), "+f"(c[3])
        : "r"(a[0]), "r"(a[1]), "r"(a[2]), "r"(a[3]), "r"(b[0]), "r"(b[1]));
}
__device__ __forceinline__ uint32_t packh2(float lo, float hi) {
    __half2 h = __floats2half2_rn(lo, hi);
    return *(uint32_t*)&h;
}
__device__ __forceinline__ void cp16(uint32_t dst, const void* src) {
    asm volatile("cp.async.cg.shared.global [%0], [%1], 16;" :: "r"(dst), "l"(src));
}
__device__ __forceinline__ void cp16z(uint32_t dst, const void* src, bool ok) {
    int sz = ok ? 16 : 0;
    asm volatile("cp.async.cg.shared.global [%0], [%1], 16, %2;" :: "r"(dst), "l"(src), "r"(sz));
}
#define CP_COMMIT() asm volatile("cp.async.commit_group;" ::: "memory")
#define CP_WAIT0()  asm volatile("cp.async.wait_group 0;" ::: "memory")
#define CP_WAIT1()  asm volatile("cp.async.wait_group 1;" ::: "memory")
#define CP_WAIT2()  asm volatile("cp.async.wait_group 2;" ::: "memory")

// ============================================================
// Flash attention, fp16 HMMA, FBQ=64 / FBK=128.
// Register-fragment softmax (no S smem round-trip); P written
// once in A-fragment layout. Fused add+LN epilogue. Global LPT.
// SMEM 190.5 KB.
// ============================================================
#define FBQ 64
#define FBK 128
#define QSTR 132
#define VTSTR 68
#define PSTR 68
#define OQ  0
#define OKo 8448
#define OVT 25344
#define OP  42752
#define OST 47104
#define FL_WORDS 47616          // *4 = 190464 bytes

__global__ void __launch_bounds__(256, 1)
flash_h(const __half* __restrict__ Qg, const __half* __restrict__ Kg,
        const __half* __restrict__ Vtg, const float* __restrict__ resid,
        const float* __restrict__ gamma, const float* __restrict__ beta,
        float* __restrict__ outF, __half* __restrict__ outH, int causal) {
    extern __shared__ float fs[];
    uint32_t* fsu = (uint32_t*)fs;
    uint32_t sb = smem_u32(fs);
    int tid = threadIdx.x;
    int wid = tid >> 5, lane = tid & 31;
    int rg = wid & 1;          // rows 32*rg..+31
    int h  = wid >> 1;         // score cols 32h..+31 / O cols 64h..+63
    int lrow = lane >> 2;
    int lcol = lane & 3;
    int bx = blockIdx.x;
    int b = bx & 3;
    int qb = causal ? ((SS / FBQ) - 1 - (bx >> 2)) : (bx >> 2);   // global LPT
    int q0 = qb * FBQ;
    int nc = causal ? ((q0 + FBQ + FBK - 1) / FBK) : (SS / FBK);

    const __half* QB  = Qg  + ((size_t)b * SS + q0) * DD;
    const __half* KB  = Kg  + (size_t)b * SS * DD;
    const __half* VtB = Vtg + (size_t)b * DD * SS;

    // ---- prologue: Q + K0 (group 1), V0 (group 2) ----
    {
        #pragma unroll
        for (int p = 0; p < 8; p++) {
            int idx = tid + p * 256;
            int r = idx >> 5, c = idx & 31;
            cp16(sb + (uint32_t)(OQ + r * QSTR + c * 4) * 4, QB + (size_t)r * DD + c * 8);
        }
        #pragma unroll
        for (int p = 0; p < 16; p++) {
            int idx = tid + p * 256;
            int r = idx >> 5, c = idx & 31;
            cp16(sb + (uint32_t)(OKo + r * QSTR + c * 4) * 4, KB + (size_t)r * DD + c * 8);
        }
        CP_COMMIT();
        #pragma unroll
        for (int p = 0; p < 16; p++) {
            int idx = tid + p * 256;
            int r = idx >> 4, c = idx & 15;
            cp16(sb + (uint32_t)(OVT + r * VTSTR + c * 4) * 4, VtB + (size_t)r * SS + c * 8);
        }
        CP_COMMIT();
    }

    // per-thread softmax state for the 4 row-instances this thread owns
    float mold[2][2] = {{-INFINITY, -INFINITY}, {-INFINITY, -INFINITY}};
    float lsum[2][2] = {{0.f, 0.f}, {0.f, 0.f}};

    float ofrag[2][8][4];
    #pragma unroll
    for (int mt = 0; mt < 2; mt++)
        #pragma unroll
        for (int nb = 0; nb < 8; nb++)
            #pragma unroll
            for (int j = 0; j < 4; j++) ofrag[mt][nb][j] = 0.0f;

    for (int c = 0; c < nc; c++) {
        int k0 = c * FBK;
        bool maskc = causal && (k0 + FBK - 1 > q0);
        bool more = (c + 1) < nc;

        CP_WAIT1();
        __syncthreads();   // (A) K(c) (and Q on c==0) visible

        // ---- scores in registers ----
        float sfrag[2][4][4];
        #pragma unroll
        for (int mt = 0; mt < 2; mt++)
            #pragma unroll
            for (int nb = 0; nb < 4; nb++)
                #pragma unroll
                for (int j = 0; j < 4; j++) sfrag[mt][nb][j] = 0.0f;

        #pragma unroll 4
        for (int kb = 0; kb < 16; kb++) {
            int kw = kb * 8 + lcol;
            uint32_t a[2][4];
            #pragma unroll
            for (int mt = 0; mt < 2; mt++) {
                int row = 32 * rg + 16 * mt + lrow;
                a[mt][0] = fsu[OQ + row * QSTR + kw];
                a[mt][1] = fsu[OQ + (row + 8) * QSTR + kw];
                a[mt][2] = fsu[OQ + row * QSTR + kw + 4];
                a[mt][3] = fsu[OQ + (row + 8) * QSTR + kw + 4];
            }
            #pragma unroll
            for (int nb = 0; nb < 4; nb++) {
                int nrow = 32 * h + 8 * nb + lrow;
                uint32_t b2[2];
                b2[0] = fsu[OKo + nrow * QSTR + kw];
                b2[1] = fsu[OKo + nrow * QSTR + kw + 4];
                mmah(sfrag[0][nb], a[0], b2);
                mmah(sfrag[1][nb], a[1], b2);
            }
        }
        // mask in registers
        if (maskc) {
            #pragma unroll
            for (int mt = 0; mt < 2; mt++) {
                int grow0 = q0 + 32 * rg + 16 * mt + lrow;
                #pragma unroll
                for (int nb = 0; nb < 4; nb++) {
                    int g = k0 + 32 * h + 8 * nb + 2 * lcol;
                    if (g > grow0)         sfrag[mt][nb][0] = -1e30f;
                    if (g + 1 > grow0)     sfrag[mt][nb][1] = -1e30f;
                    if (g > grow0 + 8)     sfrag[mt][nb][2] = -1e30f;
                    if (g + 1 > grow0 + 8) sfrag[mt][nb][3] = -1e30f;
                }
            }
        }
        // per-warp row max -> stats
        {
            float pm[2][2];
            #pragma unroll
            for (int mt = 0; mt < 2; mt++) {
                pm[mt][0] = -INFINITY; pm[mt][1] = -INFINITY;
                #pragma unroll
                for (int nb = 0; nb < 4; nb++) {
                    pm[mt][0] = fmaxf(pm[mt][0], fmaxf(sfrag[mt][nb][0], sfrag[mt][nb][1]));
                    pm[mt][1] = fmaxf(pm[mt][1], fmaxf(sfrag[mt][nb][2], sfrag[mt][nb][3]));
                }
            }
            #pragma unroll
            for (int mt = 0; mt < 2; mt++)
                #pragma unroll
                for (int hh = 0; hh < 2; hh++) {
                    pm[mt][hh] = fmaxf(pm[mt][hh], __shfl_xor_sync(0xffffffff, pm[mt][hh], 1));
                    pm[mt][hh] = fmaxf(pm[mt][hh], __shfl_xor_sync(0xffffffff, pm[mt][hh], 2));
                }
            if (lcol == 0) {
                #pragma unroll
                for (int mt = 0; mt < 2; mt++)
                    #pragma unroll
                    for (int hh = 0; hh < 2; hh++)
                        fs[OST + (32 * rg + 16 * mt + 8 * hh + lrow) * 4 + h] = pm[mt][hh];
            }
        }
        __syncthreads();   // (B) stats visible; K buffer free

        // ---- early-issue K(c+1) ----
        if (more) {
            const __half* Kn = KB + (size_t)(k0 + FBK) * DD;
            #pragma unroll
            for (int p = 0; p < 16; p++) {
                int idx = tid + p * 256;
                int r = idx >> 5, cc = idx & 31;
                cp16(sb + (uint32_t)(OKo + r * QSTR + cc * 4) * 4, Kn + (size_t)r * DD + cc * 8);
            }
            CP_COMMIT();
        }

        // ---- finalize max; exp; write P in fragment layout; sum stats ----
        float arow[2][2], srow[2][2];
        #pragma unroll
        for (int mt = 0; mt < 2; mt++)
            #pragma unroll
            for (int hh = 0; hh < 2; hh++) {
                int row = 32 * rg + 16 * mt + 8 * hh + lrow;
                float mx = fmaxf(fmaxf(fs[OST + row * 4], fs[OST + row * 4 + 1]),
                                 fmaxf(fs[OST + row * 4 + 2], fs[OST + row * 4 + 3]));
                float mn = fmaxf(mold[mt][hh], mx);
                arow[mt][hh] = __expf(mold[mt][hh] - mn);
                mold[mt][hh] = mn;
                srow[mt][hh] = 0.0f;
            }
        #pragma unroll
        for (int mt = 0; mt < 2; mt++) {
            int r0 = 32 * rg + 16 * mt + lrow;
            #pragma unroll
            for (int nb = 0; nb < 4; nb++) {
                float e0 = __expf(sfrag[mt][nb][0] - mold[mt][0]);
                float e1 = __expf(sfrag[mt][nb][1] - mold[mt][0]);
                float e2 = __expf(sfrag[mt][nb][2] - mold[mt][1]);
                float e3 = __expf(sfrag[mt][nb][3] - mold[mt][1]);
                srow[mt][0] += e0 + e1;
                srow[mt][1] += e2 + e3;
                fsu[OP + r0 * PSTR + 16 * h + 4 * nb + lcol]       = packh2(e0, e1);
                fsu[OP + (r0 + 8) * PSTR + 16 * h + 4 * nb + lcol] = packh2(e2, e3);
            }
        }
        #pragma unroll
        for (int mt = 0; mt < 2; mt++)
            #pragma unroll
            for (int hh = 0; hh < 2; hh++) {
                srow[mt][hh] += __shfl_xor_sync(0xffffffff, srow[mt][hh], 1);
                srow[mt][hh] += __shfl_xor_sync(0xffffffff, srow[mt][hh], 2);
            }
        if (lcol == 0) {
            #pragma unroll
            for (int mt = 0; mt < 2; mt++)
                #pragma unroll
                for (int hh = 0; hh < 2; hh++)
                    fs[OST + 256 + (32 * rg + 16 * mt + 8 * hh + lrow) * 4 + h] = srow[mt][hh];
        }
        if (more) { CP_WAIT1(); } else { CP_WAIT0(); }
        __syncthreads();   // (C) P + sum stats + V visible

        // l update
        #pragma unroll
        for (int mt = 0; mt < 2; mt++)
            #pragma unroll
            for (int hh = 0; hh < 2; hh++) {
                int row = 32 * rg + 16 * mt + 8 * hh + lrow;
                float s = fs[OST + 256 + row * 4] + fs[OST + 256 + row * 4 + 1] +
                          fs[OST + 256 + row * 4 + 2] + fs[OST + 256 + row * 4 + 3];
                lsum[mt][hh] = lsum[mt][hh] * arow[mt][hh] + s;
            }

        // ---- PV: warp (rg,h): O[32rg..+31][64h..+63] += P * V ----
        {
            #pragma unroll
            for (int mt = 0; mt < 2; mt++)
                #pragma unroll
                for (int nb = 0; nb < 8; nb++) {
                    ofrag[mt][nb][0] *= arow[mt][0]; ofrag[mt][nb][1] *= arow[mt][0];
                    ofrag[mt][nb][2] *= arow[mt][1]; ofrag[mt][nb][3] *= arow[mt][1];
                }
            #pragma unroll
            for (int kb = 0; kb < 8; kb++) {
                int kw = kb * 8 + lcol;
                uint32_t pa[2][4];
                #pragma unroll
                for (int mt = 0; mt < 2; mt++) {
                    int pr = 32 * rg + 16 * mt + lrow;
                    pa[mt][0] = fsu[OP + pr * PSTR + kw];
                    pa[mt][1] = fsu[OP + (pr + 8) * PSTR + kw];
                    pa[mt][2] = fsu[OP + pr * PSTR + kw + 4];
                    pa[mt][3] = fsu[OP + (pr + 8) * PSTR + kw + 4];
                }
                #pragma unroll
                for (int nb = 0; nb < 8; nb++) {
                    int ncol = 64 * h + 8 * nb + lrow;
                    uint32_t b2[2];
                    b2[0] = fsu[OVT + ncol * VTSTR + kw];
                    b2[1] = fsu[OVT + ncol * VTSTR + kw + 4];
                    mmah(ofrag[0][nb], pa[0], b2);
                    mmah(ofrag[1][nb], pa[1], b2);
                }
            }
        }
        __syncthreads();   // (D) V + P regions free

        if (more) {
            int kn = k0 + FBK;
            #pragma unroll
            for (int p = 0; p < 16; p++) {
                int idx = tid + p * 256;
                int r = idx >> 4, cc = idx & 15;
                cp16(sb + (uint32_t)(OVT + r * VTSTR + cc * 4) * 4,
                     VtB + (size_t)r * SS + kn + cc * 8);
            }
            CP_COMMIT();
        }
    }

    // ============================================================
    // fused epilogue: v = O/l + resid ; LayerNorm -> outF + outH
    // ============================================================
    {
        #pragma unroll
        for (int mt = 0; mt < 2; mt++) {
            int row = 32 * rg + 16 * mt + lrow;
            float inv0 = 1.0f / lsum[mt][0];
            float inv8 = 1.0f / lsum[mt][1];
            const float* R0 = resid + ((size_t)b * SS + q0 + row) * DD;
            const float* R8 = R0 + 8 * DD;
            #pragma unroll
            for (int nb = 0; nb < 8; nb++) {
                int col = 64 * h + 8 * nb + 2 * lcol;
                float2 r0 = *(const float2*)&R0[col];
                float2 r8 = *(const float2*)&R8[col];
                ofrag[mt][nb][0] = ofrag[mt][nb][0] * inv0 + r0.x;
                ofrag[mt][nb][1] = ofrag[mt][nb][1] * inv0 + r0.y;
                ofrag[mt][nb][2] = ofrag[mt][nb][2] * inv8 + r8.x;
                ofrag[mt][nb][3] = ofrag[mt][nb][3] * inv8 + r8.y;
            }
        }
        // pass 1: mean
        float s1[2][2] = {{0.f, 0.f}, {0.f, 0.f}};
        #pragma unroll
        for (int mt = 0; mt < 2; mt++)
            #pragma unroll
            for (int nb = 0; nb < 8; nb++) {
                s1[mt][0] += ofrag[mt][nb][0] + ofrag[mt][nb][1];
                s1[mt][1] += ofrag[mt][nb][2] + ofrag[mt][nb][3];
            }
        #pragma unroll
        for (int mt = 0; mt < 2; mt++)
            #pragma unroll
            for (int hh = 0; hh < 2; hh++) {
                s1[mt][hh] += __shfl_xor_sync(0xffffffff, s1[mt][hh], 1);
                s1[mt][hh] += __shfl_xor_sync(0xffffffff, s1[mt][hh], 2);
            }
        if (lcol == 0) {
            #pragma unroll
            for (int mt = 0; mt < 2; mt++)
                #pragma unroll
                for (int hh = 0; hh < 2; hh++) {
                    int row = 32 * rg + 16 * mt + 8 * hh + lrow;
                    fs[OP + row * 4 + h] = s1[mt][hh];
                }
        }
        __syncthreads();
        float mu[2][2];
        #pragma unroll
        for (int mt = 0; mt < 2; mt++)
            #pragma unroll
            for (int hh = 0; hh < 2; hh++) {
                int row = 32 * rg + 16 * mt + 8 * hh + lrow;
                mu[mt][hh] = (fs[OP + row * 4] + fs[OP + row * 4 + 1] +
                              fs[OP + row * 4 + 2] + fs[OP + row * 4 + 3]) * (1.0f / DD);
            }
        // pass 2: variance
        float s2[2][2] = {{0.f, 0.f}, {0.f, 0.f}};
        #pragma unroll
        for (int mt = 0; mt < 2; mt++)
            #pragma unroll
            for (int nb = 0; nb < 8; nb++) {
                float d0 = ofrag[mt][nb][0] - mu[mt][0];
                float d1 = ofrag[mt][nb][1] - mu[mt][0];
                float d2 = ofrag[mt][nb][2] - mu[mt][1];
                float d3 = ofrag[mt][nb][3] - mu[mt][1];
                s2[mt][0] += d0 * d0 + d1 * d1;
                s2[mt][1] += d2 * d2 + d3 * d3;
            }
        #pragma unroll
        for (int mt = 0; mt < 2; mt++)
            #pragma unroll
            for (int hh = 0; hh < 2; hh++) {
                s2[mt][hh] += __shfl_xor_sync(0xffffffff, s2[mt][hh], 1);
                s2[mt][hh] += __shfl_xor_sync(0xffffffff, s2[mt][hh], 2);
            }
        if (lcol == 0) {
            #pragma unroll
            for (int mt = 0; mt < 2; mt++)
                #pragma unroll
                for (int hh = 0; hh < 2; hh++) {
                    int row = 32 * rg + 16 * mt + 8 * hh + lrow;
                    fs[OP + 1024 + row * 4 + h] = s2[mt][hh];
                }
        }
        __syncthreads();
        float rs[2][2];
        #pragma unroll
        for (int mt = 0; mt < 2; mt++)
            #pragma unroll
            for (int hh = 0; hh < 2; hh++) {
                int row = 32 * rg + 16 * mt + 8 * hh + lrow;
                float var = (fs[OP + 1024 + row * 4] + fs[OP + 1024 + row * 4 + 1] +
                             fs[OP + 1024 + row * 4 + 2] + fs[OP + 1024 + row * 4 + 3]) * (1.0f / DD);
                rs[mt][hh] = rsqrtf(var + 1e-3f);
            }
        // write normalized outputs
        #pragma unroll
        for (int mt = 0; mt < 2; mt++) {
            int row = 32 * rg + 16 * mt + lrow;
            float* F0 = outF + ((size_t)b * SS + q0 + row) * DD;
            float* F8 = F0 + 8 * DD;
            __half* H0 = outH + ((size_t)b * SS + q0 + row) * DD;
            __half* H8 = H0 + 8 * DD;
            #pragma unroll
            for (int nb = 0; nb < 8; nb++) {
                int col = 64 * h + 8 * nb + 2 * lcol;
                float2 g = *(const float2*)&gamma[col];
                float2 e = *(const float2*)&beta[col];
                float o0 = (ofrag[mt][nb][0] - mu[mt][0]) * rs[mt][0] * g.x + e.x;
                float o1 = (ofrag[mt][nb][1] - mu[mt][0]) * rs[mt][0] * g.y + e.y;
                float o2 = (ofrag[mt][nb][2] - mu[mt][1]) * rs[mt][1] * g.x + e.x;
                float o3 = (ofrag[mt][nb][3] - mu[mt][1]) * rs[mt][1] * g.y + e.y;
                *(float2*)&F0[col] = make_float2(o0, o1);
                *(float2*)&F8[col] = make_float2(o2, o3);
                *(__half2*)&H0[col] = __floats2half2_rn(o0, o1);
                *(__half2*)&H8[col] = __floats2half2_rn(o2, o3);
            }
        }
    }
}

// ============================================================
// fp16 HMMA GEMM (unchanged)
// ============================================================
#define GEMM_H_WORDS 15360

template<int BIAS, int LEAKY, int OUTF32>
__device__ __forceinline__ void gemm_h_body(
    const __half* __restrict__ A, const __half* __restrict__ Wt,
    const float* __restrict__ bias, void* Cv,
    int N, int K, float oscale, int omode,
    uint32_t* su, uint32_t sb, int bx, int by) {
    int tid = threadIdx.x;
    int wid = tid >> 5, lane = tid & 31;
    int wm = wid & 3, wn = wid >> 2;
    int lrow = lane >> 2, lcol = lane & 3;
    int rb = by * 128, cb = bx * 128;

    float cfr[2][8][4];
    #pragma unroll
    for (int mt = 0; mt < 2; mt++)
        #pragma unroll
        for (int nb = 0; nb < 8; nb++)
            #pragma unroll
            for (int j = 0; j < 4; j++) cfr[mt][nb][j] = 0.0f;

    int NI = (K + 31) / 32;

    #define STAGEH(buf, k0s) do {                                                 \
        int _k0 = (k0s);                                                          \
        _Pragma("unroll")                                                         \
        for (int p = 0; p < 2; p++) {                                             \
            int idx = tid + p * 256;                                              \
            int r = idx >> 2, c = idx & 3;                                        \
            int col = _k0 + c * 8;                                                \
            bool ok = col < K;                                                    \
            const __half* src = A + (size_t)(rb + r) * K + (ok ? col : 0);        \
            cp16z(sb + (uint32_t)((buf) * 2560 + r * 20 + c * 4) * 4, src, ok);   \
        }                                                                         \
        _Pragma("unroll")                                                         \
        for (int p = 0; p < 2; p++) {                                             \
            int idx = tid + p * 256;                                              \
            int r = idx >> 2, c = idx & 3;                                        \
            int col = _k0 + c * 8;                                                \
            int nrow = cb + r;                                                    \
            bool ok = (col < K) && (nrow < N);                                    \
            const __half* src = Wt + (ok ? ((size_t)nrow * K + col) : 0);         \
            cp16z(sb + (uint32_t)(7680 + (buf) * 2560 + r * 20 + c * 4) * 4, src, ok); \
        }                                                                         \
    } while (0)

    STAGEH(0, 0);
    CP_COMMIT();
    if (NI > 1) { STAGEH(1, 32); }
    CP_COMMIT();
    if (NI > 2) { STAGEH(2, 64); }
    CP_COMMIT();

    for (int it = 0; it < NI; it++) {
        CP_WAIT2();
        __syncthreads();
        int s = it % 3;
        int Ab = s * 2560;
        int Wb = 7680 + s * 2560;
        #pragma unroll
        for (int kb = 0; kb < 2; kb++) {
            int kw = kb * 8 + lcol;
            uint32_t a[2][4];
            #pragma unroll
            for (int mt = 0; mt < 2; mt++) {
                int row = 32 * wm + 16 * mt + lrow;
                a[mt][0] = su[Ab + row * 20 + kw];
                a[mt][1] = su[Ab + (row + 8) * 20 + kw];
                a[mt][2] = su[Ab + row * 20 + kw + 4];
                a[mt][3] = su[Ab + (row + 8) * 20 + kw + 4];
            }
            #pragma unroll
            for (int nb = 0; nb < 8; nb++) {
                int ncol = 64 * wn + 8 * nb + lrow;
                uint32_t b2[2];
                b2[0] = su[Wb + ncol * 20 + kw];
                b2[1] = su[Wb + ncol * 20 + kw + 4];
                mmah(cfr[0][nb], a[0], b2);
                mmah(cfr[1][nb], a[1], b2);
            }
        }
        __syncthreads();
        if (it + 3 < NI) { STAGEH(s, (it + 3) * 32); CP_COMMIT(); }
    }
    #undef STAGEH

    #pragma unroll
    for (int mt = 0; mt < 2; mt++) {
        int r0 = rb + 32 * wm + 16 * mt + lrow;
        #pragma unroll
        for (int nb = 0; nb < 8; nb++) {
            int col = cb + 64 * wn + 8 * nb + 2 * lcol;
            if (col < N) {
                float v00 = cfr[mt][nb][0], v01 = cfr[mt][nb][1];
                float v10 = cfr[mt][nb][2], v11 = cfr[mt][nb][3];
                if (BIAS) {
                    float b0 = bias[col], b1 = bias[col + 1];
                    v00 += b0; v01 += b1; v10 += b0; v11 += b1;
                }
                if (LEAKY) {
                    v00 = (v00 > 0.0f) ? v00 : 0.2f * v00;
                    v01 = (v01 > 0.0f) ? v01 : 0.2f * v01;
                    v10 = (v10 > 0.0f) ? v10 : 0.2f * v10;
                    v11 = (v11 > 0.0f) ? v11 : 0.2f * v11;
                }
                if (OUTF32) {
                    float* C = (float*)Cv;
                    *(float2*)&C[(size_t)r0 * N + col] = make_float2(v00, v01);
                    *(float2*)&C[(size_t)(r0 + 8) * N + col] = make_float2(v10, v11);
                } else if (omode == 1) {
                    __half* C = (__half*)Cv;
                    __half2 h0 = __floats2half2_rn(v00 * oscale, v01 * oscale);
                    __half2 h1 = __floats2half2_rn(v10 * oscale, v11 * oscale);
                    *(__half2*)&C[(size_t)r0 * N + col] = h0;
                    *(__half2*)&C[(size_t)(r0 + 8) * N + col] = h1;
                } else {
                    __half* Ct = (__half*)Cv;
                    int bb = r0 >> 12, ss = r0 & 4095;
                    size_t base0 = ((size_t)(bb * DD + col)) * SS;
                    size_t base1 = ((size_t)(bb * DD + col + 1)) * SS;
                    Ct[base0 + ss]     = __float2half_rn(v00);
                    Ct[base1 + ss]     = __float2half_rn(v01);
                    Ct[base0 + ss + 8] = __float2half_rn(v10);
                    Ct[base1 + ss + 8] = __float2half_rn(v11);
                }
            }
        }
    }
}

template<int BIAS, int LEAKY, int OUTF32>
__global__ void __launch_bounds__(256, 2)
gemm_h(const __half* __restrict__ A, const __half* __restrict__ Wt,
       const float* __restrict__ bias, void* Cv,
       int N, int K, float oscale, int omode) {
    extern __shared__ float gs[];
    gemm_h_body<BIAS, LEAKY, OUTF32>(A, Wt, bias, Cv, N, K, oscale, omode,
                                     (uint32_t*)gs, smem_u32(gs), blockIdx.x, blockIdx.y);
}

struct Proj5Args {
    const __half* A[5];
    const __half* W[5];
    void* C[5];
    float s[5];
    int mode[5];
};

__global__ void __launch_bounds__(256, 2)
proj5_h(Proj5Args pa) {
    extern __shared__ float gs[];
    int z = blockIdx.z;
    gemm_h_body<0, 0, 0>(pa.A[z], pa.W[z], nullptr, pa.C[z], DD, DD, pa.s[z], pa.mode[z],
                         (uint32_t*)gs, smem_u32(gs), blockIdx.x, blockIdx.y);
}

__global__ void __launch_bounds__(256)
cvt2h(const float* __restrict__ a, const float* __restrict__ b,
      __half* __restrict__ ah, __half* __restrict__ bh, int n) {
    int i = (blockIdx.x * 256 + threadIdx.x) * 4;
    const float* s = blockIdx.y ? b : a;
    __half* d = blockIdx.y ? bh : ah;
    if (i < n) {
        float4 v = *(const float4*)(s + i);
        *(__half2*)(d + i)     = __floats2half2_rn(v.x, v.y);
        *(__half2*)(d + i + 2) = __floats2half2_rn(v.z, v.w);
    }
}

struct WT8 {
    const float* src[8];
    __half* dst[8];
    int K[8];
    int N[8];
};

__global__ void __launch_bounds__(256)
wtrans8(WT8 w) {
    int z = blockIdx.z;
    int K = w.K[z], N = w.N[z];
    int idx = blockIdx.x * 256 + threadIdx.x;
    if (idx < K * N) {
        int n = idx / K, k = idx - n * K;
        w.dst[z][idx] = __float2half_rn(w.src[z][(size_t)k * N + n]);
    }
}

// ============================================================
// standalone add+LN (final LN3 only)
// ============================================================
__global__ void __launch_bounds__(256)
add_ln_kernel(const float* __restrict__ a, const float* __restrict__ bvec,
              const float* __restrict__ gamma, const float* __restrict__ beta,
              float* __restrict__ out) {
    int wid = threadIdx.x >> 5, lane = threadIdx.x & 31;
    int row = blockIdx.x * 8 + wid;
    const float4* ar = (const float4*)(a + (size_t)row * DD);
    const float4* br = (const float4*)(bvec + (size_t)row * DD);
    float4 v0 = ar[lane];        float4 w0 = br[lane];
    float4 v1 = ar[lane + 32];   float4 w1 = br[lane + 32];
    v0.x += w0.x; v0.y += w0.y; v0.z += w0.z; v0.w += w0.w;
    v1.x += w1.x; v1.y += w1.y; v1.z += w1.z; v1.w += w1.w;

    float sum = v0.x + v0.y + v0.z + v0.w + v1.x + v1.y + v1.z + v1.w;
    #pragma unroll
    for (int off = 16; off > 0; off >>= 1) sum += __shfl_xor_sync(0xffffffff, sum, off);
    float mu = sum * (1.0f / DD);

    float sq = (v0.x - mu) * (v0.x - mu) + (v0.y - mu) * (v0.y - mu)
             + (v0.z - mu) * (v0.z - mu) + (v0.w - mu) * (v0.w - mu)
             + (v1.x - mu) * (v1.x - mu) + (v1.y - mu) * (v1.y - mu)
             + (v1.z - mu) * (v1.z - mu) + (v1.w - mu) * (v1.w - mu);
    #pragma unroll
    for (int off = 16; off > 0; off >>= 1) sq += __shfl_xor_sync(0xffffffff, sq, off);
    float rs = rsqrtf(sq * (1.0f / DD) + 1e-3f);

    const float4* g4 = (const float4*)gamma;
    const float4* b4 = (const float4*)beta;
    float4 g0 = g4[lane], g1 = g4[lane + 32];
    float4 e0 = b4[lane], e1 = b4[lane + 32];
    float4 o0, o1;
    o0.x = (v0.x - mu) * rs * g0.x + e0.x;
    o0.y = (v0.y - mu) * rs * g0.y + e0.y;
    o0.z = (v0.z - mu) * rs * g0.z + e0.z;
    o0.w = (v0.w - mu) * rs * g0.w + e0.w;
    o1.x = (v1.x - mu) * rs * g1.x + e1.x;
    o1.y = (v1.y - mu) * rs * g1.y + e1.y;
    o1.z = (v1.z - mu) * rs * g1.z + e1.z;
    o1.w = (v1.w - mu) * rs * g1.w + e1.w;
    float4* orow = (float4*)(out + (size_t)row * DD);
    orow[lane] = o0;
    orow[lane + 32] = o1;
}

// ============================================================
extern "C" void kernel_launch(void* const* d_in, const int* in_sizes, int n_in,
                              void* d_out, int out_size) {
    const float* inputs = (const float*)d_in[0];
    const float* ctx    = (const float*)d_in[1];
    const float* sa_Wk  = (const float*)d_in[2];
    const float* sa_Wv  = (const float*)d_in[3];
    const float* sa_Wq  = (const float*)d_in[4];
    const float* ca_Wk  = (const float*)d_in[5];
    const float* ca_Wv  = (const float*)d_in[6];
    const float* ca_Wq  = (const float*)d_in[7];
    const float* W1     = (const float*)d_in[8];
    const float* b1     = (const float*)d_in[9];
    const float* W2     = (const float*)d_in[10];
    const float* b2     = (const float*)d_in[11];
    const float* gamma  = (const float*)d_in[12];
    const float* beta   = (const float*)d_in[13];
    float* out = (float*)d_out;

    __half *Qh, *Kh, *Vth, *K2h, *V2th, *Ih, *Ch, *Xrh, *Yrh, *Hh, *WT;
    float *Tp, *Xp, *Yp;
    cudaGetSymbolAddress((void**)&Qh,  g_Qh);
    cudaGetSymbolAddress((void**)&Kh,  g_Kh);
    cudaGetSymbolAddress((void**)&Vth, g_Vth);
    cudaGetSymbolAddress((void**)&K2h, g_K2h);
    cudaGetSymbolAddress((void**)&V2th,g_V2th);
    cudaGetSymbolAddress((void**)&Ih,  g_Ih);
    cudaGetSymbolAddress((void**)&Ch,  g_Ch);
    cudaGetSymbolAddress((void**)&Xrh, g_Xrh);
    cudaGetSymbolAddress((void**)&Yrh, g_Yrh);
    cudaGetSymbolAddress((void**)&Hh,  g_Hh);
    cudaGetSymbolAddress((void**)&WT,  g_WTh);
    cudaGetSymbolAddress((void**)&Tp,  g_T);
    cudaGetSymbolAddress((void**)&Xp,  g_X);
    cudaGetSymbolAddress((void**)&Yp,  g_Y);

    __half* t_saWk = WT + 0;
    __half* t_saWv = WT + 65536;
    __half* t_saWq = WT + 131072;
    __half* t_caWk = WT + 196608;
    __half* t_caWv = WT + 262144;
    __half* t_caWq = WT + 327680;
    __half* t_W1   = WT + 393216;
    __half* t_W2   = WT + 495616;

    const int flash_smem = FL_WORDS * 4;
    const int gemm_smem = GEMM_H_WORDS * 4;
    cudaFuncSetAttribute(flash_h, cudaFuncAttributeMaxDynamicSharedMemorySize, flash_smem);
    cudaFuncSetAttribute(proj5_h, cudaFuncAttributeMaxDynamicSharedMemorySize, gemm_smem);
    cudaFuncSetAttribute(gemm_h<0, 0, 0>, cudaFuncAttributeMaxDynamicSharedMemorySize, gemm_smem);
    cudaFuncSetAttribute(gemm_h<1, 1, 0>, cudaFuncAttributeMaxDynamicSharedMemorySize, gemm_smem);
    cudaFuncSetAttribute(gemm_h<1, 0, 1>, cudaFuncAttributeMaxDynamicSharedMemorySize, gemm_smem);

    const float qs = 0.015625f;   // 1/sqrt(4096)

    // 0a) inputs/ctx -> half
    {
        dim3 cg((BSROWS * DD / 4 + 255) / 256, 2);
        cvt2h<<<cg, 256>>>(inputs, ctx, Ih, Ch, BSROWS * DD);
    }
    // 0b) weights -> transposed half
    {
        WT8 w;
        w.src[0] = sa_Wk; w.dst[0] = t_saWk; w.K[0] = DD; w.N[0] = DD;
        w.src[1] = sa_Wv; w.dst[1] = t_saWv; w.K[1] = DD; w.N[1] = DD;
        w.src[2] = sa_Wq; w.dst[2] = t_saWq; w.K[2] = DD; w.N[2] = DD;
        w.src[3] = ca_Wk; w.dst[3] = t_caWk; w.K[3] = DD; w.N[3] = DD;
        w.src[4] = ca_Wv; w.dst[4] = t_caWv; w.K[4] = DD; w.N[4] = DD;
        w.src[5] = ca_Wq; w.dst[5] = t_caWq; w.K[5] = DD; w.N[5] = DD;
        w.src[6] = W1;    w.dst[6] = t_W1;   w.K[6] = DD; w.N[6] = HH;
        w.src[7] = W2;    w.dst[7] = t_W2;   w.K[7] = HH; w.N[7] = DD;
        dim3 wg((DD * HH + 255) / 256, 1, 8);
        wtrans8<<<wg, 256>>>(w);
    }

    // 1) fused 5-projection batch
    {
        Proj5Args pa;
        pa.A[0] = Ih; pa.W[0] = t_saWk; pa.C[0] = Kh;   pa.s[0] = 1.0f; pa.mode[0] = 1;
        pa.A[1] = Ih; pa.W[1] = t_saWv; pa.C[1] = Vth;  pa.s[1] = 1.0f; pa.mode[1] = 2;
        pa.A[2] = Ih; pa.W[2] = t_saWq; pa.C[2] = Qh;   pa.s[2] = qs;   pa.mode[2] = 1;
        pa.A[3] = Ch; pa.W[3] = t_caWk; pa.C[3] = K2h;  pa.s[3] = 1.0f; pa.mode[3] = 1;
        pa.A[4] = Ch; pa.W[4] = t_caWv; pa.C[4] = V2th; pa.s[4] = 1.0f; pa.mode[4] = 2;
        dim3 pg(DD / 128, BSROWS / 128, 5);
        proj5_h<<<pg, 256, gemm_smem>>>(pa);
    }

    dim3 gD(DD / 128, BSROWS / 128);
    dim3 gH((HH + 127) / 128, BSROWS / 128);
    int fgrid = (SS / FBQ) * BB;
    int lnB = BSROWS / 8;

    // 2) self-attention (causal) + fused LN1 -> X (f32), Xrh (half)
    flash_h<<<fgrid, 256, flash_smem>>>(Qh, Kh, Vth, inputs, gamma, beta, Xp, Xrh, 1);

    // 3) cross-attention + fused LN2 -> Y (f32), Yrh (half)
    gemm_h<0, 0, 0><<<gD, 256, gemm_smem>>>(Xrh, t_caWq, nullptr, Qh, DD, DD, qs, 1);
    flash_h<<<fgrid, 256, flash_smem>>>(Qh, K2h, V2th, Xp, gamma, beta, Yp, Yrh, 0);

    // 4) FFN + LN3
    gemm_h<1, 1, 0><<<gH, 256, gemm_smem>>>(Yrh, t_W1, b1, Hh, HH, DD, 1.0f, 1);
    gemm_h<1, 0, 1><<<gD, 256, gemm_smem>>>(Hh, t_W2, b2, Tp, DD, HH, 1.0f, 1);
    add_ln_kernel<<<lnB, 256>>>(Tp, Yp, gamma, beta, out);
}